// round 11
// baseline (speedup 1.0000x reference)
#include <cuda_runtime.h>
#include <cuda_bf16.h>
#include <math.h>
#include <float.h>
#include <stdint.h>

#define Bx 2
#define Tt 2048
#define Dd 2048
#define Nn 16
#define Hh 128
#define WINDOW 1024
#define SOFT_CAP 50.0f

#define SZQ ((size_t)Bx * Nn * Tt * Hh)

// fp32 scratch
__device__ float g_qkv[3ull * Bx * Nn * Tt * Hh];
// bf16 split scratch (GEMMs)
__device__ __nv_bfloat16 g_xhi[(size_t)Bx * Tt * Dd], g_xlo[(size_t)Bx * Tt * Dd];
__device__ __nv_bfloat16 g_wqh[48ull * Hh * Dd],      g_wql[48ull * Hh * Dd];
__device__ __nv_bfloat16 g_woh[(size_t)Dd * Dd],      g_wol[(size_t)Dd * Dd];
__device__ __nv_bfloat16 g_ehi[(size_t)Bx * Tt * Dd], g_elo[(size_t)Bx * Tt * Dd];
// bf16 split scratch (attention): q,k as [b][n][t][h]; v transposed [b][n][h][t]
__device__ __nv_bfloat16 g_qh[SZQ], g_ql[SZQ];
__device__ __nv_bfloat16 g_kh[SZQ], g_kl[SZQ];
__device__ __nv_bfloat16 g_vth[SZQ], g_vtl[SZQ];

// ---------------------------------------------------------------------------
// helpers
// ---------------------------------------------------------------------------
__device__ __forceinline__ uint32_t smem_u32(const void* p) {
    uint32_t a;
    asm("{ .reg .u64 t; cvta.to.shared.u64 t, %1; cvt.u32.u64 %0, t; }" : "=r"(a) : "l"(p));
    return a;
}
__device__ __forceinline__ void ldm4(uint32_t* r, uint32_t addr) {
    asm volatile("ldmatrix.sync.aligned.m8n8.x4.shared.b16 {%0,%1,%2,%3}, [%4];"
        : "=r"(r[0]), "=r"(r[1]), "=r"(r[2]), "=r"(r[3]) : "r"(addr));
}
__device__ __forceinline__ void mma16816(float* c, const uint32_t* a, uint32_t b0, uint32_t b1) {
    asm volatile("mma.sync.aligned.m16n8k16.row.col.f32.bf16.bf16.f32 "
        "{%0,%1,%2,%3}, {%4,%5,%6,%7}, {%8,%9}, {%0,%1,%2,%3};"
        : "+f"(c[0]), "+f"(c[1]), "+f"(c[2]), "+f"(c[3])
        : "r"(a[0]), "r"(a[1]), "r"(a[2]), "r"(a[3]), "r"(b0), "r"(b1));
}
__device__ __forceinline__ void cp16(uint32_t dst, const void* src) {
    asm volatile("cp.async.cg.shared.global [%0], [%1], 16;" :: "r"(dst), "l"(src));
}
#define CP_COMMIT() asm volatile("cp.async.commit_group;" ::: "memory")

// ---------------------------------------------------------------------------
// fp32 -> bf16 hi/lo split (straight)
// ---------------------------------------------------------------------------
__device__ __forceinline__ void split4(const float4 v, __nv_bfloat162* H, __nv_bfloat162* L, size_t i2) {
    __nv_bfloat16 h0 = __float2bfloat16(v.x), h1 = __float2bfloat16(v.y);
    __nv_bfloat16 h2 = __float2bfloat16(v.z), h3 = __float2bfloat16(v.w);
    H[i2]     = __nv_bfloat162(h0, h1);
    H[i2 + 1] = __nv_bfloat162(h2, h3);
    L[i2]     = __nv_bfloat162(__float2bfloat16(v.x - __bfloat162float(h0)),
                               __float2bfloat16(v.y - __bfloat162float(h1)));
    L[i2 + 1] = __nv_bfloat162(__float2bfloat16(v.z - __bfloat162float(h2)),
                               __float2bfloat16(v.w - __bfloat162float(h3)));
}

__global__ void split_x_kernel(const float* __restrict__ in) {
    size_t i = (size_t)blockIdx.x * 256 + threadIdx.x;
    float4 v = ((const float4*)in)[i];
    split4(v, (__nv_bfloat162*)g_xhi, (__nv_bfloat162*)g_xlo, i * 2);
}

// ---------------------------------------------------------------------------
// fp32 [mat][R][C] -> bf16 hi/lo [mat][C][R] transpose split (weights)
// ---------------------------------------------------------------------------
template<int WHICH>
__global__ void transpose_split_kernel(const float* __restrict__ in, int R, int C) {
    __shared__ float tile[32][33];
    const int mat = blockIdx.z;
    const int c0 = blockIdx.x * 32, r0 = blockIdx.y * 32;
    const float* A = in + (size_t)mat * R * C;
    #pragma unroll
    for (int i = threadIdx.y; i < 32; i += 8)
        tile[i][threadIdx.x] = A[(size_t)(r0 + i) * C + c0 + threadIdx.x];
    __syncthreads();
    __nv_bfloat16* H = (WHICH == 0 ? g_wqh : g_woh) + (size_t)mat * R * C;
    __nv_bfloat16* L = (WHICH == 0 ? g_wql : g_wol) + (size_t)mat * R * C;
    #pragma unroll
    for (int i = threadIdx.y; i < 32; i += 8) {
        float v = tile[threadIdx.x][i];
        __nv_bfloat16 h = __float2bfloat16(v);
        size_t o = (size_t)(c0 + i) * R + r0 + threadIdx.x;
        H[o] = h;
        L[o] = __float2bfloat16(v - __bfloat162float(h));
    }
}

// ---------------------------------------------------------------------------
// mma.sync GEMM (R6 config): K-chunk 32, 3-stage ring, 256 thr, 2 CTAs/SM
// ---------------------------------------------------------------------------
#define TILE32_B 8192
#define STAGE32_B (4 * TILE32_B)       // 32 KB
#define GEMM_SMEM (3 * STAGE32_B)      // 96 KB

__device__ __forceinline__ uint32_t sw64(int r, int g) {
    return (uint32_t)(r * 64 + ((g ^ ((r >> 1) & 3)) << 4));
}

template<int MODE>
__global__ void __launch_bounds__(256, 2) mma_gemm(float* __restrict__ outg) {
    extern __shared__ char smc[];
    const uint32_t smb = smem_u32(smc);
    const int tid = threadIdx.x;
    const int wid = tid >> 5, lane = tid & 31;
    const int m0 = blockIdx.x * 128;

    const __nv_bfloat16 *Ahi, *Alo, *Bhi, *Blo;
    if (MODE == 0) { Ahi = g_xhi; Alo = g_xlo; Bhi = g_wqh; Blo = g_wql; }
    else           { Ahi = g_ehi; Alo = g_elo; Bhi = g_woh; Blo = g_wol; }

    const int srow = tid >> 1, sg0 = (tid & 1) * 2;
    const size_t bbase = (size_t)blockIdx.y * (128 * Dd);
    const __nv_bfloat16* gsrc[4];
    gsrc[0] = Ahi + (size_t)(m0 + srow) * Dd + sg0 * 8;
    gsrc[1] = Alo + (size_t)(m0 + srow) * Dd + sg0 * 8;
    gsrc[2] = Bhi + bbase + (size_t)srow * Dd + sg0 * 8;
    gsrc[3] = Blo + bbase + (size_t)srow * Dd + sg0 * 8;
    uint32_t soff[2];
    soff[0] = sw64(srow, sg0);
    soff[1] = sw64(srow, sg0 + 1);

    const int wm = wid & 3, wn = wid >> 2;
    const int arow = wm * 32 + (lane & 15);
    const int agsel = lane >> 4;
    const int brow = wn * 64 + (lane & 7) + (lane >> 4) * 8;
    const int bgsel = (lane >> 3) & 1;

    float acc[2][8][4];
    #pragma unroll
    for (int i = 0; i < 2; i++)
        #pragma unroll
        for (int j = 0; j < 8; j++)
            #pragma unroll
            for (int q = 0; q < 4; q++) acc[i][j][q] = 0.f;

    const int KT = Dd / 32;  // 64 chunks

    #pragma unroll
    for (int pc = 0; pc < 2; pc++) {
        uint32_t buf = smb + pc * STAGE32_B;
        #pragma unroll
        for (int t = 0; t < 4; t++) {
            cp16(buf + t * TILE32_B + soff[0], gsrc[t] + pc * 32);
            cp16(buf + t * TILE32_B + soff[1], gsrc[t] + pc * 32 + 8);
        }
        CP_COMMIT();
    }

    int rbuf = 0, wbuf = 2;
    for (int kc = 0; kc < KT; kc++) {
        if (kc + 1 < KT) asm volatile("cp.async.wait_group 1;" ::: "memory");
        else             asm volatile("cp.async.wait_group 0;" ::: "memory");
        __syncthreads();

        if (kc + 2 < KT) {
            uint32_t buf = smb + wbuf * STAGE32_B;
            #pragma unroll
            for (int t = 0; t < 4; t++) {
                cp16(buf + t * TILE32_B + soff[0], gsrc[t] + (kc + 2) * 32);
                cp16(buf + t * TILE32_B + soff[1], gsrc[t] + (kc + 2) * 32 + 8);
            }
            CP_COMMIT();
        }

        const uint32_t tb = smb + rbuf * STAGE32_B;
        #pragma unroll
        for (int ks = 0; ks < 2; ks++) {
            uint32_t ah[2][4], al[2][4];
            #pragma unroll
            for (int mm = 0; mm < 2; mm++) {
                uint32_t ad = sw64(arow + mm * 16, ks * 2 + agsel);
                ldm4(ah[mm], tb + ad);
                ldm4(al[mm], tb + TILE32_B + ad);
            }
            #pragma unroll
            for (int j = 0; j < 4; j++) {
                uint32_t bd = sw64(brow + j * 16, ks * 2 + bgsel);
                uint32_t bh[4], bl[4];
                ldm4(bh, tb + 2 * TILE32_B + bd);
                ldm4(bl, tb + 3 * TILE32_B + bd);
                mma16816(acc[0][2 * j],     ah[0], bh[0], bh[1]);
                mma16816(acc[0][2 * j + 1], ah[0], bh[2], bh[3]);
                mma16816(acc[1][2 * j],     ah[1], bh[0], bh[1]);
                mma16816(acc[1][2 * j + 1], ah[1], bh[2], bh[3]);
                mma16816(acc[0][2 * j],     al[0], bh[0], bh[1]);
                mma16816(acc[0][2 * j + 1], al[0], bh[2], bh[3]);
                mma16816(acc[1][2 * j],     al[1], bh[0], bh[1]);
                mma16816(acc[1][2 * j + 1], al[1], bh[2], bh[3]);
                mma16816(acc[0][2 * j],     ah[0], bl[0], bl[1]);
                mma16816(acc[0][2 * j + 1], ah[0], bl[2], bl[3]);
                mma16816(acc[1][2 * j],     ah[1], bl[0], bl[1]);
                mma16816(acc[1][2 * j + 1], ah[1], bl[2], bl[3]);
            }
        }
        rbuf = (rbuf == 2) ? 0 : rbuf + 1;
        wbuf = (wbuf == 2) ? 0 : wbuf + 1;
    }

    #pragma unroll
    for (int mm = 0; mm < 2; mm++) {
        #pragma unroll
        for (int half = 0; half < 2; half++) {
            const int r = wm * 32 + mm * 16 + (lane >> 2) + half * 8;
            const int m = m0 + r;
            float* rowp;
            if (MODE == 0) {
                const int s = blockIdx.y >> 4, n = blockIdx.y & 15;
                const int b = m >> 11, t = m & (Tt - 1);
                rowp = g_qkv + ((size_t)s * Bx * Nn + (size_t)(b * Nn + n)) * Tt * Hh
                             + (size_t)t * Hh;
            } else {
                rowp = outg + (size_t)m * Dd + blockIdx.y * 128;
            }
            #pragma unroll
            for (int j = 0; j < 8; j++) {
                const int c = wn * 64 + j * 8 + (lane & 3) * 2;
                float2 v;
                v.x = acc[mm][j][half * 2];
                v.y = acc[mm][j][half * 2 + 1];
                *(float2*)(rowp + c) = v;
            }
        }
    }
}

// ---------------------------------------------------------------------------
// RoPE + bf16 split of q (scaled) and k
// ---------------------------------------------------------------------------
__global__ void rope_split_kernel(const int* __restrict__ segment_pos)
{
    const int row = blockIdx.x * 4 + (threadIdx.x >> 6);
    const int h = threadIdx.x & 63;
    const int b = row / (Nn * Tt);
    const int nt = row - b * (Nn * Tt);
    const int n = nt >> 11;
    const int t = nt & (Tt - 1);
    const int pos = segment_pos[b * Tt + t];

    const double ts = pow(10000.0, (double)h / 64.0);
    const float ang = (float)((double)pos / ts);
    float sn, cs;
    sincosf(ang, &sn, &cs);

    const size_t base = ((size_t)(b * Nn + n) * Tt + t) * Hh;
    const float* q = g_qkv + base;
    const float* k = g_qkv + SZQ + base;
    const float qs = 0.08838834764831845f;

    float q1 = q[h], q2 = q[h + 64];
    float qa = (q1 * cs - q2 * sn) * qs;
    float qb = (q2 * cs + q1 * sn) * qs;
    float k1 = k[h], k2 = k[h + 64];
    float ka = k1 * cs - k2 * sn;
    float kb = k2 * cs + k1 * sn;

    __nv_bfloat16 hqa = __float2bfloat16(qa), hqb = __float2bfloat16(qb);
    __nv_bfloat16 hka = __float2bfloat16(ka), hkb = __float2bfloat16(kb);
    g_qh[base + h] = hqa;       g_qh[base + h + 64] = hqb;
    g_ql[base + h] = __float2bfloat16(qa - __bfloat162float(hqa));
    g_ql[base + h + 64] = __float2bfloat16(qb - __bfloat162float(hqb));
    g_kh[base + h] = hka;       g_kh[base + h + 64] = hkb;
    g_kl[base + h] = __float2bfloat16(ka - __bfloat162float(hka));
    g_kl[base + h + 64] = __float2bfloat16(kb - __bfloat162float(hkb));
}

// ---------------------------------------------------------------------------
// V: fp32 [b][n][t][h] -> bf16 hi/lo transposed [b][n][h][t]
// ---------------------------------------------------------------------------
__global__ void vsplit_kernel()
{
    __shared__ float tile[32][33];
    const int bnz = blockIdx.z;
    const int t0 = blockIdx.x * 32, h0 = blockIdx.y * 32;
    const float* v = g_qkv + 2 * SZQ + (size_t)bnz * Tt * Hh;
    #pragma unroll
    for (int i = threadIdx.y; i < 32; i += 8)
        tile[i][threadIdx.x] = v[(size_t)(t0 + i) * Hh + h0 + threadIdx.x];
    __syncthreads();
    const size_t dbase = (size_t)bnz * Hh * Tt;
    #pragma unroll
    for (int i = threadIdx.y; i < 32; i += 8) {
        float val = tile[threadIdx.x][i];
        __nv_bfloat16 hi = __float2bfloat16(val);
        size_t o = dbase + (size_t)(h0 + i) * Tt + t0 + threadIdx.x;
        g_vth[o] = hi;
        g_vtl[o] = __float2bfloat16(val - __bfloat162float(hi));
    }
}

// ---------------------------------------------------------------------------
// Flash attention: 64 q-rows x 32-key chunks, 4 warps, Q in registers,
// 3-stage 32KB ring (96KB -> 2 CTAs/SM), fixed-base softmax fused with PV.
// LPT 1D grid (qt descending).
// ---------------------------------------------------------------------------
#define AT_STAGE 32768
#define ATTN_SMEM3 (3 * 32768)   // 98304
// stage layout: Khi @0 (8KB), Klo @8192, Vhi @16384, Vlo @24576

__global__ void __launch_bounds__(128, 2) attn_mma_kernel()
{
    extern __shared__ char smc[];
    const uint32_t smb = smem_u32(smc);
    const int tid = threadIdx.x;
    const int wid = tid >> 5, lane = tid & 31;
    const int qt = 31 - (blockIdx.x >> 5);
    const int sub = blockIdx.x & 31;
    const int n = sub >> 1, b = sub & 1;
    const int t0 = qt * 64;
    const size_t bn = (size_t)(b * Nn + n) * Tt * Hh;

    const __nv_bfloat16* qhp = g_qh + bn;
    const __nv_bfloat16* qlp = g_ql + bn;
    const __nv_bfloat16* khp = g_kh + bn;
    const __nv_bfloat16* klp = g_kl + bn;
    const __nv_bfloat16* vhp = g_vth + bn;
    const __nv_bfloat16* vlp = g_vtl + bn;

    const int c_lo = (t0 >= WINDOW) ? ((t0 - WINDOW + 1) >> 5) : 0;
    const int c_hi = (t0 + 63) >> 5;

    const int arow = wid * 16 + (lane & 15);
    const int agsel = lane >> 4;
    const int bro = (lane & 7) + ((lane >> 4) << 3);
    const int bgsel = (lane >> 3) & 1;
    const int qr0 = t0 + wid * 16 + (lane >> 2);

    // ---- load Q (64 rows x 128 h, hi/lo) into registers via buffer 0
    uint32_t qhf[8][4], qlf[8][4];
    {
        const int r = tid >> 1;
        const __nv_bfloat16* sh = qhp + (size_t)(t0 + r) * Hh;
        const __nv_bfloat16* sl = qlp + (size_t)(t0 + r) * Hh;
        #pragma unroll
        for (int i = 0; i < 8; i++) {
            int g = (tid & 1) * 8 + i;
            uint32_t off = (uint32_t)(r * 256 + ((g ^ (r & 7)) << 4));
            cp16(smb + off, sh + g * 8);
            cp16(smb + 16384 + off, sl + g * 8);
        }
        CP_COMMIT();
        asm volatile("cp.async.wait_group 0;" ::: "memory");
        __syncthreads();
        #pragma unroll
        for (int ks = 0; ks < 8; ks++) {
            uint32_t qa = (uint32_t)(arow * 256 + (((ks * 2 + agsel) ^ (arow & 7)) << 4));
            ldm4(qhf[ks], smb + qa);
            ldm4(qlf[ks], smb + 16384 + qa);
        }
        __syncthreads();  // all warps done reading buf0 before prologue overwrites
    }

    // ---- prologue: stage chunks c_lo, c_lo+1 into buffers 0, 1
    #pragma unroll 1
    for (int pc = 0; pc < 2; pc++) {
        const int c = c_lo + pc;
        const int k0 = c * 32;
        uint32_t sb = smb + pc * AT_STAGE;
        {   // K: 32 rows x 256B, hi + lo
            const int r = tid >> 2;
            const __nv_bfloat16* sh = khp + (size_t)(k0 + r) * Hh;
            const __nv_bfloat16* sl = klp + (size_t)(k0 + r) * Hh;
            #pragma unroll
            for (int i = 0; i < 4; i++) {
                int g = (tid & 3) * 4 + i;
                uint32_t off = (uint32_t)(r * 256 + ((g ^ (r & 7)) << 4));
                cp16(sb + off, sh + g * 8);
                cp16(sb + 8192 + off, sl + g * 8);
            }
        }
        {   // Vt: 128 rows x 64B, hi + lo
            const int r = tid;
            const __nv_bfloat16* sh = vhp + (size_t)r * Tt + k0;
            const __nv_bfloat16* sl = vlp + (size_t)r * Tt + k0;
            #pragma unroll
            for (int i = 0; i < 4; i++) {
                uint32_t off = sw64(r, i);
                cp16(sb + 16384 + off, sh + i * 8);
                cp16(sb + 24576 + off, sl + i * 8);
            }
        }
        CP_COMMIT();
    }

    float oacc[16][4];
    #pragma unroll
    for (int i = 0; i < 16; i++)
        #pragma unroll
        for (int q = 0; q < 4; q++) oacc[i][q] = 0.f;
    float l0 = 0.f, l1 = 0.f;

    int rbuf = 0, wbuf = 2;
    for (int c = c_lo; c <= c_hi; c++) {
        if (c < c_hi) asm volatile("cp.async.wait_group 1;" ::: "memory");
        else          asm volatile("cp.async.wait_group 0;" ::: "memory");
        __syncthreads();

        // prefetch chunk c+2 into the free buffer
        if (c + 2 <= c_hi) {
            const int k2 = (c + 2) * 32;
            uint32_t sb = smb + wbuf * AT_STAGE;
            {
                const int r = tid >> 2;
                const __nv_bfloat16* sh = khp + (size_t)(k2 + r) * Hh;
                const __nv_bfloat16* sl = klp + (size_t)(k2 + r) * Hh;
                #pragma unroll
                for (int i = 0; i < 4; i++) {
                    int g = (tid & 3) * 4 + i;
                    uint32_t off = (uint32_t)(r * 256 + ((g ^ (r & 7)) << 4));
                    cp16(sb + off, sh + g * 8);
                    cp16(sb + 8192 + off, sl + g * 8);
                }
            }
            {
                const int r = tid;
                const __nv_bfloat16* sh = vhp + (size_t)r * Tt + k2;
                const __nv_bfloat16* sl = vlp + (size_t)r * Tt + k2;
                #pragma unroll
                for (int i = 0; i < 4; i++) {
                    uint32_t off = sw64(r, i);
                    cp16(sb + 16384 + off, sh + i * 8);
                    cp16(sb + 24576 + off, sl + i * 8);
                }
            }
            CP_COMMIT();
        }

        const int k0 = c * 32;
        const bool full = (k0 + 31 <= t0) && (k0 >= t0 - (WINDOW - 64));
        const uint32_t KHb = smb + rbuf * AT_STAGE;
        const uint32_t KLb = KHb + 8192, VHb = KHb + 16384, VLb = KHb + 24576;

        // ---- S = Q K^T (Q from registers), 16 q-rows x 32 keys per warp
        float sacc[4][4];
        #pragma unroll
        for (int i = 0; i < 4; i++)
            #pragma unroll
            for (int q = 0; q < 4; q++) sacc[i][q] = 0.f;

        #pragma unroll
        for (int ks = 0; ks < 8; ks++) {
            #pragma unroll
            for (int nk = 0; nk < 2; nk++) {
                int r = nk * 16 + bro;
                uint32_t ka = (uint32_t)(r * 256 + (((ks * 2 + bgsel) ^ (r & 7)) << 4));
                uint32_t khf[4], klf[4];
                ldm4(khf, KHb + ka);
                ldm4(klf, KLb + ka);
                mma16816(sacc[2 * nk],     qhf[ks], khf[0], khf[1]);
                mma16816(sacc[2 * nk + 1], qhf[ks], khf[2], khf[3]);
                mma16816(sacc[2 * nk],     qlf[ks], khf[0], khf[1]);
                mma16816(sacc[2 * nk + 1], qlf[ks], khf[2], khf[3]);
                mma16816(sacc[2 * nk],     qhf[ks], klf[0], klf[1]);
                mma16816(sacc[2 * nk + 1], qhf[ks], klf[2], klf[3]);
            }
        }

        // ---- fused: per 16-key group, softcap+exp+mask -> pack -> PV
        float s0 = 0.f, s1 = 0.f;
        #pragma unroll
        for (int kt = 0; kt < 2; kt++) {
            #pragma unroll
            for (int sub2 = 0; sub2 < 2; sub2++) {
                int nt = 2 * kt + sub2;
                #pragma unroll
                for (int q = 0; q < 4; q++) {
                    float s = sacc[nt][q];
                    float e = __expf(s * (2.0f / SOFT_CAP));
                    float r = __fdividef(2.0f, e + 1.0f);
                    float p = __expf(SOFT_CAP - SOFT_CAP * r);
                    if (!full) {
                        int qr = qr0 + ((q & 2) ? 8 : 0);
                        int kc = k0 + nt * 8 + (lane & 3) * 2 + (q & 1);
                        if (kc > qr || qr - kc >= WINDOW) p = 0.f;
                    }
                    sacc[nt][q] = p;
                    if (q & 2) s1 += p; else s0 += p;
                }
            }
            uint32_t phi[4], plo[4];
            #pragma unroll
            for (int part = 0; part < 4; part++) {
                int nt = 2 * kt + (part >> 1);
                float x = sacc[nt][(part & 1) * 2];
                float y = sacc[nt][(part & 1) * 2 + 1];
                __nv_bfloat162 h2 = __floats2bfloat162_rn(x, y);
                float lx = x - __bfloat162float(h2.x);
                float ly = y - __bfloat162float(h2.y);
                __nv_bfloat162 l2 = __floats2bfloat162_rn(lx, ly);
                phi[part] = *(uint32_t*)&h2;
                plo[part] = *(uint32_t*)&l2;
            }
            #pragma unroll
            for (int nh = 0; nh < 8; nh++) {
                int r = nh * 16 + bro;
                uint32_t va = sw64(r, kt * 2 + bgsel);
                uint32_t vhf[4], vlf[4];
                ldm4(vhf, VHb + va);
                ldm4(vlf, VLb + va);
                mma16816(oacc[2 * nh],     phi, vhf[0], vhf[1]);
                mma16816(oacc[2 * nh + 1], phi, vhf[2], vhf[3]);
                mma16816(oacc[2 * nh],     plo, vhf[0], vhf[1]);
                mma16816(oacc[2 * nh + 1], plo, vhf[2], vhf[3]);
                mma16816(oacc[2 * nh],     phi, vlf[0], vlf[1]);
                mma16816(oacc[2 * nh + 1], phi, vlf[2], vlf[3]);
            }
        }
        s0 += __shfl_xor_sync(0xffffffffu, s0, 1);
        s0 += __shfl_xor_sync(0xffffffffu, s0, 2);
        s1 += __shfl_xor_sync(0xffffffffu, s1, 1);
        s1 += __shfl_xor_sync(0xffffffffu, s1, 2);
        l0 += s0;
        l1 += s1;

        __syncthreads();  // all warps done reading rbuf before reuse
        rbuf = (rbuf == 2) ? 0 : rbuf + 1;
        wbuf = (wbuf == 2) ? 0 : wbuf + 1;
    }

    // normalize + hi/lo split + write enc directly as bf16 pair arrays
    float inv0 = __fdividef(1.f, l0), inv1 = __fdividef(1.f, l1);
    const int tr0 = t0 + wid * 16 + (lane >> 2);
    #pragma unroll
    for (int nt = 0; nt < 16; nt++) {
        int col = nt * 8 + (lane & 3) * 2;
        size_t o0 = ((size_t)b * Tt + tr0) * Dd + n * Hh + col;
        size_t o1 = ((size_t)b * Tt + tr0 + 8) * Dd + n * Hh + col;
        float x0 = oacc[nt][0] * inv0, y0 = oacc[nt][1] * inv0;
        float x1 = oacc[nt][2] * inv1, y1 = oacc[nt][3] * inv1;
        __nv_bfloat162 h0 = __floats2bfloat162_rn(x0, y0);
        __nv_bfloat162 h1 = __floats2bfloat162_rn(x1, y1);
        __nv_bfloat162 l0v = __floats2bfloat162_rn(x0 - __bfloat162float(h0.x),
                                                   y0 - __bfloat162float(h0.y));
        __nv_bfloat162 l1v = __floats2bfloat162_rn(x1 - __bfloat162float(h1.x),
                                                   y1 - __bfloat162float(h1.y));
        *(__nv_bfloat162*)(g_ehi + o0) = h0;
        *(__nv_bfloat162*)(g_elo + o0) = l0v;
        *(__nv_bfloat162*)(g_ehi + o1) = h1;
        *(__nv_bfloat162*)(g_elo + o1) = l1v;
    }
}

// ---------------------------------------------------------------------------
extern "C" void kernel_launch(void* const* d_in, const int* in_sizes, int n_in,
                              void* d_out, int out_size)
{
    const float* x       = (const float*)d_in[0];
    const float* w_qkv   = (const float*)d_in[1];
    const float* w_out   = (const float*)d_in[2];
    const int*   seg_pos = (const int*)d_in[3];
    float* out = (float*)d_out;

    const int n4 = Bx * Tt * Dd / 4;

    split_x_kernel<<<n4 / 256, 256>>>(x);
    transpose_split_kernel<0><<<dim3(Hh / 32, Dd / 32, 48), dim3(32, 8)>>>(w_qkv, Dd, Hh);
    transpose_split_kernel<1><<<dim3(Dd / 32, Dd / 32, 1), dim3(32, 8)>>>(w_out, Dd, Dd);

    cudaFuncSetAttribute(mma_gemm<0>, cudaFuncAttributeMaxDynamicSharedMemorySize, GEMM_SMEM);
    cudaFuncSetAttribute(mma_gemm<1>, cudaFuncAttributeMaxDynamicSharedMemorySize, GEMM_SMEM);
    cudaFuncSetAttribute(attn_mma_kernel, cudaFuncAttributeMaxDynamicSharedMemorySize, ATTN_SMEM3);

    mma_gemm<0><<<dim3(Bx * Tt / 128, 48), 256, GEMM_SMEM>>>(nullptr);
    rope_split_kernel<<<dim3(Bx * Nn * Tt / 4), 256>>>(seg_pos);
    vsplit_kernel<<<dim3(Tt / 32, Hh / 32, Bx * Nn), dim3(32, 8)>>>();

    attn_mma_kernel<<<dim3(32 * 32), 128, ATTN_SMEM3>>>();

    mma_gemm<1><<<dim3(Bx * Tt / 128, Dd / 128), 256, GEMM_SMEM>>>(out);
}

// round 12
// speedup vs baseline: 1.0021x; 1.0021x over previous
#include <cuda_runtime.h>
#include <cuda_bf16.h>
#include <math.h>
#include <float.h>
#include <stdint.h>

#define Bx 2
#define Tt 2048
#define Dd 2048
#define Nn 16
#define Hh 128
#define WINDOW 1024
#define SOFT_CAP 50.0f

#define SZQ ((size_t)Bx * Nn * Tt * Hh)
#define PAD 8192

// fp32 scratch
__device__ float g_qkv[3ull * Bx * Nn * Tt * Hh];
// bf16 split scratch (GEMMs)
__device__ __nv_bfloat16 g_xhi[(size_t)Bx * Tt * Dd], g_xlo[(size_t)Bx * Tt * Dd];
__device__ __nv_bfloat16 g_wqh[48ull * Hh * Dd],      g_wql[48ull * Hh * Dd];
__device__ __nv_bfloat16 g_woh[(size_t)Dd * Dd],      g_wol[(size_t)Dd * Dd];
__device__ __nv_bfloat16 g_ehi[(size_t)Bx * Tt * Dd], g_elo[(size_t)Bx * Tt * Dd];
// attention operands (padded: 96-key chunks may read past the last row; pad is zero)
__device__ __nv_bfloat16 g_qh[SZQ], g_ql[SZQ];
__device__ __nv_bfloat16 g_kh[SZQ + PAD], g_kl[SZQ + PAD];
__device__ __nv_bfloat16 g_vth[SZQ + PAD], g_vtl[SZQ + PAD];

// ---------------------------------------------------------------------------
// helpers
// ---------------------------------------------------------------------------
__device__ __forceinline__ uint32_t smem_u32(const void* p) {
    uint32_t a;
    asm("{ .reg .u64 t; cvta.to.shared.u64 t, %1; cvt.u32.u64 %0, t; }" : "=r"(a) : "l"(p));
    return a;
}
__device__ __forceinline__ void ldm4(uint32_t* r, uint32_t addr) {
    asm volatile("ldmatrix.sync.aligned.m8n8.x4.shared.b16 {%0,%1,%2,%3}, [%4];"
        : "=r"(r[0]), "=r"(r[1]), "=r"(r[2]), "=r"(r[3]) : "r"(addr));
}
__device__ __forceinline__ void mma16816(float* c, const uint32_t* a, uint32_t b0, uint32_t b1) {
    asm volatile("mma.sync.aligned.m16n8k16.row.col.f32.bf16.bf16.f32 "
        "{%0,%1,%2,%3}, {%4,%5,%6,%7}, {%8,%9}, {%0,%1,%2,%3};"
        : "+f"(c[0]), "+f"(c[1]), "+f"(c[2]), "+f"(c[3])
        : "r"(a[0]), "r"(a[1]), "r"(a[2]), "r"(a[3]), "r"(b0), "r"(b1));
}
__device__ __forceinline__ void cp16(uint32_t dst, const void* src) {
    asm volatile("cp.async.cg.shared.global [%0], [%1], 16;" :: "r"(dst), "l"(src));
}
#define CP_COMMIT() asm volatile("cp.async.commit_group;" ::: "memory")

// ---------------------------------------------------------------------------
// fp32 -> bf16 hi/lo split (straight)
// ---------------------------------------------------------------------------
__device__ __forceinline__ void split4(const float4 v, __nv_bfloat162* H, __nv_bfloat162* L, size_t i2) {
    __nv_bfloat16 h0 = __float2bfloat16(v.x), h1 = __float2bfloat16(v.y);
    __nv_bfloat16 h2 = __float2bfloat16(v.z), h3 = __float2bfloat16(v.w);
    H[i2]     = __nv_bfloat162(h0, h1);
    H[i2 + 1] = __nv_bfloat162(h2, h3);
    L[i2]     = __nv_bfloat162(__float2bfloat16(v.x - __bfloat162float(h0)),
                               __float2bfloat16(v.y - __bfloat162float(h1)));
    L[i2 + 1] = __nv_bfloat162(__float2bfloat16(v.z - __bfloat162float(h2)),
                               __float2bfloat16(v.w - __bfloat162float(h3)));
}

__global__ void split_x_kernel(const float* __restrict__ in) {
    size_t i = (size_t)blockIdx.x * 256 + threadIdx.x;
    float4 v = ((const float4*)in)[i];
    split4(v, (__nv_bfloat162*)g_xhi, (__nv_bfloat162*)g_xlo, i * 2);
}

// ---------------------------------------------------------------------------
// fp32 [mat][R][C] -> bf16 hi/lo [mat][C][R] transpose split (weights)
// ---------------------------------------------------------------------------
template<int WHICH>
__global__ void transpose_split_kernel(const float* __restrict__ in, int R, int C) {
    __shared__ float tile[32][33];
    const int mat = blockIdx.z;
    const int c0 = blockIdx.x * 32, r0 = blockIdx.y * 32;
    const float* A = in + (size_t)mat * R * C;
    #pragma unroll
    for (int i = threadIdx.y; i < 32; i += 8)
        tile[i][threadIdx.x] = A[(size_t)(r0 + i) * C + c0 + threadIdx.x];
    __syncthreads();
    __nv_bfloat16* H = (WHICH == 0 ? g_wqh : g_woh) + (size_t)mat * R * C;
    __nv_bfloat16* L = (WHICH == 0 ? g_wql : g_wol) + (size_t)mat * R * C;
    #pragma unroll
    for (int i = threadIdx.y; i < 32; i += 8) {
        float v = tile[threadIdx.x][i];
        __nv_bfloat16 h = __float2bfloat16(v);
        size_t o = (size_t)(c0 + i) * R + r0 + threadIdx.x;
        H[o] = h;
        L[o] = __float2bfloat16(v - __bfloat162float(h));
    }
}

// ---------------------------------------------------------------------------
// mma.sync GEMM (R6 config): K-chunk 32, 3-stage ring, 256 thr, 2 CTAs/SM
// ---------------------------------------------------------------------------
#define TILE32_B 8192
#define STAGE32_B (4 * TILE32_B)       // 32 KB
#define GEMM_SMEM (3 * STAGE32_B)      // 96 KB

__device__ __forceinline__ uint32_t sw64(int r, int g) {
    return (uint32_t)(r * 64 + ((g ^ ((r >> 1) & 3)) << 4));
}

template<int MODE>
__global__ void __launch_bounds__(256, 2) mma_gemm(float* __restrict__ outg) {
    extern __shared__ char smc[];
    const uint32_t smb = smem_u32(smc);
    const int tid = threadIdx.x;
    const int wid = tid >> 5, lane = tid & 31;
    const int m0 = blockIdx.x * 128;

    const __nv_bfloat16 *Ahi, *Alo, *Bhi, *Blo;
    if (MODE == 0) { Ahi = g_xhi; Alo = g_xlo; Bhi = g_wqh; Blo = g_wql; }
    else           { Ahi = g_ehi; Alo = g_elo; Bhi = g_woh; Blo = g_wol; }

    const int srow = tid >> 1, sg0 = (tid & 1) * 2;
    const size_t bbase = (size_t)blockIdx.y * (128 * Dd);
    const __nv_bfloat16* gsrc[4];
    gsrc[0] = Ahi + (size_t)(m0 + srow) * Dd + sg0 * 8;
    gsrc[1] = Alo + (size_t)(m0 + srow) * Dd + sg0 * 8;
    gsrc[2] = Bhi + bbase + (size_t)srow * Dd + sg0 * 8;
    gsrc[3] = Blo + bbase + (size_t)srow * Dd + sg0 * 8;
    uint32_t soff[2];
    soff[0] = sw64(srow, sg0);
    soff[1] = sw64(srow, sg0 + 1);

    const int wm = wid & 3, wn = wid >> 2;
    const int arow = wm * 32 + (lane & 15);
    const int agsel = lane >> 4;
    const int brow = wn * 64 + (lane & 7) + (lane >> 4) * 8;
    const int bgsel = (lane >> 3) & 1;

    float acc[2][8][4];
    #pragma unroll
    for (int i = 0; i < 2; i++)
        #pragma unroll
        for (int j = 0; j < 8; j++)
            #pragma unroll
            for (int q = 0; q < 4; q++) acc[i][j][q] = 0.f;

    const int KT = Dd / 32;  // 64 chunks

    #pragma unroll
    for (int pc = 0; pc < 2; pc++) {
        uint32_t buf = smb + pc * STAGE32_B;
        #pragma unroll
        for (int t = 0; t < 4; t++) {
            cp16(buf + t * TILE32_B + soff[0], gsrc[t] + pc * 32);
            cp16(buf + t * TILE32_B + soff[1], gsrc[t] + pc * 32 + 8);
        }
        CP_COMMIT();
    }

    int rbuf = 0, wbuf = 2;
    for (int kc = 0; kc < KT; kc++) {
        if (kc + 1 < KT) asm volatile("cp.async.wait_group 1;" ::: "memory");
        else             asm volatile("cp.async.wait_group 0;" ::: "memory");
        __syncthreads();

        if (kc + 2 < KT) {
            uint32_t buf = smb + wbuf * STAGE32_B;
            #pragma unroll
            for (int t = 0; t < 4; t++) {
                cp16(buf + t * TILE32_B + soff[0], gsrc[t] + (kc + 2) * 32);
                cp16(buf + t * TILE32_B + soff[1], gsrc[t] + (kc + 2) * 32 + 8);
            }
            CP_COMMIT();
        }

        const uint32_t tb = smb + rbuf * STAGE32_B;
        #pragma unroll
        for (int ks = 0; ks < 2; ks++) {
            uint32_t ah[2][4], al[2][4];
            #pragma unroll
            for (int mm = 0; mm < 2; mm++) {
                uint32_t ad = sw64(arow + mm * 16, ks * 2 + agsel);
                ldm4(ah[mm], tb + ad);
                ldm4(al[mm], tb + TILE32_B + ad);
            }
            #pragma unroll
            for (int j = 0; j < 4; j++) {
                uint32_t bd = sw64(brow + j * 16, ks * 2 + bgsel);
                uint32_t bh[4], bl[4];
                ldm4(bh, tb + 2 * TILE32_B + bd);
                ldm4(bl, tb + 3 * TILE32_B + bd);
                mma16816(acc[0][2 * j],     ah[0], bh[0], bh[1]);
                mma16816(acc[0][2 * j + 1], ah[0], bh[2], bh[3]);
                mma16816(acc[1][2 * j],     ah[1], bh[0], bh[1]);
                mma16816(acc[1][2 * j + 1], ah[1], bh[2], bh[3]);
                mma16816(acc[0][2 * j],     al[0], bh[0], bh[1]);
                mma16816(acc[0][2 * j + 1], al[0], bh[2], bh[3]);
                mma16816(acc[1][2 * j],     al[1], bh[0], bh[1]);
                mma16816(acc[1][2 * j + 1], al[1], bh[2], bh[3]);
                mma16816(acc[0][2 * j],     ah[0], bl[0], bl[1]);
                mma16816(acc[0][2 * j + 1], ah[0], bl[2], bl[3]);
                mma16816(acc[1][2 * j],     ah[1], bl[0], bl[1]);
                mma16816(acc[1][2 * j + 1], ah[1], bl[2], bl[3]);
            }
        }
        rbuf = (rbuf == 2) ? 0 : rbuf + 1;
        wbuf = (wbuf == 2) ? 0 : wbuf + 1;
    }

    #pragma unroll
    for (int mm = 0; mm < 2; mm++) {
        #pragma unroll
        for (int half = 0; half < 2; half++) {
            const int r = wm * 32 + mm * 16 + (lane >> 2) + half * 8;
            const int m = m0 + r;
            float* rowp;
            if (MODE == 0) {
                const int s = blockIdx.y >> 4, n = blockIdx.y & 15;
                const int b = m >> 11, t = m & (Tt - 1);
                rowp = g_qkv + ((size_t)s * Bx * Nn + (size_t)(b * Nn + n)) * Tt * Hh
                             + (size_t)t * Hh;
            } else {
                rowp = outg + (size_t)m * Dd + blockIdx.y * 128;
            }
            #pragma unroll
            for (int j = 0; j < 8; j++) {
                const int c = wn * 64 + j * 8 + (lane & 3) * 2;
                float2 v;
                v.x = acc[mm][j][half * 2];
                v.y = acc[mm][j][half * 2 + 1];
                *(float2*)(rowp + c) = v;
            }
        }
    }
}

// ---------------------------------------------------------------------------
// RoPE + bf16 split of q (scaled) and k
// ---------------------------------------------------------------------------
__global__ void rope_split_kernel(const int* __restrict__ segment_pos)
{
    const int row = blockIdx.x * 4 + (threadIdx.x >> 6);
    const int h = threadIdx.x & 63;
    const int b = row / (Nn * Tt);
    const int nt = row - b * (Nn * Tt);
    const int n = nt >> 11;
    const int t = nt & (Tt - 1);
    const int pos = segment_pos[b * Tt + t];

    const double ts = pow(10000.0, (double)h / 64.0);
    const float ang = (float)((double)pos / ts);
    float sn, cs;
    sincosf(ang, &sn, &cs);

    const size_t base = ((size_t)(b * Nn + n) * Tt + t) * Hh;
    const float* q = g_qkv + base;
    const float* k = g_qkv + SZQ + base;
    const float qs = 0.08838834764831845f;

    float q1 = q[h], q2 = q[h + 64];
    float qa = (q1 * cs - q2 * sn) * qs;
    float qb = (q2 * cs + q1 * sn) * qs;
    float k1 = k[h], k2 = k[h + 64];
    float ka = k1 * cs - k2 * sn;
    float kb = k2 * cs + k1 * sn;

    __nv_bfloat16 hqa = __float2bfloat16(qa), hqb = __float2bfloat16(qb);
    __nv_bfloat16 hka = __float2bfloat16(ka), hkb = __float2bfloat16(kb);
    g_qh[base + h] = hqa;       g_qh[base + h + 64] = hqb;
    g_ql[base + h] = __float2bfloat16(qa - __bfloat162float(hqa));
    g_ql[base + h + 64] = __float2bfloat16(qb - __bfloat162float(hqb));
    g_kh[base + h] = hka;       g_kh[base + h + 64] = hkb;
    g_kl[base + h] = __float2bfloat16(ka - __bfloat162float(hka));
    g_kl[base + h + 64] = __float2bfloat16(kb - __bfloat162float(hkb));
}

// ---------------------------------------------------------------------------
// V: fp32 [b][n][t][h] -> bf16 hi/lo transposed [b][n][h][t]
// ---------------------------------------------------------------------------
__global__ void vsplit_kernel()
{
    __shared__ float tile[32][33];
    const int bnz = blockIdx.z;
    const int t0 = blockIdx.x * 32, h0 = blockIdx.y * 32;
    const float* v = g_qkv + 2 * SZQ + (size_t)bnz * Tt * Hh;
    #pragma unroll
    for (int i = threadIdx.y; i < 32; i += 8)
        tile[i][threadIdx.x] = v[(size_t)(t0 + i) * Hh + h0 + threadIdx.x];
    __syncthreads();
    const size_t dbase = (size_t)bnz * Hh * Tt;
    #pragma unroll
    for (int i = threadIdx.y; i < 32; i += 8) {
        float val = tile[threadIdx.x][i];
        __nv_bfloat16 hi = __float2bfloat16(val);
        size_t o = dbase + (size_t)(h0 + i) * Tt + t0 + threadIdx.x;
        g_vth[o] = hi;
        g_vtl[o] = __float2bfloat16(val - __bfloat162float(hi));
    }
}

// ---------------------------------------------------------------------------
// Flash attention: 128q x 96-key chunks, Q-hi in regs, Q-lo persistent smem,
// 2-stage 96KB ring, ONE barrier per chunk, fixed-base softmax fused with PV.
// ---------------------------------------------------------------------------
#define CH 96
#define AS_B 98304                      // 96 KB per stage
#define QLO_OFF (2 * AS_B)              // 196608
#define ATTN_SMEM4 (2 * AS_B + 32768)   // 229376
// stage: KH @0 (24K), KL @24576, VH64 @49152 (16K), VL64 @65536,
//        VH32 @81920 (8K), VL32 @90112

__device__ __forceinline__ void stage_chunk96(uint32_t sb, int k0, int tid,
    const __nv_bfloat16* khp, const __nv_bfloat16* klp,
    const __nv_bfloat16* vhp, const __nv_bfloat16* vlp)
{
    // K: 96 rows x 256B (16 granules) hi+lo; 6 granules each per thread
    #pragma unroll
    for (int i = 0; i < 6; i++) {
        int ga = tid * 6 + i;
        int r = ga >> 4, g = ga & 15;
        uint32_t off = (uint32_t)(r * 256 + ((g ^ (r & 7)) << 4));
        const size_t go = (size_t)(k0 + r) * Hh + g * 8;
        cp16(sb + off,         khp + go);
        cp16(sb + 24576 + off, klp + go);
    }
    // V64: 128 rows x 128B (8 granules), keys [0,64)
    #pragma unroll
    for (int i = 0; i < 4; i++) {
        int ga = tid * 4 + i;
        int r = ga >> 3, g = ga & 7;
        uint32_t off = (uint32_t)(r * 128 + ((g ^ (r & 7)) << 4));
        const size_t go = (size_t)r * Tt + k0 + g * 8;
        cp16(sb + 49152 + off, vhp + go);
        cp16(sb + 65536 + off, vlp + go);
    }
    // V32: 128 rows x 64B (4 granules), keys [64,96)
    #pragma unroll
    for (int i = 0; i < 2; i++) {
        int ga = tid * 2 + i;
        int r = ga >> 2, g = ga & 3;
        uint32_t off = sw64(r, g);
        const size_t go = (size_t)r * Tt + k0 + 64 + g * 8;
        cp16(sb + 81920 + off, vhp + go);
        cp16(sb + 90112 + off, vlp + go);
    }
}

__global__ void __launch_bounds__(256, 1) attn_mma_kernel()
{
    extern __shared__ char smc[];
    const uint32_t smb = smem_u32(smc);
    const int tid = threadIdx.x;
    const int wid = tid >> 5, lane = tid & 31;
    const int qt = 15 - (blockIdx.x >> 5);
    const int sub = blockIdx.x & 31;
    const int n = sub >> 1, b = sub & 1;
    const int t0 = qt * 128;
    const size_t bn = (size_t)(b * Nn + n) * Tt * Hh;

    const __nv_bfloat16* qhp = g_qh + bn;
    const __nv_bfloat16* qlp = g_ql + bn;
    const __nv_bfloat16* khp = g_kh + bn;
    const __nv_bfloat16* klp = g_kl + bn;
    const __nv_bfloat16* vhp = g_vth + bn;
    const __nv_bfloat16* vlp = g_vtl + bn;

    const int c_lo = (t0 >= WINDOW) ? ((t0 - WINDOW + 1) / CH) : 0;
    const int c_hi = (t0 + 127) / CH;

    const int arow = wid * 16 + (lane & 15);
    const int agsel = lane >> 4;
    const int bro = (lane & 7) + ((lane >> 4) << 3);
    const int bgsel = (lane >> 3) & 1;
    const int qr0 = t0 + wid * 16 + (lane >> 2);

    // ---- stage Q: hi into buffer 0 (transient), lo into persistent QLO
    uint32_t qhf[8][4];
    {
        const int r = tid >> 1;
        const __nv_bfloat16* sh = qhp + (size_t)(t0 + r) * Hh;
        const __nv_bfloat16* sl = qlp + (size_t)(t0 + r) * Hh;
        #pragma unroll
        for (int i = 0; i < 8; i++) {
            int g = (tid & 1) * 8 + i;
            uint32_t off = (uint32_t)(r * 256 + ((g ^ (r & 7)) << 4));
            cp16(smb + off, sh + g * 8);
            cp16(smb + QLO_OFF + off, sl + g * 8);
        }
        CP_COMMIT();
        asm volatile("cp.async.wait_group 0;" ::: "memory");
        __syncthreads();
        #pragma unroll
        for (int ks = 0; ks < 8; ks++) {
            uint32_t qa = (uint32_t)(arow * 256 + (((ks * 2 + agsel) ^ (arow & 7)) << 4));
            ldm4(qhf[ks], smb + qa);
        }
        __syncthreads();  // buf0 free for prologue
    }

    // ---- prologue: stage chunk c_lo into buffer 0
    stage_chunk96(smb, c_lo * CH, tid, khp, klp, vhp, vlp);
    CP_COMMIT();

    float oacc[16][4];
    #pragma unroll
    for (int i = 0; i < 16; i++)
        #pragma unroll
        for (int q = 0; q < 4; q++) oacc[i][q] = 0.f;
    float l0 = 0.f, l1 = 0.f;

    for (int c = c_lo; c <= c_hi; c++) {
        // chunk c's data was committed exactly one group ago
        asm volatile("cp.async.wait_group 0;" ::: "memory");
        __syncthreads();   // (a) everyone's data arrived (b) everyone done with c-1

        const int buf = (c - c_lo) & 1;
        if (c + 1 <= c_hi) {
            stage_chunk96(smb + (buf ^ 1) * AS_B, (c + 1) * CH, tid, khp, klp, vhp, vlp);
            CP_COMMIT();
        }

        const int k0 = c * CH;
        const bool full = (k0 + CH - 1 <= t0) && (k0 >= t0 - (WINDOW - 128));
        const uint32_t Sb = smb + buf * AS_B;
        const uint32_t KHb = Sb, KLb = Sb + 24576;

        // ---- S = Q K^T (Q-hi regs, Q-lo smem), 16 q-rows x 96 keys per warp
        float sacc[12][4];
        #pragma unroll
        for (int i = 0; i < 12; i++)
            #pragma unroll
            for (int q = 0; q < 4; q++) sacc[i][q] = 0.f;

        #pragma unroll
        for (int ks = 0; ks < 8; ks++) {
            uint32_t qa = (uint32_t)(arow * 256 + (((ks * 2 + agsel) ^ (arow & 7)) << 4));
            uint32_t qlf[4];
            ldm4(qlf, smb + QLO_OFF + qa);
            #pragma unroll
            for (int nk = 0; nk < 6; nk++) {
                int r = nk * 16 + bro;
                uint32_t ka = (uint32_t)(r * 256 + (((ks * 2 + bgsel) ^ (r & 7)) << 4));
                uint32_t khf[4], klf[4];
                ldm4(khf, KHb + ka);
                ldm4(klf, KLb + ka);
                mma16816(sacc[2 * nk],     qhf[ks], khf[0], khf[1]);
                mma16816(sacc[2 * nk + 1], qhf[ks], khf[2], khf[3]);
                mma16816(sacc[2 * nk],     qlf,     khf[0], khf[1]);
                mma16816(sacc[2 * nk + 1], qlf,     khf[2], khf[3]);
                mma16816(sacc[2 * nk],     qhf[ks], klf[0], klf[1]);
                mma16816(sacc[2 * nk + 1], qhf[ks], klf[2], klf[3]);
            }
        }

        // ---- fused: per 16-key group, softcap+exp+mask -> pack -> PV
        float s0 = 0.f, s1 = 0.f;
        #pragma unroll
        for (int kt = 0; kt < 6; kt++) {
            #pragma unroll
            for (int sub2 = 0; sub2 < 2; sub2++) {
                int nt = 2 * kt + sub2;
                #pragma unroll
                for (int q = 0; q < 4; q++) {
                    float s = sacc[nt][q];
                    float e = __expf(s * (2.0f / SOFT_CAP));
                    float r = __fdividef(2.0f, e + 1.0f);
                    float p = __expf(SOFT_CAP - SOFT_CAP * r);
                    if (!full) {
                        int qr = qr0 + ((q & 2) ? 8 : 0);
                        int kc = k0 + nt * 8 + (lane & 3) * 2 + (q & 1);
                        if (kc > qr || qr - kc >= WINDOW) p = 0.f;
                    }
                    sacc[nt][q] = p;
                    if (q & 2) s1 += p; else s0 += p;
                }
            }
            uint32_t phi[4], plo[4];
            #pragma unroll
            for (int part = 0; part < 4; part++) {
                int nt = 2 * kt + (part >> 1);
                float x = sacc[nt][(part & 1) * 2];
                float y = sacc[nt][(part & 1) * 2 + 1];
                __nv_bfloat162 h2 = __floats2bfloat162_rn(x, y);
                float lx = x - __bfloat162float(h2.x);
                float ly = y - __bfloat162float(h2.y);
                __nv_bfloat162 l2 = __floats2bfloat162_rn(lx, ly);
                phi[part] = *(uint32_t*)&h2;
                plo[part] = *(uint32_t*)&l2;
            }
            #pragma unroll
            for (int nh = 0; nh < 8; nh++) {
                int r = nh * 16 + bro;
                uint32_t vah, val;
                if (kt < 4) {
                    uint32_t o = (uint32_t)(r * 128 + (((kt * 2 + bgsel) ^ (r & 7)) << 4));
                    vah = Sb + 49152 + o;
                    val = Sb + 65536 + o;
                } else {
                    uint32_t o = sw64(r, (kt - 4) * 2 + bgsel);
                    vah = Sb + 81920 + o;
                    val = Sb + 90112 + o;
                }
                uint32_t vhf[4], vlf[4];
                ldm4(vhf, vah);
                ldm4(vlf, val);
                mma16816(oacc[2 * nh],     phi, vhf[0], vhf[1]);
                mma16816(oacc[2 * nh + 1], phi, vhf[2], vhf[3]);
                mma16816(oacc[2 * nh],     plo, vhf[0], vhf[1]);
                mma16816(oacc[2 * nh + 1], plo, vhf[2], vhf[3]);
                mma16816(oacc[2 * nh],     phi, vlf[0], vlf[1]);
                mma16816(oacc[2 * nh + 1], phi, vlf[2], vlf[3]);
            }
        }
        s0 += __shfl_xor_sync(0xffffffffu, s0, 1);
        s0 += __shfl_xor_sync(0xffffffffu, s0, 2);
        s1 += __shfl_xor_sync(0xffffffffu, s1, 1);
        s1 += __shfl_xor_sync(0xffffffffu, s1, 2);
        l0 += s0;
        l1 += s1;
    }

    // normalize + hi/lo split + write enc directly as bf16 pair arrays
    float inv0 = __fdividef(1.f, l0), inv1 = __fdividef(1.f, l1);
    const int tr0 = t0 + wid * 16 + (lane >> 2);
    #pragma unroll
    for (int nt = 0; nt < 16; nt++) {
        int col = nt * 8 + (lane & 3) * 2;
        size_t o0 = ((size_t)b * Tt + tr0) * Dd + n * Hh + col;
        size_t o1 = ((size_t)b * Tt + tr0 + 8) * Dd + n * Hh + col;
        float x0 = oacc[nt][0] * inv0, y0 = oacc[nt][1] * inv0;
        float x1 = oacc[nt][2] * inv1, y1 = oacc[nt][3] * inv1;
        __nv_bfloat162 h0 = __floats2bfloat162_rn(x0, y0);
        __nv_bfloat162 h1 = __floats2bfloat162_rn(x1, y1);
        __nv_bfloat162 l0v = __floats2bfloat162_rn(x0 - __bfloat162float(h0.x),
                                                   y0 - __bfloat162float(h0.y));
        __nv_bfloat162 l1v = __floats2bfloat162_rn(x1 - __bfloat162float(h1.x),
                                                   y1 - __bfloat162float(h1.y));
        *(__nv_bfloat162*)(g_ehi + o0) = h0;
        *(__nv_bfloat162*)(g_elo + o0) = l0v;
        *(__nv_bfloat162*)(g_ehi + o1) = h1;
        *(__nv_bfloat162*)(g_elo + o1) = l1v;
    }
}

// ---------------------------------------------------------------------------
extern "C" void kernel_launch(void* const* d_in, const int* in_sizes, int n_in,
                              void* d_out, int out_size)
{
    const float* x       = (const float*)d_in[0];
    const float* w_qkv   = (const float*)d_in[1];
    const float* w_out   = (const float*)d_in[2];
    const int*   seg_pos = (const int*)d_in[3];
    float* out = (float*)d_out;

    const int n4 = Bx * Tt * Dd / 4;

    split_x_kernel<<<n4 / 256, 256>>>(x);
    transpose_split_kernel<0><<<dim3(Hh / 32, Dd / 32, 48), dim3(32, 8)>>>(w_qkv, Dd, Hh);
    transpose_split_kernel<1><<<dim3(Dd / 32, Dd / 32, 1), dim3(32, 8)>>>(w_out, Dd, Dd);

    cudaFuncSetAttribute(mma_gemm<0>, cudaFuncAttributeMaxDynamicSharedMemorySize, GEMM_SMEM);
    cudaFuncSetAttribute(mma_gemm<1>, cudaFuncAttributeMaxDynamicSharedMemorySize, GEMM_SMEM);
    cudaFuncSetAttribute(attn_mma_kernel, cudaFuncAttributeMaxDynamicSharedMemorySize, ATTN_SMEM4);

    mma_gemm<0><<<dim3(Bx * Tt / 128, 48), 256, GEMM_SMEM>>>(nullptr);
    rope_split_kernel<<<dim3(Bx * Nn * Tt / 4), 256>>>(seg_pos);
    vsplit_kernel<<<dim3(Tt / 32, Hh / 32, Bx * Nn), dim3(32, 8)>>>();

    attn_mma_kernel<<<dim3(16 * Nn * Bx), 256, ATTN_SMEM4>>>();

    mma_gemm<1><<<dim3(Bx * Tt / 128, Dd / 128), 256, GEMM_SMEM>>>(out);
}

// round 13
// speedup vs baseline: 1.0189x; 1.0168x over previous
#include <cuda_runtime.h>
#include <cuda_bf16.h>
#include <math.h>
#include <float.h>
#include <stdint.h>

#define Bx 2
#define Tt 2048
#define Dd 2048
#define Nn 16
#define Hh 128
#define WINDOW 1024
#define SOFT_CAP 50.0f

#define SZQ ((size_t)Bx * Nn * Tt * Hh)

// fp32 scratch
__device__ float g_qkv[3ull * Bx * Nn * Tt * Hh];
// bf16 split scratch (GEMMs)
__device__ __nv_bfloat16 g_xhi[(size_t)Bx * Tt * Dd], g_xlo[(size_t)Bx * Tt * Dd];
__device__ __nv_bfloat16 g_wqh[48ull * Hh * Dd],      g_wql[48ull * Hh * Dd];
__device__ __nv_bfloat16 g_woh[(size_t)Dd * Dd],      g_wol[(size_t)Dd * Dd];
__device__ __nv_bfloat16 g_ehi[(size_t)Bx * Tt * Dd], g_elo[(size_t)Bx * Tt * Dd];
// bf16 split scratch (attention): q,k as [b][n][t][h]; v transposed [b][n][h][t]
__device__ __nv_bfloat16 g_qh[SZQ], g_ql[SZQ];
__device__ __nv_bfloat16 g_kh[SZQ], g_kl[SZQ];
__device__ __nv_bfloat16 g_vth[SZQ], g_vtl[SZQ];

// ---------------------------------------------------------------------------
// helpers
// ---------------------------------------------------------------------------
__device__ __forceinline__ uint32_t smem_u32(const void* p) {
    uint32_t a;
    asm("{ .reg .u64 t; cvta.to.shared.u64 t, %1; cvt.u32.u64 %0, t; }" : "=r"(a) : "l"(p));
    return a;
}
__device__ __forceinline__ void ldm4(uint32_t* r, uint32_t addr) {
    asm volatile("ldmatrix.sync.aligned.m8n8.x4.shared.b16 {%0,%1,%2,%3}, [%4];"
        : "=r"(r[0]), "=r"(r[1]), "=r"(r[2]), "=r"(r[3]) : "r"(addr));
}
__device__ __forceinline__ void mma16816(float* c, const uint32_t* a, uint32_t b0, uint32_t b1) {
    asm volatile("mma.sync.aligned.m16n8k16.row.col.f32.bf16.bf16.f32 "
        "{%0,%1,%2,%3}, {%4,%5,%6,%7}, {%8,%9}, {%0,%1,%2,%3};"
        : "+f"(c[0]), "+f"(c[1]), "+f"(c[2]), "+f"(c[3])
        : "r"(a[0]), "r"(a[1]), "r"(a[2]), "r"(a[3]), "r"(b0), "r"(b1));
}
__device__ __forceinline__ void cp16(uint32_t dst, const void* src) {
    asm volatile("cp.async.cg.shared.global [%0], [%1], 16;" :: "r"(dst), "l"(src));
}
#define CP_COMMIT() asm volatile("cp.async.commit_group;" ::: "memory")

// ---------------------------------------------------------------------------
// fp32 -> bf16 hi/lo split (straight)
// ---------------------------------------------------------------------------
__device__ __forceinline__ void split4(const float4 v, __nv_bfloat162* H, __nv_bfloat162* L, size_t i2) {
    __nv_bfloat16 h0 = __float2bfloat16(v.x), h1 = __float2bfloat16(v.y);
    __nv_bfloat16 h2 = __float2bfloat16(v.z), h3 = __float2bfloat16(v.w);
    H[i2]     = __nv_bfloat162(h0, h1);
    H[i2 + 1] = __nv_bfloat162(h2, h3);
    L[i2]     = __nv_bfloat162(__float2bfloat16(v.x - __bfloat162float(h0)),
                               __float2bfloat16(v.y - __bfloat162float(h1)));
    L[i2 + 1] = __nv_bfloat162(__float2bfloat16(v.z - __bfloat162float(h2)),
                               __float2bfloat16(v.w - __bfloat162float(h3)));
}

__global__ void split_x_kernel(const float* __restrict__ in) {
    size_t i = (size_t)blockIdx.x * 256 + threadIdx.x;
    float4 v = ((const float4*)in)[i];
    split4(v, (__nv_bfloat162*)g_xhi, (__nv_bfloat162*)g_xlo, i * 2);
}

// ---------------------------------------------------------------------------
// fp32 [mat][R][C] -> bf16 hi/lo [mat][C][R] transpose split (weights)
// ---------------------------------------------------------------------------
template<int WHICH>
__global__ void transpose_split_kernel(const float* __restrict__ in, int R, int C) {
    __shared__ float tile[32][33];
    const int mat = blockIdx.z;
    const int c0 = blockIdx.x * 32, r0 = blockIdx.y * 32;
    const float* A = in + (size_t)mat * R * C;
    #pragma unroll
    for (int i = threadIdx.y; i < 32; i += 8)
        tile[i][threadIdx.x] = A[(size_t)(r0 + i) * C + c0 + threadIdx.x];
    __syncthreads();
    __nv_bfloat16* H = (WHICH == 0 ? g_wqh : g_woh) + (size_t)mat * R * C;
    __nv_bfloat16* L = (WHICH == 0 ? g_wql : g_wol) + (size_t)mat * R * C;
    #pragma unroll
    for (int i = threadIdx.y; i < 32; i += 8) {
        float v = tile[threadIdx.x][i];
        __nv_bfloat16 h = __float2bfloat16(v);
        size_t o = (size_t)(c0 + i) * R + r0 + threadIdx.x;
        H[o] = h;
        L[o] = __float2bfloat16(v - __bfloat162float(h));
    }
}

// ---------------------------------------------------------------------------
// mma.sync GEMM (R6 config): K-chunk 32, 3-stage ring, 256 thr, 2 CTAs/SM
// ---------------------------------------------------------------------------
#define TILE32_B 8192
#define STAGE32_B (4 * TILE32_B)       // 32 KB
#define GEMM_SMEM (3 * STAGE32_B)      // 96 KB

__device__ __forceinline__ uint32_t sw64(int r, int g) {
    return (uint32_t)(r * 64 + ((g ^ ((r >> 1) & 3)) << 4));
}

template<int MODE>
__global__ void __launch_bounds__(256, 2) mma_gemm(float* __restrict__ outg) {
    extern __shared__ char smc[];
    const uint32_t smb = smem_u32(smc);
    const int tid = threadIdx.x;
    const int wid = tid >> 5, lane = tid & 31;
    const int m0 = blockIdx.x * 128;

    const __nv_bfloat16 *Ahi, *Alo, *Bhi, *Blo;
    if (MODE == 0) { Ahi = g_xhi; Alo = g_xlo; Bhi = g_wqh; Blo = g_wql; }
    else           { Ahi = g_ehi; Alo = g_elo; Bhi = g_woh; Blo = g_wol; }

    const int srow = tid >> 1, sg0 = (tid & 1) * 2;
    const size_t bbase = (size_t)blockIdx.y * (128 * Dd);
    const __nv_bfloat16* gsrc[4];
    gsrc[0] = Ahi + (size_t)(m0 + srow) * Dd + sg0 * 8;
    gsrc[1] = Alo + (size_t)(m0 + srow) * Dd + sg0 * 8;
    gsrc[2] = Bhi + bbase + (size_t)srow * Dd + sg0 * 8;
    gsrc[3] = Blo + bbase + (size_t)srow * Dd + sg0 * 8;
    uint32_t soff[2];
    soff[0] = sw64(srow, sg0);
    soff[1] = sw64(srow, sg0 + 1);

    const int wm = wid & 3, wn = wid >> 2;
    const int arow = wm * 32 + (lane & 15);
    const int agsel = lane >> 4;
    const int brow = wn * 64 + (lane & 7) + (lane >> 4) * 8;
    const int bgsel = (lane >> 3) & 1;

    float acc[2][8][4];
    #pragma unroll
    for (int i = 0; i < 2; i++)
        #pragma unroll
        for (int j = 0; j < 8; j++)
            #pragma unroll
            for (int q = 0; q < 4; q++) acc[i][j][q] = 0.f;

    const int KT = Dd / 32;  // 64 chunks

    #pragma unroll
    for (int pc = 0; pc < 2; pc++) {
        uint32_t buf = smb + pc * STAGE32_B;
        #pragma unroll
        for (int t = 0; t < 4; t++) {
            cp16(buf + t * TILE32_B + soff[0], gsrc[t] + pc * 32);
            cp16(buf + t * TILE32_B + soff[1], gsrc[t] + pc * 32 + 8);
        }
        CP_COMMIT();
    }

    int rbuf = 0, wbuf = 2;
    for (int kc = 0; kc < KT; kc++) {
        if (kc + 1 < KT) asm volatile("cp.async.wait_group 1;" ::: "memory");
        else             asm volatile("cp.async.wait_group 0;" ::: "memory");
        __syncthreads();

        if (kc + 2 < KT) {
            uint32_t buf = smb + wbuf * STAGE32_B;
            #pragma unroll
            for (int t = 0; t < 4; t++) {
                cp16(buf + t * TILE32_B + soff[0], gsrc[t] + (kc + 2) * 32);
                cp16(buf + t * TILE32_B + soff[1], gsrc[t] + (kc + 2) * 32 + 8);
            }
            CP_COMMIT();
        }

        const uint32_t tb = smb + rbuf * STAGE32_B;
        #pragma unroll
        for (int ks = 0; ks < 2; ks++) {
            uint32_t ah[2][4], al[2][4];
            #pragma unroll
            for (int mm = 0; mm < 2; mm++) {
                uint32_t ad = sw64(arow + mm * 16, ks * 2 + agsel);
                ldm4(ah[mm], tb + ad);
                ldm4(al[mm], tb + TILE32_B + ad);
            }
            #pragma unroll
            for (int j = 0; j < 4; j++) {
                uint32_t bd = sw64(brow + j * 16, ks * 2 + bgsel);
                uint32_t bh[4], bl[4];
                ldm4(bh, tb + 2 * TILE32_B + bd);
                ldm4(bl, tb + 3 * TILE32_B + bd);
                mma16816(acc[0][2 * j],     ah[0], bh[0], bh[1]);
                mma16816(acc[0][2 * j + 1], ah[0], bh[2], bh[3]);
                mma16816(acc[1][2 * j],     ah[1], bh[0], bh[1]);
                mma16816(acc[1][2 * j + 1], ah[1], bh[2], bh[3]);
                mma16816(acc[0][2 * j],     al[0], bh[0], bh[1]);
                mma16816(acc[0][2 * j + 1], al[0], bh[2], bh[3]);
                mma16816(acc[1][2 * j],     al[1], bh[0], bh[1]);
                mma16816(acc[1][2 * j + 1], al[1], bh[2], bh[3]);
                mma16816(acc[0][2 * j],     ah[0], bl[0], bl[1]);
                mma16816(acc[0][2 * j + 1], ah[0], bl[2], bl[3]);
                mma16816(acc[1][2 * j],     ah[1], bl[0], bl[1]);
                mma16816(acc[1][2 * j + 1], ah[1], bl[2], bl[3]);
            }
        }
        rbuf = (rbuf == 2) ? 0 : rbuf + 1;
        wbuf = (wbuf == 2) ? 0 : wbuf + 1;
    }

    #pragma unroll
    for (int mm = 0; mm < 2; mm++) {
        #pragma unroll
        for (int half = 0; half < 2; half++) {
            const int r = wm * 32 + mm * 16 + (lane >> 2) + half * 8;
            const int m = m0 + r;
            float* rowp;
            if (MODE == 0) {
                const int s = blockIdx.y >> 4, n = blockIdx.y & 15;
                const int b = m >> 11, t = m & (Tt - 1);
                rowp = g_qkv + ((size_t)s * Bx * Nn + (size_t)(b * Nn + n)) * Tt * Hh
                             + (size_t)t * Hh;
            } else {
                rowp = outg + (size_t)m * Dd + blockIdx.y * 128;
            }
            #pragma unroll
            for (int j = 0; j < 8; j++) {
                const int c = wn * 64 + j * 8 + (lane & 3) * 2;
                float2 v;
                v.x = acc[mm][j][half * 2];
                v.y = acc[mm][j][half * 2 + 1];
                *(float2*)(rowp + c) = v;
            }
        }
    }
}

// ---------------------------------------------------------------------------
// RoPE + bf16 split of q (scaled) and k
// ---------------------------------------------------------------------------
__global__ void rope_split_kernel(const int* __restrict__ segment_pos)
{
    const int row = blockIdx.x * 4 + (threadIdx.x >> 6);
    const int h = threadIdx.x & 63;
    const int b = row / (Nn * Tt);
    const int nt = row - b * (Nn * Tt);
    const int n = nt >> 11;
    const int t = nt & (Tt - 1);
    const int pos = segment_pos[b * Tt + t];

    const double ts = pow(10000.0, (double)h / 64.0);
    const float ang = (float)((double)pos / ts);
    float sn, cs;
    sincosf(ang, &sn, &cs);

    const size_t base = ((size_t)(b * Nn + n) * Tt + t) * Hh;
    const float* q = g_qkv + base;
    const float* k = g_qkv + SZQ + base;
    const float qs = 0.08838834764831845f;

    float q1 = q[h], q2 = q[h + 64];
    float qa = (q1 * cs - q2 * sn) * qs;
    float qb = (q2 * cs + q1 * sn) * qs;
    float k1 = k[h], k2 = k[h + 64];
    float ka = k1 * cs - k2 * sn;
    float kb = k2 * cs + k1 * sn;

    __nv_bfloat16 hqa = __float2bfloat16(qa), hqb = __float2bfloat16(qb);
    __nv_bfloat16 hka = __float2bfloat16(ka), hkb = __float2bfloat16(kb);
    g_qh[base + h] = hqa;       g_qh[base + h + 64] = hqb;
    g_ql[base + h] = __float2bfloat16(qa - __bfloat162float(hqa));
    g_ql[base + h + 64] = __float2bfloat16(qb - __bfloat162float(hqb));
    g_kh[base + h] = hka;       g_kh[base + h + 64] = hkb;
    g_kl[base + h] = __float2bfloat16(ka - __bfloat162float(hka));
    g_kl[base + h + 64] = __float2bfloat16(kb - __bfloat162float(hkb));
}

// ---------------------------------------------------------------------------
// V: fp32 [b][n][t][h] -> bf16 hi/lo transposed [b][n][h][t]
// ---------------------------------------------------------------------------
__global__ void vsplit_kernel()
{
    __shared__ float tile[32][33];
    const int bnz = blockIdx.z;
    const int t0 = blockIdx.x * 32, h0 = blockIdx.y * 32;
    const float* v = g_qkv + 2 * SZQ + (size_t)bnz * Tt * Hh;
    #pragma unroll
    for (int i = threadIdx.y; i < 32; i += 8)
        tile[i][threadIdx.x] = v[(size_t)(t0 + i) * Hh + h0 + threadIdx.x];
    __syncthreads();
    const size_t dbase = (size_t)bnz * Hh * Tt;
    #pragma unroll
    for (int i = threadIdx.y; i < 32; i += 8) {
        float val = tile[threadIdx.x][i];
        __nv_bfloat16 hi = __float2bfloat16(val);
        size_t o = dbase + (size_t)(h0 + i) * Tt + t0 + threadIdx.x;
        g_vth[o] = hi;
        g_vtl[o] = __float2bfloat16(val - __bfloat162float(hi));
    }
}

// ---------------------------------------------------------------------------
// Flash attention (R10 base): 128q x 64key chunks, Q in registers, 3-stage
// ring, fixed-base softmax; MMA streams reordered for accumulator reuse
// distance 8 (was 2) in both QK and PV.
// ---------------------------------------------------------------------------
#define AT_STAGE 65536
#define ATTN_SMEM2 (3 * 65536)   // 196608

__global__ void __launch_bounds__(256, 1) attn_mma_kernel()
{
    extern __shared__ char smc[];
    const uint32_t smb = smem_u32(smc);
    const int tid = threadIdx.x;
    const int wid = tid >> 5, lane = tid & 31;
    const int qt = 15 - (blockIdx.x >> 5);
    const int sub = blockIdx.x & 31;
    const int n = sub >> 1, b = sub & 1;
    const int t0 = qt * 128;
    const size_t bn = (size_t)(b * Nn + n) * Tt * Hh;

    const __nv_bfloat16* qhp = g_qh + bn;
    const __nv_bfloat16* qlp = g_ql + bn;
    const __nv_bfloat16* khp = g_kh + bn;
    const __nv_bfloat16* klp = g_kl + bn;
    const __nv_bfloat16* vhp = g_vth + bn;
    const __nv_bfloat16* vlp = g_vtl + bn;

    const int c_lo = (t0 >= WINDOW) ? ((t0 - WINDOW + 1) >> 6) : 0;
    const int c_hi = (t0 + 127) >> 6;

    const int arow = wid * 16 + (lane & 15);
    const int agsel = lane >> 4;
    const int bro = (lane & 7) + ((lane >> 4) << 3);
    const int bgsel = (lane >> 3) & 1;
    const int qr0 = t0 + wid * 16 + (lane >> 2);

    // ---- load Q into registers via one-time smem staging in buffer 0
    uint32_t qhf[8][4], qlf[8][4];
    {
        const int r = tid >> 1;
        const __nv_bfloat16* sh = qhp + (size_t)(t0 + r) * Hh;
        const __nv_bfloat16* sl = qlp + (size_t)(t0 + r) * Hh;
        #pragma unroll
        for (int i = 0; i < 8; i++) {
            int g = (tid & 1) * 8 + i;
            uint32_t off = (uint32_t)(r * 256 + ((g ^ (r & 7)) << 4));
            cp16(smb + off, sh + g * 8);
            cp16(smb + 32768 + off, sl + g * 8);
        }
        CP_COMMIT();
        asm volatile("cp.async.wait_group 0;" ::: "memory");
        __syncthreads();
        #pragma unroll
        for (int ks = 0; ks < 8; ks++) {
            uint32_t qa = (uint32_t)(arow * 256 + (((ks * 2 + agsel) ^ (arow & 7)) << 4));
            ldm4(qhf[ks], smb + qa);
            ldm4(qlf[ks], smb + 32768 + qa);
        }
        __syncthreads();  // all warps done reading buf0 before prologue overwrites
    }

    // ---- prologue: stage chunks c_lo, c_lo+1 into buffers 0, 1
    #pragma unroll 1
    for (int pc = 0; pc < 2; pc++) {
        const int c = c_lo + pc;
        const int k0 = c * 64;
        uint32_t sb = smb + pc * AT_STAGE;
        {
            const int r = tid >> 2;
            const __nv_bfloat16* sh = khp + (size_t)(k0 + r) * Hh;
            const __nv_bfloat16* sl = klp + (size_t)(k0 + r) * Hh;
            #pragma unroll
            for (int i = 0; i < 4; i++) {
                int g = (tid & 3) * 4 + i;
                uint32_t off = (uint32_t)(r * 256 + ((g ^ (r & 7)) << 4));
                cp16(sb + off, sh + g * 8);
                cp16(sb + 16384 + off, sl + g * 8);
            }
        }
        {
            const int r = tid >> 1;
            const __nv_bfloat16* sh = vhp + (size_t)r * Tt + k0;
            const __nv_bfloat16* sl = vlp + (size_t)r * Tt + k0;
            #pragma unroll
            for (int i = 0; i < 4; i++) {
                int g = (tid & 1) * 4 + i;
                uint32_t off = (uint32_t)(r * 128 + ((g ^ (r & 7)) << 4));
                cp16(sb + 32768 + off, sh + g * 8);
                cp16(sb + 49152 + off, sl + g * 8);
            }
        }
        CP_COMMIT();
    }

    float oacc[16][4];
    #pragma unroll
    for (int i = 0; i < 16; i++)
        #pragma unroll
        for (int q = 0; q < 4; q++) oacc[i][q] = 0.f;
    float l0 = 0.f, l1 = 0.f;

    int rbuf = 0, wbuf = 2;
    for (int c = c_lo; c <= c_hi; c++) {
        if (c < c_hi) asm volatile("cp.async.wait_group 1;" ::: "memory");
        else          asm volatile("cp.async.wait_group 0;" ::: "memory");
        __syncthreads();

        // prefetch chunk c+2 into the free buffer (freed at end of iter c-1)
        if (c + 2 <= c_hi) {
            const int k2 = (c + 2) * 64;
            uint32_t sb = smb + wbuf * AT_STAGE;
            {
                const int r = tid >> 2;
                const __nv_bfloat16* sh = khp + (size_t)(k2 + r) * Hh;
                const __nv_bfloat16* sl = klp + (size_t)(k2 + r) * Hh;
                #pragma unroll
                for (int i = 0; i < 4; i++) {
                    int g = (tid & 3) * 4 + i;
                    uint32_t off = (uint32_t)(r * 256 + ((g ^ (r & 7)) << 4));
                    cp16(sb + off, sh + g * 8);
                    cp16(sb + 16384 + off, sl + g * 8);
                }
            }
            {
                const int r = tid >> 1;
                const __nv_bfloat16* sh = vhp + (size_t)r * Tt + k2;
                const __nv_bfloat16* sl = vlp + (size_t)r * Tt + k2;
                #pragma unroll
                for (int i = 0; i < 4; i++) {
                    int g = (tid & 1) * 4 + i;
                    uint32_t off = (uint32_t)(r * 128 + ((g ^ (r & 7)) << 4));
                    cp16(sb + 32768 + off, sh + g * 8);
                    cp16(sb + 49152 + off, sl + g * 8);
                }
            }
            CP_COMMIT();
        }

        const int k0 = c * 64;
        const bool full = (k0 <= t0 - 64) && (k0 >= t0 - (WINDOW - 128));
        const uint32_t KHb = smb + rbuf * AT_STAGE;
        const uint32_t KLb = KHb + 16384, VHb = KHb + 32768, VLb = KHb + 49152;

        // ---- S = Q K^T (Q from registers); term-major MMA order:
        // per ks, load all 4 nk K frags, then 3 passes over 8 accumulators.
        float sacc[8][4];
        #pragma unroll
        for (int i = 0; i < 8; i++)
            #pragma unroll
            for (int q = 0; q < 4; q++) sacc[i][q] = 0.f;

        #pragma unroll
        for (int ks = 0; ks < 8; ks++) {
            uint32_t khf[4][4], klf[4][4];
            #pragma unroll
            for (int nk = 0; nk < 4; nk++) {
                int r = nk * 16 + bro;
                uint32_t ka = (uint32_t)(r * 256 + (((ks * 2 + bgsel) ^ (r & 7)) << 4));
                ldm4(khf[nk], KHb + ka);
                ldm4(klf[nk], KLb + ka);
            }
            #pragma unroll
            for (int nk = 0; nk < 4; nk++) {
                mma16816(sacc[2 * nk],     qhf[ks], khf[nk][0], khf[nk][1]);
                mma16816(sacc[2 * nk + 1], qhf[ks], khf[nk][2], khf[nk][3]);
            }
            #pragma unroll
            for (int nk = 0; nk < 4; nk++) {
                mma16816(sacc[2 * nk],     qlf[ks], khf[nk][0], khf[nk][1]);
                mma16816(sacc[2 * nk + 1], qlf[ks], khf[nk][2], khf[nk][3]);
            }
            #pragma unroll
            for (int nk = 0; nk < 4; nk++) {
                mma16816(sacc[2 * nk],     qhf[ks], klf[nk][0], klf[nk][1]);
                mma16816(sacc[2 * nk + 1], qhf[ks], klf[nk][2], klf[nk][3]);
            }
        }

        // ---- softcap + mask + exp (fixed base), pack P
        float s0 = 0.f, s1 = 0.f;
        uint32_t phi[4][4], plo[4][4];
        #pragma unroll
        for (int nt = 0; nt < 8; nt++)
            #pragma unroll
            for (int q = 0; q < 4; q++) {
                float s = sacc[nt][q];
                float e = __expf(s * (2.0f / SOFT_CAP));
                float r = __fdividef(2.0f, e + 1.0f);
                float p = __expf(SOFT_CAP - SOFT_CAP * r);
                if (!full) {
                    int qr = qr0 + ((q & 2) ? 8 : 0);
                    int kc = k0 + nt * 8 + (lane & 3) * 2 + (q & 1);
                    if (kc > qr || qr - kc >= WINDOW) p = 0.f;
                }
                sacc[nt][q] = p;
                if (q & 2) s1 += p; else s0 += p;
            }
        #pragma unroll
        for (int kt = 0; kt < 4; kt++) {
            #pragma unroll
            for (int part = 0; part < 4; part++) {
                int nt = 2 * kt + (part >> 1);
                float x = sacc[nt][(part & 1) * 2];
                float y = sacc[nt][(part & 1) * 2 + 1];
                __nv_bfloat162 h2 = __floats2bfloat162_rn(x, y);
                float lx = x - __bfloat162float(h2.x);
                float ly = y - __bfloat162float(h2.y);
                __nv_bfloat162 l2 = __floats2bfloat162_rn(lx, ly);
                phi[kt][part] = *(uint32_t*)&h2;
                plo[kt][part] = *(uint32_t*)&l2;
            }
        }
        s0 += __shfl_xor_sync(0xffffffffu, s0, 1);
        s0 += __shfl_xor_sync(0xffffffffu, s0, 2);
        s1 += __shfl_xor_sync(0xffffffffu, s1, 1);
        s1 += __shfl_xor_sync(0xffffffffu, s1, 2);
        l0 += s0;
        l1 += s1;

        // ---- O += P V; per kt, nh in groups of 4, term-major (distance 8)
        #pragma unroll
        for (int kt = 0; kt < 4; kt++) {
            #pragma unroll
            for (int gh = 0; gh < 2; gh++) {
                uint32_t vhf[4][4], vlf[4][4];
                #pragma unroll
                for (int j = 0; j < 4; j++) {
                    int r = (gh * 4 + j) * 16 + bro;
                    uint32_t va = (uint32_t)(r * 128 + (((kt * 2 + bgsel) ^ (r & 7)) << 4));
                    ldm4(vhf[j], VHb + va);
                    ldm4(vlf[j], VLb + va);
                }
                float (*oa)[4] = &oacc[gh * 8];
                #pragma unroll
                for (int j = 0; j < 4; j++) {
                    mma16816(oa[2 * j],     phi[kt], vhf[j][0], vhf[j][1]);
                    mma16816(oa[2 * j + 1], phi[kt], vhf[j][2], vhf[j][3]);
                }
                #pragma unroll
                for (int j = 0; j < 4; j++) {
                    mma16816(oa[2 * j],     plo[kt], vhf[j][0], vhf[j][1]);
                    mma16816(oa[2 * j + 1], plo[kt], vhf[j][2], vhf[j][3]);
                }
                #pragma unroll
                for (int j = 0; j < 4; j++) {
                    mma16816(oa[2 * j],     phi[kt], vlf[j][0], vlf[j][1]);
                    mma16816(oa[2 * j + 1], phi[kt], vlf[j][2], vlf[j][3]);
                }
            }
        }
        __syncthreads();  // all warps done reading rbuf before reuse
        rbuf = (rbuf == 2) ? 0 : rbuf + 1;
        wbuf = (wbuf == 2) ? 0 : wbuf + 1;
    }

    // normalize + hi/lo split + write enc directly as bf16 pair arrays
    float inv0 = __fdividef(1.f, l0), inv1 = __fdividef(1.f, l1);
    const int tr0 = t0 + wid * 16 + (lane >> 2);
    #pragma unroll
    for (int nt = 0; nt < 16; nt++) {
        int col = nt * 8 + (lane & 3) * 2;
        size_t o0 = ((size_t)b * Tt + tr0) * Dd + n * Hh + col;
        size_t o1 = ((size_t)b * Tt + tr0 + 8) * Dd + n * Hh + col;
        float x0 = oacc[nt][0] * inv0, y0 = oacc[nt][1] * inv0;
        float x1 = oacc[nt][2] * inv1, y1 = oacc[nt][3] * inv1;
        __nv_bfloat162 h0 = __floats2bfloat162_rn(x0, y0);
        __nv_bfloat162 h1 = __floats2bfloat162_rn(x1, y1);
        __nv_bfloat162 l0v = __floats2bfloat162_rn(x0 - __bfloat162float(h0.x),
                                                   y0 - __bfloat162float(h0.y));
        __nv_bfloat162 l1v = __floats2bfloat162_rn(x1 - __bfloat162float(h1.x),
                                                   y1 - __bfloat162float(h1.y));
        *(__nv_bfloat162*)(g_ehi + o0) = h0;
        *(__nv_bfloat162*)(g_elo + o0) = l0v;
        *(__nv_bfloat162*)(g_ehi + o1) = h1;
        *(__nv_bfloat162*)(g_elo + o1) = l1v;
    }
}

// ---------------------------------------------------------------------------
extern "C" void kernel_launch(void* const* d_in, const int* in_sizes, int n_in,
                              void* d_out, int out_size)
{
    const float* x       = (const float*)d_in[0];
    const float* w_qkv   = (const float*)d_in[1];
    const float* w_out   = (const float*)d_in[2];
    const int*   seg_pos = (const int*)d_in[3];
    float* out = (float*)d_out;

    const int n4 = Bx * Tt * Dd / 4;

    split_x_kernel<<<n4 / 256, 256>>>(x);
    transpose_split_kernel<0><<<dim3(Hh / 32, Dd / 32, 48), dim3(32, 8)>>>(w_qkv, Dd, Hh);
    transpose_split_kernel<1><<<dim3(Dd / 32, Dd / 32, 1), dim3(32, 8)>>>(w_out, Dd, Dd);

    cudaFuncSetAttribute(mma_gemm<0>, cudaFuncAttributeMaxDynamicSharedMemorySize, GEMM_SMEM);
    cudaFuncSetAttribute(mma_gemm<1>, cudaFuncAttributeMaxDynamicSharedMemorySize, GEMM_SMEM);
    cudaFuncSetAttribute(attn_mma_kernel, cudaFuncAttributeMaxDynamicSharedMemorySize, ATTN_SMEM2);

    mma_gemm<0><<<dim3(Bx * Tt / 128, 48), 256, GEMM_SMEM>>>(nullptr);
    rope_split_kernel<<<dim3(Bx * Nn * Tt / 4), 256>>>(seg_pos);
    vsplit_kernel<<<dim3(Tt / 32, Hh / 32, Bx * Nn), dim3(32, 8)>>>();

    attn_mma_kernel<<<dim3(16 * Nn * Bx), 256, ATTN_SMEM2>>>();

    mma_gemm<1><<<dim3(Bx * Tt / 128, Dd / 128), 256, GEMM_SMEM>>>(out);
}

// round 14
// speedup vs baseline: 1.2327x; 1.2098x over previous
#include <cuda_runtime.h>
#include <cuda_bf16.h>
#include <cuda_fp16.h>
#include <math.h>
#include <float.h>
#include <stdint.h>

#define Bx 2
#define Tt 2048
#define Dd 2048
#define Nn 16
#define Hh 128
#define WINDOW 1024
#define SOFT_CAP 50.0f

#define SZQ ((size_t)Bx * Nn * Tt * Hh)

// fp32 scratch
__device__ float g_qkv[3ull * Bx * Nn * Tt * Hh];
// fp16 split scratch (GEMMs): A = hi+lo, B = hi only
__device__ __half g_xhi[(size_t)Bx * Tt * Dd], g_xlo[(size_t)Bx * Tt * Dd];
__device__ __half g_wqh[48ull * Hh * Dd];
__device__ __half g_woh[(size_t)Dd * Dd];
__device__ __half g_ehi[(size_t)Bx * Tt * Dd], g_elo[(size_t)Bx * Tt * Dd];
// bf16 split scratch (attention): q,k as [b][n][t][h]; v transposed [b][n][h][t]
__device__ __nv_bfloat16 g_qh[SZQ], g_ql[SZQ];
__device__ __nv_bfloat16 g_kh[SZQ], g_kl[SZQ];
__device__ __nv_bfloat16 g_vth[SZQ], g_vtl[SZQ];

// ---------------------------------------------------------------------------
// helpers
// ---------------------------------------------------------------------------
__device__ __forceinline__ uint32_t smem_u32(const void* p) {
    uint32_t a;
    asm("{ .reg .u64 t; cvta.to.shared.u64 t, %1; cvt.u32.u64 %0, t; }" : "=r"(a) : "l"(p));
    return a;
}
__device__ __forceinline__ void ldm4(uint32_t* r, uint32_t addr) {
    asm volatile("ldmatrix.sync.aligned.m8n8.x4.shared.b16 {%0,%1,%2,%3}, [%4];"
        : "=r"(r[0]), "=r"(r[1]), "=r"(r[2]), "=r"(r[3]) : "r"(addr));
}
// bf16 MMA (attention)
__device__ __forceinline__ void mma16816(float* c, const uint32_t* a, uint32_t b0, uint32_t b1) {
    asm volatile("mma.sync.aligned.m16n8k16.row.col.f32.bf16.bf16.f32 "
        "{%0,%1,%2,%3}, {%4,%5,%6,%7}, {%8,%9}, {%0,%1,%2,%3};"
        : "+f"(c[0]), "+f"(c[1]), "+f"(c[2]), "+f"(c[3])
        : "r"(a[0]), "r"(a[1]), "r"(a[2]), "r"(a[3]), "r"(b0), "r"(b1));
}
// fp16 MMA (projection GEMMs)
__device__ __forceinline__ void mma16816h(float* c, const uint32_t* a, uint32_t b0, uint32_t b1) {
    asm volatile("mma.sync.aligned.m16n8k16.row.col.f32.f16.f16.f32 "
        "{%0,%1,%2,%3}, {%4,%5,%6,%7}, {%8,%9}, {%0,%1,%2,%3};"
        : "+f"(c[0]), "+f"(c[1]), "+f"(c[2]), "+f"(c[3])
        : "r"(a[0]), "r"(a[1]), "r"(a[2]), "r"(a[3]), "r"(b0), "r"(b1));
}
__device__ __forceinline__ void cp16(uint32_t dst, const void* src) {
    asm volatile("cp.async.cg.shared.global [%0], [%1], 16;" :: "r"(dst), "l"(src));
}
#define CP_COMMIT() asm volatile("cp.async.commit_group;" ::: "memory")

// ---------------------------------------------------------------------------
// fp32 -> fp16 hi/lo split (straight)
// ---------------------------------------------------------------------------
__device__ __forceinline__ void split4h(const float4 v, __half2* H, __half2* L, size_t i2) {
    __half h0 = __float2half(v.x), h1 = __float2half(v.y);
    __half h2 = __float2half(v.z), h3 = __float2half(v.w);
    H[i2]     = __half2(h0, h1);
    H[i2 + 1] = __half2(h2, h3);
    L[i2]     = __half2(__float2half(v.x - __half2float(h0)),
                        __float2half(v.y - __half2float(h1)));
    L[i2 + 1] = __half2(__float2half(v.z - __half2float(h2)),
                        __float2half(v.w - __half2float(h3)));
}

__global__ void split_x_kernel(const float* __restrict__ in) {
    size_t i = (size_t)blockIdx.x * 256 + threadIdx.x;
    float4 v = ((const float4*)in)[i];
    split4h(v, (__half2*)g_xhi, (__half2*)g_xlo, i * 2);
}

// ---------------------------------------------------------------------------
// fp32 [mat][R][C] -> fp16 hi-only [mat][C][R] transpose (weights)
// ---------------------------------------------------------------------------
template<int WHICH>
__global__ void transpose_split_kernel(const float* __restrict__ in, int R, int C) {
    __shared__ float tile[32][33];
    const int mat = blockIdx.z;
    const int c0 = blockIdx.x * 32, r0 = blockIdx.y * 32;
    const float* A = in + (size_t)mat * R * C;
    #pragma unroll
    for (int i = threadIdx.y; i < 32; i += 8)
        tile[i][threadIdx.x] = A[(size_t)(r0 + i) * C + c0 + threadIdx.x];
    __syncthreads();
    __half* H = (WHICH == 0 ? g_wqh : g_woh) + (size_t)mat * R * C;
    #pragma unroll
    for (int i = threadIdx.y; i < 32; i += 8) {
        float v = tile[threadIdx.x][i];
        size_t o = (size_t)(c0 + i) * R + r0 + threadIdx.x;
        H[o] = __float2half(v);
    }
}

// ---------------------------------------------------------------------------
// fp16 2-term mma.sync GEMM: D = A*B_hi with A = Ah + Al.
// K-chunk 32, 3 tiles (Ah, Al, Bh), 3-stage ring, 256 thr, 2 CTAs/SM.
// ---------------------------------------------------------------------------
#define TILE32_B 8192
#define STAGE32_B (3 * TILE32_B)       // 24 KB
#define GEMM_SMEM (3 * STAGE32_B)      // 72 KB

__device__ __forceinline__ uint32_t sw64(int r, int g) {
    return (uint32_t)(r * 64 + ((g ^ ((r >> 1) & 3)) << 4));
}

template<int MODE>
__global__ void __launch_bounds__(256, 2) mma_gemm(float* __restrict__ outg) {
    extern __shared__ char smc[];
    const uint32_t smb = smem_u32(smc);
    const int tid = threadIdx.x;
    const int wid = tid >> 5, lane = tid & 31;
    const int m0 = blockIdx.x * 128;

    const __half *Ahi, *Alo, *Bhi;
    if (MODE == 0) { Ahi = g_xhi; Alo = g_xlo; Bhi = g_wqh; }
    else           { Ahi = g_ehi; Alo = g_elo; Bhi = g_woh; }

    const int srow = tid >> 1, sg0 = (tid & 1) * 2;
    const size_t bbase = (size_t)blockIdx.y * (128 * Dd);
    const __half* gsrc[3];
    gsrc[0] = Ahi + (size_t)(m0 + srow) * Dd + sg0 * 8;
    gsrc[1] = Alo + (size_t)(m0 + srow) * Dd + sg0 * 8;
    gsrc[2] = Bhi + bbase + (size_t)srow * Dd + sg0 * 8;
    uint32_t soff[2];
    soff[0] = sw64(srow, sg0);
    soff[1] = sw64(srow, sg0 + 1);

    const int wm = wid & 3, wn = wid >> 2;
    const int arow = wm * 32 + (lane & 15);
    const int agsel = lane >> 4;
    const int brow = wn * 64 + (lane & 7) + (lane >> 4) * 8;
    const int bgsel = (lane >> 3) & 1;

    float acc[2][8][4];
    #pragma unroll
    for (int i = 0; i < 2; i++)
        #pragma unroll
        for (int j = 0; j < 8; j++)
            #pragma unroll
            for (int q = 0; q < 4; q++) acc[i][j][q] = 0.f;

    const int KT = Dd / 32;  // 64 chunks

    #pragma unroll
    for (int pc = 0; pc < 2; pc++) {
        uint32_t buf = smb + pc * STAGE32_B;
        #pragma unroll
        for (int t = 0; t < 3; t++) {
            cp16(buf + t * TILE32_B + soff[0], gsrc[t] + pc * 32);
            cp16(buf + t * TILE32_B + soff[1], gsrc[t] + pc * 32 + 8);
        }
        CP_COMMIT();
    }

    int rbuf = 0, wbuf = 2;
    for (int kc = 0; kc < KT; kc++) {
        if (kc + 1 < KT) asm volatile("cp.async.wait_group 1;" ::: "memory");
        else             asm volatile("cp.async.wait_group 0;" ::: "memory");
        __syncthreads();

        if (kc + 2 < KT) {
            uint32_t buf = smb + wbuf * STAGE32_B;
            #pragma unroll
            for (int t = 0; t < 3; t++) {
                cp16(buf + t * TILE32_B + soff[0], gsrc[t] + (kc + 2) * 32);
                cp16(buf + t * TILE32_B + soff[1], gsrc[t] + (kc + 2) * 32 + 8);
            }
            CP_COMMIT();
        }

        const uint32_t tb = smb + rbuf * STAGE32_B;
        #pragma unroll
        for (int ks = 0; ks < 2; ks++) {
            uint32_t ah[2][4], al[2][4];
            #pragma unroll
            for (int mm = 0; mm < 2; mm++) {
                uint32_t ad = sw64(arow + mm * 16, ks * 2 + agsel);
                ldm4(ah[mm], tb + ad);
                ldm4(al[mm], tb + TILE32_B + ad);
            }
            #pragma unroll
            for (int j = 0; j < 4; j++) {
                uint32_t bd = sw64(brow + j * 16, ks * 2 + bgsel);
                uint32_t bh[4];
                ldm4(bh, tb + 2 * TILE32_B + bd);
                mma16816h(acc[0][2 * j],     ah[0], bh[0], bh[1]);
                mma16816h(acc[0][2 * j + 1], ah[0], bh[2], bh[3]);
                mma16816h(acc[1][2 * j],     ah[1], bh[0], bh[1]);
                mma16816h(acc[1][2 * j + 1], ah[1], bh[2], bh[3]);
                mma16816h(acc[0][2 * j],     al[0], bh[0], bh[1]);
                mma16816h(acc[0][2 * j + 1], al[0], bh[2], bh[3]);
                mma16816h(acc[1][2 * j],     al[1], bh[0], bh[1]);
                mma16816h(acc[1][2 * j + 1], al[1], bh[2], bh[3]);
            }
        }
        rbuf = (rbuf == 2) ? 0 : rbuf + 1;
        wbuf = (wbuf == 2) ? 0 : wbuf + 1;
    }

    #pragma unroll
    for (int mm = 0; mm < 2; mm++) {
        #pragma unroll
        for (int half = 0; half < 2; half++) {
            const int r = wm * 32 + mm * 16 + (lane >> 2) + half * 8;
            const int m = m0 + r;
            float* rowp;
            if (MODE == 0) {
                const int s = blockIdx.y >> 4, n = blockIdx.y & 15;
                const int b = m >> 11, t = m & (Tt - 1);
                rowp = g_qkv + ((size_t)s * Bx * Nn + (size_t)(b * Nn + n)) * Tt * Hh
                             + (size_t)t * Hh;
            } else {
                rowp = outg + (size_t)m * Dd + blockIdx.y * 128;
            }
            #pragma unroll
            for (int j = 0; j < 8; j++) {
                const int c = wn * 64 + j * 8 + (lane & 3) * 2;
                float2 v;
                v.x = acc[mm][j][half * 2];
                v.y = acc[mm][j][half * 2 + 1];
                *(float2*)(rowp + c) = v;
            }
        }
    }
}

// ---------------------------------------------------------------------------
// RoPE + bf16 split of q (scaled) and k
// ---------------------------------------------------------------------------
__global__ void rope_split_kernel(const int* __restrict__ segment_pos)
{
    const int row = blockIdx.x * 4 + (threadIdx.x >> 6);
    const int h = threadIdx.x & 63;
    const int b = row / (Nn * Tt);
    const int nt = row - b * (Nn * Tt);
    const int n = nt >> 11;
    const int t = nt & (Tt - 1);
    const int pos = segment_pos[b * Tt + t];

    const double ts = pow(10000.0, (double)h / 64.0);
    const float ang = (float)((double)pos / ts);
    float sn, cs;
    sincosf(ang, &sn, &cs);

    const size_t base = ((size_t)(b * Nn + n) * Tt + t) * Hh;
    const float* q = g_qkv + base;
    const float* k = g_qkv + SZQ + base;
    const float qs = 0.08838834764831845f;

    float q1 = q[h], q2 = q[h + 64];
    float qa = (q1 * cs - q2 * sn) * qs;
    float qb = (q2 * cs + q1 * sn) * qs;
    float k1 = k[h], k2 = k[h + 64];
    float ka = k1 * cs - k2 * sn;
    float kb = k2 * cs + k1 * sn;

    __nv_bfloat16 hqa = __float2bfloat16(qa), hqb = __float2bfloat16(qb);
    __nv_bfloat16 hka = __float2bfloat16(ka), hkb = __float2bfloat16(kb);
    g_qh[base + h] = hqa;       g_qh[base + h + 64] = hqb;
    g_ql[base + h] = __float2bfloat16(qa - __bfloat162float(hqa));
    g_ql[base + h + 64] = __float2bfloat16(qb - __bfloat162float(hqb));
    g_kh[base + h] = hka;       g_kh[base + h + 64] = hkb;
    g_kl[base + h] = __float2bfloat16(ka - __bfloat162float(hka));
    g_kl[base + h + 64] = __float2bfloat16(kb - __bfloat162float(hkb));
}

// ---------------------------------------------------------------------------
// V: fp32 [b][n][t][h] -> bf16 hi/lo transposed [b][n][h][t]
// ---------------------------------------------------------------------------
__global__ void vsplit_kernel()
{
    __shared__ float tile[32][33];
    const int bnz = blockIdx.z;
    const int t0 = blockIdx.x * 32, h0 = blockIdx.y * 32;
    const float* v = g_qkv + 2 * SZQ + (size_t)bnz * Tt * Hh;
    #pragma unroll
    for (int i = threadIdx.y; i < 32; i += 8)
        tile[i][threadIdx.x] = v[(size_t)(t0 + i) * Hh + h0 + threadIdx.x];
    __syncthreads();
    const size_t dbase = (size_t)bnz * Hh * Tt;
    #pragma unroll
    for (int i = threadIdx.y; i < 32; i += 8) {
        float val = tile[threadIdx.x][i];
        __nv_bfloat16 hi = __float2bfloat16(val);
        size_t o = dbase + (size_t)(h0 + i) * Tt + t0 + threadIdx.x;
        g_vth[o] = hi;
        g_vtl[o] = __float2bfloat16(val - __bfloat162float(hi));
    }
}

// ---------------------------------------------------------------------------
// Flash attention (R13 config, unchanged numerics): 128q x 64key chunks,
// Q in registers, 3-stage ring, fixed-base softmax, term-major MMA order.
// Epilogue writes fp16 hi/lo enc for the fp16 out-projection.
// ---------------------------------------------------------------------------
#define AT_STAGE 65536
#define ATTN_SMEM2 (3 * 65536)   // 196608

__global__ void __launch_bounds__(256, 1) attn_mma_kernel()
{
    extern __shared__ char smc[];
    const uint32_t smb = smem_u32(smc);
    const int tid = threadIdx.x;
    const int wid = tid >> 5, lane = tid & 31;
    const int qt = 15 - (blockIdx.x >> 5);
    const int sub = blockIdx.x & 31;
    const int n = sub >> 1, b = sub & 1;
    const int t0 = qt * 128;
    const size_t bn = (size_t)(b * Nn + n) * Tt * Hh;

    const __nv_bfloat16* qhp = g_qh + bn;
    const __nv_bfloat16* qlp = g_ql + bn;
    const __nv_bfloat16* khp = g_kh + bn;
    const __nv_bfloat16* klp = g_kl + bn;
    const __nv_bfloat16* vhp = g_vth + bn;
    const __nv_bfloat16* vlp = g_vtl + bn;

    const int c_lo = (t0 >= WINDOW) ? ((t0 - WINDOW + 1) >> 6) : 0;
    const int c_hi = (t0 + 127) >> 6;

    const int arow = wid * 16 + (lane & 15);
    const int agsel = lane >> 4;
    const int bro = (lane & 7) + ((lane >> 4) << 3);
    const int bgsel = (lane >> 3) & 1;
    const int qr0 = t0 + wid * 16 + (lane >> 2);

    // ---- load Q into registers via one-time smem staging in buffer 0
    uint32_t qhf[8][4], qlf[8][4];
    {
        const int r = tid >> 1;
        const __nv_bfloat16* sh = qhp + (size_t)(t0 + r) * Hh;
        const __nv_bfloat16* sl = qlp + (size_t)(t0 + r) * Hh;
        #pragma unroll
        for (int i = 0; i < 8; i++) {
            int g = (tid & 1) * 8 + i;
            uint32_t off = (uint32_t)(r * 256 + ((g ^ (r & 7)) << 4));
            cp16(smb + off, sh + g * 8);
            cp16(smb + 32768 + off, sl + g * 8);
        }
        CP_COMMIT();
        asm volatile("cp.async.wait_group 0;" ::: "memory");
        __syncthreads();
        #pragma unroll
        for (int ks = 0; ks < 8; ks++) {
            uint32_t qa = (uint32_t)(arow * 256 + (((ks * 2 + agsel) ^ (arow & 7)) << 4));
            ldm4(qhf[ks], smb + qa);
            ldm4(qlf[ks], smb + 32768 + qa);
        }
        __syncthreads();
    }

    // ---- prologue: stage chunks c_lo, c_lo+1 into buffers 0, 1
    #pragma unroll 1
    for (int pc = 0; pc < 2; pc++) {
        const int c = c_lo + pc;
        const int k0 = c * 64;
        uint32_t sb = smb + pc * AT_STAGE;
        {
            const int r = tid >> 2;
            const __nv_bfloat16* sh = khp + (size_t)(k0 + r) * Hh;
            const __nv_bfloat16* sl = klp + (size_t)(k0 + r) * Hh;
            #pragma unroll
            for (int i = 0; i < 4; i++) {
                int g = (tid & 3) * 4 + i;
                uint32_t off = (uint32_t)(r * 256 + ((g ^ (r & 7)) << 4));
                cp16(sb + off, sh + g * 8);
                cp16(sb + 16384 + off, sl + g * 8);
            }
        }
        {
            const int r = tid >> 1;
            const __nv_bfloat16* sh = vhp + (size_t)r * Tt + k0;
            const __nv_bfloat16* sl = vlp + (size_t)r * Tt + k0;
            #pragma unroll
            for (int i = 0; i < 4; i++) {
                int g = (tid & 1) * 4 + i;
                uint32_t off = (uint32_t)(r * 128 + ((g ^ (r & 7)) << 4));
                cp16(sb + 32768 + off, sh + g * 8);
                cp16(sb + 49152 + off, sl + g * 8);
            }
        }
        CP_COMMIT();
    }

    float oacc[16][4];
    #pragma unroll
    for (int i = 0; i < 16; i++)
        #pragma unroll
        for (int q = 0; q < 4; q++) oacc[i][q] = 0.f;
    float l0 = 0.f, l1 = 0.f;

    int rbuf = 0, wbuf = 2;
    for (int c = c_lo; c <= c_hi; c++) {
        if (c < c_hi) asm volatile("cp.async.wait_group 1;" ::: "memory");
        else          asm volatile("cp.async.wait_group 0;" ::: "memory");
        __syncthreads();

        if (c + 2 <= c_hi) {
            const int k2 = (c + 2) * 64;
            uint32_t sb = smb + wbuf * AT_STAGE;
            {
                const int r = tid >> 2;
                const __nv_bfloat16* sh = khp + (size_t)(k2 + r) * Hh;
                const __nv_bfloat16* sl = klp + (size_t)(k2 + r) * Hh;
                #pragma unroll
                for (int i = 0; i < 4; i++) {
                    int g = (tid & 3) * 4 + i;
                    uint32_t off = (uint32_t)(r * 256 + ((g ^ (r & 7)) << 4));
                    cp16(sb + off, sh + g * 8);
                    cp16(sb + 16384 + off, sl + g * 8);
                }
            }
            {
                const int r = tid >> 1;
                const __nv_bfloat16* sh = vhp + (size_t)r * Tt + k2;
                const __nv_bfloat16* sl = vlp + (size_t)r * Tt + k2;
                #pragma unroll
                for (int i = 0; i < 4; i++) {
                    int g = (tid & 1) * 4 + i;
                    uint32_t off = (uint32_t)(r * 128 + ((g ^ (r & 7)) << 4));
                    cp16(sb + 32768 + off, sh + g * 8);
                    cp16(sb + 49152 + off, sl + g * 8);
                }
            }
            CP_COMMIT();
        }

        const int k0 = c * 64;
        const bool full = (k0 <= t0 - 64) && (k0 >= t0 - (WINDOW - 128));
        const uint32_t KHb = smb + rbuf * AT_STAGE;
        const uint32_t KLb = KHb + 16384, VHb = KHb + 32768, VLb = KHb + 49152;

        float sacc[8][4];
        #pragma unroll
        for (int i = 0; i < 8; i++)
            #pragma unroll
            for (int q = 0; q < 4; q++) sacc[i][q] = 0.f;

        #pragma unroll
        for (int ks = 0; ks < 8; ks++) {
            uint32_t khf[4][4], klf[4][4];
            #pragma unroll
            for (int nk = 0; nk < 4; nk++) {
                int r = nk * 16 + bro;
                uint32_t ka = (uint32_t)(r * 256 + (((ks * 2 + bgsel) ^ (r & 7)) << 4));
                ldm4(khf[nk], KHb + ka);
                ldm4(klf[nk], KLb + ka);
            }
            #pragma unroll
            for (int nk = 0; nk < 4; nk++) {
                mma16816(sacc[2 * nk],     qhf[ks], khf[nk][0], khf[nk][1]);
                mma16816(sacc[2 * nk + 1], qhf[ks], khf[nk][2], khf[nk][3]);
            }
            #pragma unroll
            for (int nk = 0; nk < 4; nk++) {
                mma16816(sacc[2 * nk],     qlf[ks], khf[nk][0], khf[nk][1]);
                mma16816(sacc[2 * nk + 1], qlf[ks], khf[nk][2], khf[nk][3]);
            }
            #pragma unroll
            for (int nk = 0; nk < 4; nk++) {
                mma16816(sacc[2 * nk],     qhf[ks], klf[nk][0], klf[nk][1]);
                mma16816(sacc[2 * nk + 1], qhf[ks], klf[nk][2], klf[nk][3]);
            }
        }

        float s0 = 0.f, s1 = 0.f;
        uint32_t phi[4][4], plo[4][4];
        #pragma unroll
        for (int nt = 0; nt < 8; nt++)
            #pragma unroll
            for (int q = 0; q < 4; q++) {
                float s = sacc[nt][q];
                float e = __expf(s * (2.0f / SOFT_CAP));
                float r = __fdividef(2.0f, e + 1.0f);
                float p = __expf(SOFT_CAP - SOFT_CAP * r);
                if (!full) {
                    int qr = qr0 + ((q & 2) ? 8 : 0);
                    int kc = k0 + nt * 8 + (lane & 3) * 2 + (q & 1);
                    if (kc > qr || qr - kc >= WINDOW) p = 0.f;
                }
                sacc[nt][q] = p;
                if (q & 2) s1 += p; else s0 += p;
            }
        #pragma unroll
        for (int kt = 0; kt < 4; kt++) {
            #pragma unroll
            for (int part = 0; part < 4; part++) {
                int nt = 2 * kt + (part >> 1);
                float x = sacc[nt][(part & 1) * 2];
                float y = sacc[nt][(part & 1) * 2 + 1];
                __nv_bfloat162 h2 = __floats2bfloat162_rn(x, y);
                float lx = x - __bfloat162float(h2.x);
                float ly = y - __bfloat162float(h2.y);
                __nv_bfloat162 l2 = __floats2bfloat162_rn(lx, ly);
                phi[kt][part] = *(uint32_t*)&h2;
                plo[kt][part] = *(uint32_t*)&l2;
            }
        }
        s0 += __shfl_xor_sync(0xffffffffu, s0, 1);
        s0 += __shfl_xor_sync(0xffffffffu, s0, 2);
        s1 += __shfl_xor_sync(0xffffffffu, s1, 1);
        s1 += __shfl_xor_sync(0xffffffffu, s1, 2);
        l0 += s0;
        l1 += s1;

        #pragma unroll
        for (int kt = 0; kt < 4; kt++) {
            #pragma unroll
            for (int gh = 0; gh < 2; gh++) {
                uint32_t vhf[4][4], vlf[4][4];
                #pragma unroll
                for (int j = 0; j < 4; j++) {
                    int r = (gh * 4 + j) * 16 + bro;
                    uint32_t va = (uint32_t)(r * 128 + (((kt * 2 + bgsel) ^ (r & 7)) << 4));
                    ldm4(vhf[j], VHb + va);
                    ldm4(vlf[j], VLb + va);
                }
                float (*oa)[4] = &oacc[gh * 8];
                #pragma unroll
                for (int j = 0; j < 4; j++) {
                    mma16816(oa[2 * j],     phi[kt], vhf[j][0], vhf[j][1]);
                    mma16816(oa[2 * j + 1], phi[kt], vhf[j][2], vhf[j][3]);
                }
                #pragma unroll
                for (int j = 0; j < 4; j++) {
                    mma16816(oa[2 * j],     plo[kt], vhf[j][0], vhf[j][1]);
                    mma16816(oa[2 * j + 1], plo[kt], vhf[j][2], vhf[j][3]);
                }
                #pragma unroll
                for (int j = 0; j < 4; j++) {
                    mma16816(oa[2 * j],     phi[kt], vlf[j][0], vlf[j][1]);
                    mma16816(oa[2 * j + 1], phi[kt], vlf[j][2], vlf[j][3]);
                }
            }
        }
        __syncthreads();
        rbuf = (rbuf == 2) ? 0 : rbuf + 1;
        wbuf = (wbuf == 2) ? 0 : wbuf + 1;
    }

    // normalize + fp16 hi/lo split + write enc
    float inv0 = __fdividef(1.f, l0), inv1 = __fdividef(1.f, l1);
    const int tr0 = t0 + wid * 16 + (lane >> 2);
    #pragma unroll
    for (int nt = 0; nt < 16; nt++) {
        int col = nt * 8 + (lane & 3) * 2;
        size_t o0 = ((size_t)b * Tt + tr0) * Dd + n * Hh + col;
        size_t o1 = ((size_t)b * Tt + tr0 + 8) * Dd + n * Hh + col;
        float x0 = oacc[nt][0] * inv0, y0 = oacc[nt][1] * inv0;
        float x1 = oacc[nt][2] * inv1, y1 = oacc[nt][3] * inv1;
        __half hx0 = __float2half(x0), hy0 = __float2half(y0);
        __half hx1 = __float2half(x1), hy1 = __float2half(y1);
        *(__half2*)(g_ehi + o0) = __half2(hx0, hy0);
        *(__half2*)(g_elo + o0) = __half2(__float2half(x0 - __half2float(hx0)),
                                          __float2half(y0 - __half2float(hy0)));
        *(__half2*)(g_ehi + o1) = __half2(hx1, hy1);
        *(__half2*)(g_elo + o1) = __half2(__float2half(x1 - __half2float(hx1)),
                                          __float2half(y1 - __half2float(hy1)));
    }
}

// ---------------------------------------------------------------------------
extern "C" void kernel_launch(void* const* d_in, const int* in_sizes, int n_in,
                              void* d_out, int out_size)
{
    const float* x       = (const float*)d_in[0];
    const float* w_qkv   = (const float*)d_in[1];
    const float* w_out   = (const float*)d_in[2];
    const int*   seg_pos = (const int*)d_in[3];
    float* out = (float*)d_out;

    const int n4 = Bx * Tt * Dd / 4;

    split_x_kernel<<<n4 / 256, 256>>>(x);
    transpose_split_kernel<0><<<dim3(Hh / 32, Dd / 32, 48), dim3(32, 8)>>>(w_qkv, Dd, Hh);
    transpose_split_kernel<1><<<dim3(Dd / 32, Dd / 32, 1), dim3(32, 8)>>>(w_out, Dd, Dd);

    cudaFuncSetAttribute(mma_gemm<0>, cudaFuncAttributeMaxDynamicSharedMemorySize, GEMM_SMEM);
    cudaFuncSetAttribute(mma_gemm<1>, cudaFuncAttributeMaxDynamicSharedMemorySize, GEMM_SMEM);
    cudaFuncSetAttribute(attn_mma_kernel, cudaFuncAttributeMaxDynamicSharedMemorySize, ATTN_SMEM2);

    mma_gemm<0><<<dim3(Bx * Tt / 128, 48), 256, GEMM_SMEM>>>(nullptr);
    rope_split_kernel<<<dim3(Bx * Nn * Tt / 4), 256>>>(seg_pos);
    vsplit_kernel<<<dim3(Tt / 32, Hh / 32, Bx * Nn), dim3(32, 8)>>>();

    attn_mma_kernel<<<dim3(16 * Nn * Bx), 256, ATTN_SMEM2>>>();

    mma_gemm<1><<<dim3(Bx * Tt / 128, Dd / 128), 256, GEMM_SMEM>>>(out);
}

// round 15
// speedup vs baseline: 2.0197x; 1.6385x over previous
#include <cuda_runtime.h>
#include <cuda_bf16.h>
#include <cuda_fp16.h>
#include <math.h>
#include <float.h>
#include <stdint.h>

#define Bx 2
#define Tt 2048
#define Dd 2048
#define Nn 16
#define Hh 128
#define WINDOW 1024
#define SOFT_CAP 50.0f

#define SZQ ((size_t)Bx * Nn * Tt * Hh)

// fp32 scratch
__device__ float g_qkv[3ull * Bx * Nn * Tt * Hh];
// fp16 split scratch (GEMMs): A = hi+lo, B = hi only
__device__ __half g_xhi[(size_t)Bx * Tt * Dd], g_xlo[(size_t)Bx * Tt * Dd];
__device__ __half g_wqh[48ull * Hh * Dd];
__device__ __half g_woh[(size_t)Dd * Dd];
__device__ __half g_ehi[(size_t)Bx * Tt * Dd], g_elo[(size_t)Bx * Tt * Dd];
// bf16 split scratch (attention)
__device__ __nv_bfloat16 g_qh[SZQ], g_ql[SZQ];
__device__ __nv_bfloat16 g_kh[SZQ], g_kl[SZQ];
__device__ __nv_bfloat16 g_vth[SZQ], g_vtl[SZQ];
// RoPE inverse timescales
__device__ double g_invts[64];

// ---------------------------------------------------------------------------
// helpers
// ---------------------------------------------------------------------------
__device__ __forceinline__ uint32_t smem_u32(const void* p) {
    uint32_t a;
    asm("{ .reg .u64 t; cvta.to.shared.u64 t, %1; cvt.u32.u64 %0, t; }" : "=r"(a) : "l"(p));
    return a;
}
__device__ __forceinline__ void ldm4(uint32_t* r, uint32_t addr) {
    asm volatile("ldmatrix.sync.aligned.m8n8.x4.shared.b16 {%0,%1,%2,%3}, [%4];"
        : "=r"(r[0]), "=r"(r[1]), "=r"(r[2]), "=r"(r[3]) : "r"(addr));
}
__device__ __forceinline__ void mma16816(float* c, const uint32_t* a, uint32_t b0, uint32_t b1) {
    asm volatile("mma.sync.aligned.m16n8k16.row.col.f32.bf16.bf16.f32 "
        "{%0,%1,%2,%3}, {%4,%5,%6,%7}, {%8,%9}, {%0,%1,%2,%3};"
        : "+f"(c[0]), "+f"(c[1]), "+f"(c[2]), "+f"(c[3])
        : "r"(a[0]), "r"(a[1]), "r"(a[2]), "r"(a[3]), "r"(b0), "r"(b1));
}
__device__ __forceinline__ void mma16816h(float* c, const uint32_t* a, uint32_t b0, uint32_t b1) {
    asm volatile("mma.sync.aligned.m16n8k16.row.col.f32.f16.f16.f32 "
        "{%0,%1,%2,%3}, {%4,%5,%6,%7}, {%8,%9}, {%0,%1,%2,%3};"
        : "+f"(c[0]), "+f"(c[1]), "+f"(c[2]), "+f"(c[3])
        : "r"(a[0]), "r"(a[1]), "r"(a[2]), "r"(a[3]), "r"(b0), "r"(b1));
}
__device__ __forceinline__ void cp16(uint32_t dst, const void* src) {
    asm volatile("cp.async.cg.shared.global [%0], [%1], 16;" :: "r"(dst), "l"(src));
}
#define CP_COMMIT() asm volatile("cp.async.commit_group;" ::: "memory")

// ---------------------------------------------------------------------------
// prep A: split_x (fp32->fp16 hi/lo) + w_qkv transpose (fp16 hi) + ts table
// ---------------------------------------------------------------------------
__device__ __forceinline__ void split4h(const float4 v, __half2* H, __half2* L, size_t i2) {
    __half h0 = __float2half(v.x), h1 = __float2half(v.y);
    __half h2 = __float2half(v.z), h3 = __float2half(v.w);
    H[i2]     = __half2(h0, h1);
    H[i2 + 1] = __half2(h2, h3);
    L[i2]     = __half2(__float2half(v.x - __half2float(h0)),
                        __float2half(v.y - __half2float(h1)));
    L[i2 + 1] = __half2(__float2half(v.z - __half2float(h2)),
                        __float2half(v.w - __half2float(h3)));
}

#define PREPA_SPLITX 8192   // blocks for split_x (2M float4 / 256)
__global__ void prepA_kernel(const float* __restrict__ x,
                             const float* __restrict__ w_qkv)
{
    if (blockIdx.x < PREPA_SPLITX) {
        size_t i = (size_t)blockIdx.x * 256 + threadIdx.x;
        float4 v = ((const float4*)x)[i];
        split4h(v, (__half2*)g_xhi, (__half2*)g_xlo, i * 2);
        if (blockIdx.x == 0 && threadIdx.x < 64) {
            // inv_ts[h] = 10000^(-h/64)  (exp2-based, <=1ulp vs pow)
            g_invts[threadIdx.x] =
                exp2(-(double)threadIdx.x * (13.287712379549449 / 64.0));
        }
        return;
    }
    // transpose w_qkv: [mat][R=2048][C=128] -> hi fp16 [mat][C][R]
    __shared__ float tile[32][33];
    const int bid = blockIdx.x - PREPA_SPLITX;     // 0 .. 4*64*48-1
    const int cx = bid & 3;                        // C/32 = 4
    const int ry = (bid >> 2) & 63;                // R/32 = 64
    const int mat = bid >> 8;                      // 48 mats
    const int tx = threadIdx.x & 31, ty = threadIdx.x >> 5;  // 32 x 8
    const int c0 = cx * 32, r0 = ry * 32;
    const float* A = w_qkv + (size_t)mat * Dd * Hh;
    #pragma unroll
    for (int i = ty; i < 32; i += 8)
        tile[i][tx] = A[(size_t)(r0 + i) * Hh + c0 + tx];
    __syncthreads();
    __half* H = g_wqh + (size_t)mat * Dd * Hh;
    #pragma unroll
    for (int i = ty; i < 32; i += 8)
        H[(size_t)(c0 + i) * Dd + r0 + tx] = __float2half(tile[tx][i]);
}

// ---------------------------------------------------------------------------
// w_out transpose (runs after attn; keeps attn at launch #4)
// ---------------------------------------------------------------------------
__global__ void transpose_wout_kernel(const float* __restrict__ in)
{
    __shared__ float tile[32][33];
    const int c0 = blockIdx.x * 32, r0 = blockIdx.y * 32;
    const int tx = threadIdx.x & 31, ty = threadIdx.x >> 5;
    #pragma unroll
    for (int i = ty; i < 32; i += 8)
        tile[i][tx] = in[(size_t)(r0 + i) * Dd + c0 + tx];
    __syncthreads();
    #pragma unroll
    for (int i = ty; i < 32; i += 8)
        g_woh[(size_t)(c0 + i) * Dd + r0 + tx] = __float2half(tile[tx][i]);
}

// ---------------------------------------------------------------------------
// prep B: rope+split (blocks [0, 16384)) + vsplit (blocks [16384, 24576))
// ---------------------------------------------------------------------------
#define PREPB_ROPE 16384
__global__ void prepB_kernel(const int* __restrict__ segment_pos)
{
    if (blockIdx.x < PREPB_ROPE) {
        const int row = blockIdx.x * 4 + ((int)threadIdx.x >> 6);
        const int h = threadIdx.x & 63;
        const int b = row / (Nn * Tt);
        const int nt = row - b * (Nn * Tt);
        const int n = nt >> 11;
        const int t = nt & (Tt - 1);
        const int pos = segment_pos[b * Tt + t];

        const float ang = (float)((double)pos * g_invts[h]);
        float sn, cs;
        sincosf(ang, &sn, &cs);

        const size_t base = ((size_t)(b * Nn + n) * Tt + t) * Hh;
        const float* q = g_qkv + base;
        const float* k = g_qkv + SZQ + base;
        const float qs = 0.08838834764831845f;

        float q1 = q[h], q2 = q[h + 64];
        float qa = (q1 * cs - q2 * sn) * qs;
        float qb = (q2 * cs + q1 * sn) * qs;
        float k1 = k[h], k2 = k[h + 64];
        float ka = k1 * cs - k2 * sn;
        float kb = k2 * cs + k1 * sn;

        __nv_bfloat16 hqa = __float2bfloat16(qa), hqb = __float2bfloat16(qb);
        __nv_bfloat16 hka = __float2bfloat16(ka), hkb = __float2bfloat16(kb);
        g_qh[base + h] = hqa;       g_qh[base + h + 64] = hqb;
        g_ql[base + h] = __float2bfloat16(qa - __bfloat162float(hqa));
        g_ql[base + h + 64] = __float2bfloat16(qb - __bfloat162float(hqb));
        g_kh[base + h] = hka;       g_kh[base + h + 64] = hkb;
        g_kl[base + h] = __float2bfloat16(ka - __bfloat162float(hka));
        g_kl[base + h + 64] = __float2bfloat16(kb - __bfloat162float(hkb));
        return;
    }
    // vsplit: fp32 [bn][t][h] -> bf16 hi/lo [bn][h][t]
    __shared__ float tile[32][33];
    const int bid = blockIdx.x - PREPB_ROPE;       // 0 .. 64*4*32-1
    const int tx = threadIdx.x & 31, ty = threadIdx.x >> 5;
    const int xt = bid & 63;                       // Tt/32 = 64
    const int yh = (bid >> 6) & 3;                 // Hh/32 = 4
    const int bnz = bid >> 8;                      // 32
    const int t0 = xt * 32, h0 = yh * 32;
    const float* v = g_qkv + 2 * SZQ + (size_t)bnz * Tt * Hh;
    #pragma unroll
    for (int i = ty; i < 32; i += 8)
        tile[i][tx] = v[(size_t)(t0 + i) * Hh + h0 + tx];
    __syncthreads();
    const size_t dbase = (size_t)bnz * Hh * Tt;
    #pragma unroll
    for (int i = ty; i < 32; i += 8) {
        float val = tile[tx][i];
        __nv_bfloat16 hi = __float2bfloat16(val);
        size_t o = dbase + (size_t)(h0 + i) * Tt + t0 + tx;
        g_vth[o] = hi;
        g_vtl[o] = __float2bfloat16(val - __bfloat162float(hi));
    }
}

// ---------------------------------------------------------------------------
// fp16 2-term mma.sync GEMM (R14): K-chunk 32, 3 tiles, 3-stage, 2 CTAs/SM
// ---------------------------------------------------------------------------
#define TILE32_B 8192
#define STAGE32_B (3 * TILE32_B)       // 24 KB
#define GEMM_SMEM (3 * STAGE32_B)      // 72 KB

__device__ __forceinline__ uint32_t sw64(int r, int g) {
    return (uint32_t)(r * 64 + ((g ^ ((r >> 1) & 3)) << 4));
}

template<int MODE>
__global__ void __launch_bounds__(256, 2) mma_gemm(float* __restrict__ outg) {
    extern __shared__ char smc[];
    const uint32_t smb = smem_u32(smc);
    const int tid = threadIdx.x;
    const int wid = tid >> 5, lane = tid & 31;
    const int m0 = blockIdx.x * 128;

    const __half *Ahi, *Alo, *Bhi;
    if (MODE == 0) { Ahi = g_xhi; Alo = g_xlo; Bhi = g_wqh; }
    else           { Ahi = g_ehi; Alo = g_elo; Bhi = g_woh; }

    const int srow = tid >> 1, sg0 = (tid & 1) * 2;
    const size_t bbase = (size_t)blockIdx.y * (128 * Dd);
    const __half* gsrc[3];
    gsrc[0] = Ahi + (size_t)(m0 + srow) * Dd + sg0 * 8;
    gsrc[1] = Alo + (size_t)(m0 + srow) * Dd + sg0 * 8;
    gsrc[2] = Bhi + bbase + (size_t)srow * Dd + sg0 * 8;
    uint32_t soff[2];
    soff[0] = sw64(srow, sg0);
    soff[1] = sw64(srow, sg0 + 1);

    const int wm = wid & 3, wn = wid >> 2;
    const int arow = wm * 32 + (lane & 15);
    const int agsel = lane >> 4;
    const int brow = wn * 64 + (lane & 7) + (lane >> 4) * 8;
    const int bgsel = (lane >> 3) & 1;

    float acc[2][8][4];
    #pragma unroll
    for (int i = 0; i < 2; i++)
        #pragma unroll
        for (int j = 0; j < 8; j++)
            #pragma unroll
            for (int q = 0; q < 4; q++) acc[i][j][q] = 0.f;

    const int KT = Dd / 32;

    #pragma unroll
    for (int pc = 0; pc < 2; pc++) {
        uint32_t buf = smb + pc * STAGE32_B;
        #pragma unroll
        for (int t = 0; t < 3; t++) {
            cp16(buf + t * TILE32_B + soff[0], gsrc[t] + pc * 32);
            cp16(buf + t * TILE32_B + soff[1], gsrc[t] + pc * 32 + 8);
        }
        CP_COMMIT();
    }

    int rbuf = 0, wbuf = 2;
    for (int kc = 0; kc < KT; kc++) {
        if (kc + 1 < KT) asm volatile("cp.async.wait_group 1;" ::: "memory");
        else             asm volatile("cp.async.wait_group 0;" ::: "memory");
        __syncthreads();

        if (kc + 2 < KT) {
            uint32_t buf = smb + wbuf * STAGE32_B;
            #pragma unroll
            for (int t = 0; t < 3; t++) {
                cp16(buf + t * TILE32_B + soff[0], gsrc[t] + (kc + 2) * 32);
                cp16(buf + t * TILE32_B + soff[1], gsrc[t] + (kc + 2) * 32 + 8);
            }
            CP_COMMIT();
        }

        const uint32_t tb = smb + rbuf * STAGE32_B;
        #pragma unroll
        for (int ks = 0; ks < 2; ks++) {
            uint32_t ah[2][4], al[2][4];
            #pragma unroll
            for (int mm = 0; mm < 2; mm++) {
                uint32_t ad = sw64(arow + mm * 16, ks * 2 + agsel);
                ldm4(ah[mm], tb + ad);
                ldm4(al[mm], tb + TILE32_B + ad);
            }
            #pragma unroll
            for (int j = 0; j < 4; j++) {
                uint32_t bd = sw64(brow + j * 16, ks * 2 + bgsel);
                uint32_t bh[4];
                ldm4(bh, tb + 2 * TILE32_B + bd);
                mma16816h(acc[0][2 * j],     ah[0], bh[0], bh[1]);
                mma16816h(acc[0][2 * j + 1], ah[0], bh[2], bh[3]);
                mma16816h(acc[1][2 * j],     ah[1], bh[0], bh[1]);
                mma16816h(acc[1][2 * j + 1], ah[1], bh[2], bh[3]);
                mma16816h(acc[0][2 * j],     al[0], bh[0], bh[1]);
                mma16816h(acc[0][2 * j + 1], al[0], bh[2], bh[3]);
                mma16816h(acc[1][2 * j],     al[1], bh[0], bh[1]);
                mma16816h(acc[1][2 * j + 1], al[1], bh[2], bh[3]);
            }
        }
        rbuf = (rbuf == 2) ? 0 : rbuf + 1;
        wbuf = (wbuf == 2) ? 0 : wbuf + 1;
    }

    #pragma unroll
    for (int mm = 0; mm < 2; mm++) {
        #pragma unroll
        for (int half = 0; half < 2; half++) {
            const int r = wm * 32 + mm * 16 + (lane >> 2) + half * 8;
            const int m = m0 + r;
            float* rowp;
            if (MODE == 0) {
                const int s = blockIdx.y >> 4, n = blockIdx.y & 15;
                const int b = m >> 11, t = m & (Tt - 1);
                rowp = g_qkv + ((size_t)s * Bx * Nn + (size_t)(b * Nn + n)) * Tt * Hh
                             + (size_t)t * Hh;
            } else {
                rowp = outg + (size_t)m * Dd + blockIdx.y * 128;
            }
            #pragma unroll
            for (int j = 0; j < 8; j++) {
                const int c = wn * 64 + j * 8 + (lane & 3) * 2;
                float2 v;
                v.x = acc[mm][j][half * 2];
                v.y = acc[mm][j][half * 2 + 1];
                *(float2*)(rowp + c) = v;
            }
        }
    }
}

// ---------------------------------------------------------------------------
// Flash attention (R14, unchanged)
// ---------------------------------------------------------------------------
#define AT_STAGE 65536
#define ATTN_SMEM2 (3 * 65536)

__global__ void __launch_bounds__(256, 1) attn_mma_kernel()
{
    extern __shared__ char smc[];
    const uint32_t smb = smem_u32(smc);
    const int tid = threadIdx.x;
    const int wid = tid >> 5, lane = tid & 31;
    const int qt = 15 - (blockIdx.x >> 5);
    const int sub = blockIdx.x & 31;
    const int n = sub >> 1, b = sub & 1;
    const int t0 = qt * 128;
    const size_t bn = (size_t)(b * Nn + n) * Tt * Hh;

    const __nv_bfloat16* qhp = g_qh + bn;
    const __nv_bfloat16* qlp = g_ql + bn;
    const __nv_bfloat16* khp = g_kh + bn;
    const __nv_bfloat16* klp = g_kl + bn;
    const __nv_bfloat16* vhp = g_vth + bn;
    const __nv_bfloat16* vlp = g_vtl + bn;

    const int c_lo = (t0 >= WINDOW) ? ((t0 - WINDOW + 1) >> 6) : 0;
    const int c_hi = (t0 + 127) >> 6;

    const int arow = wid * 16 + (lane & 15);
    const int agsel = lane >> 4;
    const int bro = (lane & 7) + ((lane >> 4) << 3);
    const int bgsel = (lane >> 3) & 1;
    const int qr0 = t0 + wid * 16 + (lane >> 2);

    uint32_t qhf[8][4], qlf[8][4];
    {
        const int r = tid >> 1;
        const __nv_bfloat16* sh = qhp + (size_t)(t0 + r) * Hh;
        const __nv_bfloat16* sl = qlp + (size_t)(t0 + r) * Hh;
        #pragma unroll
        for (int i = 0; i < 8; i++) {
            int g = (tid & 1) * 8 + i;
            uint32_t off = (uint32_t)(r * 256 + ((g ^ (r & 7)) << 4));
            cp16(smb + off, sh + g * 8);
            cp16(smb + 32768 + off, sl + g * 8);
        }
        CP_COMMIT();
        asm volatile("cp.async.wait_group 0;" ::: "memory");
        __syncthreads();
        #pragma unroll
        for (int ks = 0; ks < 8; ks++) {
            uint32_t qa = (uint32_t)(arow * 256 + (((ks * 2 + agsel) ^ (arow & 7)) << 4));
            ldm4(qhf[ks], smb + qa);
            ldm4(qlf[ks], smb + 32768 + qa);
        }
        __syncthreads();
    }

    #pragma unroll 1
    for (int pc = 0; pc < 2; pc++) {
        const int c = c_lo + pc;
        const int k0 = c * 64;
        uint32_t sb = smb + pc * AT_STAGE;
        {
            const int r = tid >> 2;
            const __nv_bfloat16* sh = khp + (size_t)(k0 + r) * Hh;
            const __nv_bfloat16* sl = klp + (size_t)(k0 + r) * Hh;
            #pragma unroll
            for (int i = 0; i < 4; i++) {
                int g = (tid & 3) * 4 + i;
                uint32_t off = (uint32_t)(r * 256 + ((g ^ (r & 7)) << 4));
                cp16(sb + off, sh + g * 8);
                cp16(sb + 16384 + off, sl + g * 8);
            }
        }
        {
            const int r = tid >> 1;
            const __nv_bfloat16* sh = vhp + (size_t)r * Tt + k0;
            const __nv_bfloat16* sl = vlp + (size_t)r * Tt + k0;
            #pragma unroll
            for (int i = 0; i < 4; i++) {
                int g = (tid & 1) * 4 + i;
                uint32_t off = (uint32_t)(r * 128 + ((g ^ (r & 7)) << 4));
                cp16(sb + 32768 + off, sh + g * 8);
                cp16(sb + 49152 + off, sl + g * 8);
            }
        }
        CP_COMMIT();
    }

    float oacc[16][4];
    #pragma unroll
    for (int i = 0; i < 16; i++)
        #pragma unroll
        for (int q = 0; q < 4; q++) oacc[i][q] = 0.f;
    float l0 = 0.f, l1 = 0.f;

    int rbuf = 0, wbuf = 2;
    for (int c = c_lo; c <= c_hi; c++) {
        if (c < c_hi) asm volatile("cp.async.wait_group 1;" ::: "memory");
        else          asm volatile("cp.async.wait_group 0;" ::: "memory");
        __syncthreads();

        if (c + 2 <= c_hi) {
            const int k2 = (c + 2) * 64;
            uint32_t sb = smb + wbuf * AT_STAGE;
            {
                const int r = tid >> 2;
                const __nv_bfloat16* sh = khp + (size_t)(k2 + r) * Hh;
                const __nv_bfloat16* sl = klp + (size_t)(k2 + r) * Hh;
                #pragma unroll
                for (int i = 0; i < 4; i++) {
                    int g = (tid & 3) * 4 + i;
                    uint32_t off = (uint32_t)(r * 256 + ((g ^ (r & 7)) << 4));
                    cp16(sb + off, sh + g * 8);
                    cp16(sb + 16384 + off, sl + g * 8);
                }
            }
            {
                const int r = tid >> 1;
                const __nv_bfloat16* sh = vhp + (size_t)r * Tt + k2;
                const __nv_bfloat16* sl = vlp + (size_t)r * Tt + k2;
                #pragma unroll
                for (int i = 0; i < 4; i++) {
                    int g = (tid & 1) * 4 + i;
                    uint32_t off = (uint32_t)(r * 128 + ((g ^ (r & 7)) << 4));
                    cp16(sb + 32768 + off, sh + g * 8);
                    cp16(sb + 49152 + off, sl + g * 8);
                }
            }
            CP_COMMIT();
        }

        const int k0 = c * 64;
        const bool full = (k0 <= t0 - 64) && (k0 >= t0 - (WINDOW - 128));
        const uint32_t KHb = smb + rbuf * AT_STAGE;
        const uint32_t KLb = KHb + 16384, VHb = KHb + 32768, VLb = KHb + 49152;

        float sacc[8][4];
        #pragma unroll
        for (int i = 0; i < 8; i++)
            #pragma unroll
            for (int q = 0; q < 4; q++) sacc[i][q] = 0.f;

        #pragma unroll
        for (int ks = 0; ks < 8; ks++) {
            uint32_t khf[4][4], klf[4][4];
            #pragma unroll
            for (int nk = 0; nk < 4; nk++) {
                int r = nk * 16 + bro;
                uint32_t ka = (uint32_t)(r * 256 + (((ks * 2 + bgsel) ^ (r & 7)) << 4));
                ldm4(khf[nk], KHb + ka);
                ldm4(klf[nk], KLb + ka);
            }
            #pragma unroll
            for (int nk = 0; nk < 4; nk++) {
                mma16816(sacc[2 * nk],     qhf[ks], khf[nk][0], khf[nk][1]);
                mma16816(sacc[2 * nk + 1], qhf[ks], khf[nk][2], khf[nk][3]);
            }
            #pragma unroll
            for (int nk = 0; nk < 4; nk++) {
                mma16816(sacc[2 * nk],     qlf[ks], khf[nk][0], khf[nk][1]);
                mma16816(sacc[2 * nk + 1], qlf[ks], khf[nk][2], khf[nk][3]);
            }
            #pragma unroll
            for (int nk = 0; nk < 4; nk++) {
                mma16816(sacc[2 * nk],     qhf[ks], klf[nk][0], klf[nk][1]);
                mma16816(sacc[2 * nk + 1], qhf[ks], klf[nk][2], klf[nk][3]);
            }
        }

        float s0 = 0.f, s1 = 0.f;
        uint32_t phi[4][4], plo[4][4];
        #pragma unroll
        for (int nt = 0; nt < 8; nt++)
            #pragma unroll
            for (int q = 0; q < 4; q++) {
                float s = sacc[nt][q];
                float e = __expf(s * (2.0f / SOFT_CAP));
                float r = __fdividef(2.0f, e + 1.0f);
                float p = __expf(SOFT_CAP - SOFT_CAP * r);
                if (!full) {
                    int qr = qr0 + ((q & 2) ? 8 : 0);
                    int kc = k0 + nt * 8 + (lane & 3) * 2 + (q & 1);
                    if (kc > qr || qr - kc >= WINDOW) p = 0.f;
                }
                sacc[nt][q] = p;
                if (q & 2) s1 += p; else s0 += p;
            }
        #pragma unroll
        for (int kt = 0; kt < 4; kt++) {
            #pragma unroll
            for (int part = 0; part < 4; part++) {
                int nt = 2 * kt + (part >> 1);
                float x = sacc[nt][(part & 1) * 2];
                float y = sacc[nt][(part & 1) * 2 + 1];
                __nv_bfloat162 h2 = __floats2bfloat162_rn(x, y);
                float lx = x - __bfloat162float(h2.x);
                float ly = y - __bfloat162float(h2.y);
                __nv_bfloat162 l2 = __floats2bfloat162_rn(lx, ly);
                phi[kt][part] = *(uint32_t*)&h2;
                plo[kt][part] = *(uint32_t*)&l2;
            }
        }
        s0 += __shfl_xor_sync(0xffffffffu, s0, 1);
        s0 += __shfl_xor_sync(0xffffffffu, s0, 2);
        s1 += __shfl_xor_sync(0xffffffffu, s1, 1);
        s1 += __shfl_xor_sync(0xffffffffu, s1, 2);
        l0 += s0;
        l1 += s1;

        #pragma unroll
        for (int kt = 0; kt < 4; kt++) {
            #pragma unroll
            for (int gh = 0; gh < 2; gh++) {
                uint32_t vhf[4][4], vlf[4][4];
                #pragma unroll
                for (int j = 0; j < 4; j++) {
                    int r = (gh * 4 + j) * 16 + bro;
                    uint32_t va = (uint32_t)(r * 128 + (((kt * 2 + bgsel) ^ (r & 7)) << 4));
                    ldm4(vhf[j], VHb + va);
                    ldm4(vlf[j], VLb + va);
                }
                float (*oa)[4] = &oacc[gh * 8];
                #pragma unroll
                for (int j = 0; j < 4; j++) {
                    mma16816(oa[2 * j],     phi[kt], vhf[j][0], vhf[j][1]);
                    mma16816(oa[2 * j + 1], phi[kt], vhf[j][2], vhf[j][3]);
                }
                #pragma unroll
                for (int j = 0; j < 4; j++) {
                    mma16816(oa[2 * j],     plo[kt], vhf[j][0], vhf[j][1]);
                    mma16816(oa[2 * j + 1], plo[kt], vhf[j][2], vhf[j][3]);
                }
                #pragma unroll
                for (int j = 0; j < 4; j++) {
                    mma16816(oa[2 * j],     phi[kt], vlf[j][0], vlf[j][1]);
                    mma16816(oa[2 * j + 1], phi[kt], vlf[j][2], vlf[j][3]);
                }
            }
        }
        __syncthreads();
        rbuf = (rbuf == 2) ? 0 : rbuf + 1;
        wbuf = (wbuf == 2) ? 0 : wbuf + 1;
    }

    float inv0 = __fdividef(1.f, l0), inv1 = __fdividef(1.f, l1);
    const int tr0 = t0 + wid * 16 + (lane >> 2);
    #pragma unroll
    for (int nt = 0; nt < 16; nt++) {
        int col = nt * 8 + (lane & 3) * 2;
        size_t o0 = ((size_t)b * Tt + tr0) * Dd + n * Hh + col;
        size_t o1 = ((size_t)b * Tt + tr0 + 8) * Dd + n * Hh + col;
        float x0 = oacc[nt][0] * inv0, y0 = oacc[nt][1] * inv0;
        float x1 = oacc[nt][2] * inv1, y1 = oacc[nt][3] * inv1;
        __half hx0 = __float2half(x0), hy0 = __float2half(y0);
        __half hx1 = __float2half(x1), hy1 = __float2half(y1);
        *(__half2*)(g_ehi + o0) = __half2(hx0, hy0);
        *(__half2*)(g_elo + o0) = __half2(__float2half(x0 - __half2float(hx0)),
                                          __float2half(y0 - __half2float(hy0)));
        *(__half2*)(g_ehi + o1) = __half2(hx1, hy1);
        *(__half2*)(g_elo + o1) = __half2(__float2half(x1 - __half2float(hx1)),
                                          __float2half(y1 - __half2float(hy1)));
    }
}

// ---------------------------------------------------------------------------
extern "C" void kernel_launch(void* const* d_in, const int* in_sizes, int n_in,
                              void* d_out, int out_size)
{
    const float* x       = (const float*)d_in[0];
    const float* w_qkv   = (const float*)d_in[1];
    const float* w_out   = (const float*)d_in[2];
    const int*   seg_pos = (const int*)d_in[3];
    float* out = (float*)d_out;

    cudaFuncSetAttribute(mma_gemm<0>, cudaFuncAttributeMaxDynamicSharedMemorySize, GEMM_SMEM);
    cudaFuncSetAttribute(mma_gemm<1>, cudaFuncAttributeMaxDynamicSharedMemorySize, GEMM_SMEM);
    cudaFuncSetAttribute(attn_mma_kernel, cudaFuncAttributeMaxDynamicSharedMemorySize, ATTN_SMEM2);

    // launch order chosen so attn is the 4th launch (ncu capture target)
    prepA_kernel<<<PREPA_SPLITX + 4 * 64 * 48, 256>>>(x, w_qkv);              // 1
    mma_gemm<0><<<dim3(Bx * Tt / 128, 48), 256, GEMM_SMEM>>>(nullptr);        // 2
    prepB_kernel<<<PREPB_ROPE + 64 * 4 * 32, 256>>>(seg_pos);                 // 3
    attn_mma_kernel<<<dim3(16 * Nn * Bx), 256, ATTN_SMEM2>>>();               // 4
    transpose_wout_kernel<<<dim3(Dd / 32, Dd / 32), 256>>>(w_out);            // 5
    mma_gemm<1><<<dim3(Bx * Tt / 128, Dd / 128), 256, GEMM_SMEM>>>(out);      // 6
}

// round 16
// speedup vs baseline: 2.5417x; 1.2584x over previous
#include <cuda_runtime.h>
#include <cuda_bf16.h>
#include <cuda_fp16.h>
#include <math.h>
#include <float.h>
#include <stdint.h>

#define Bx 2
#define Tt 2048
#define Dd 2048
#define Nn 16
#define Hh 128
#define WINDOW 1024
#define SOFT_CAP 50.0f

#define SZQ ((size_t)Bx * Nn * Tt * Hh)

// fp32 scratch
__device__ float g_qkv[3ull * Bx * Nn * Tt * Hh];
// fp16 scratch (GEMMs)
__device__ __half g_xhi[(size_t)Bx * Tt * Dd];
__device__ __half g_wqh[48ull * Hh * Dd];
__device__ __half g_woh[(size_t)Dd * Dd];
__device__ __half g_ehi[(size_t)Bx * Tt * Dd], g_elo[(size_t)Bx * Tt * Dd];
// bf16 split scratch (attention)
__device__ __nv_bfloat16 g_qh[SZQ], g_ql[SZQ];
__device__ __nv_bfloat16 g_kh[SZQ], g_kl[SZQ];
__device__ __nv_bfloat16 g_vth[SZQ], g_vtl[SZQ];
// RoPE inverse timescales
__device__ double g_invts[64];

// ---------------------------------------------------------------------------
// helpers
// ---------------------------------------------------------------------------
__device__ __forceinline__ uint32_t smem_u32(const void* p) {
    uint32_t a;
    asm("{ .reg .u64 t; cvta.to.shared.u64 t, %1; cvt.u32.u64 %0, t; }" : "=r"(a) : "l"(p));
    return a;
}
__device__ __forceinline__ void ldm4(uint32_t* r, uint32_t addr) {
    asm volatile("ldmatrix.sync.aligned.m8n8.x4.shared.b16 {%0,%1,%2,%3}, [%4];"
        : "=r"(r[0]), "=r"(r[1]), "=r"(r[2]), "=r"(r[3]) : "r"(addr));
}
__device__ __forceinline__ void mma16816(float* c, const uint32_t* a, uint32_t b0, uint32_t b1) {
    asm volatile("mma.sync.aligned.m16n8k16.row.col.f32.bf16.bf16.f32 "
        "{%0,%1,%2,%3}, {%4,%5,%6,%7}, {%8,%9}, {%0,%1,%2,%3};"
        : "+f"(c[0]), "+f"(c[1]), "+f"(c[2]), "+f"(c[3])
        : "r"(a[0]), "r"(a[1]), "r"(a[2]), "r"(a[3]), "r"(b0), "r"(b1));
}
__device__ __forceinline__ void mma16816h(float* c, const uint32_t* a, uint32_t b0, uint32_t b1) {
    asm volatile("mma.sync.aligned.m16n8k16.row.col.f32.f16.f16.f32 "
        "{%0,%1,%2,%3}, {%4,%5,%6,%7}, {%8,%9}, {%0,%1,%2,%3};"
        : "+f"(c[0]), "+f"(c[1]), "+f"(c[2]), "+f"(c[3])
        : "r"(a[0]), "r"(a[1]), "r"(a[2]), "r"(a[3]), "r"(b0), "r"(b1));
}
__device__ __forceinline__ void cp16(uint32_t dst, const void* src) {
    asm volatile("cp.async.cg.shared.global [%0], [%1], 16;" :: "r"(dst), "l"(src));
}
#define CP_COMMIT() asm volatile("cp.async.commit_group;" ::: "memory")

// ---------------------------------------------------------------------------
// prep A: split_x (fp32->fp16 hi only) + w_qkv transpose + ts table
// ---------------------------------------------------------------------------
#define PREPA_SPLITX 8192
__global__ void prepA_kernel(const float* __restrict__ x,
                             const float* __restrict__ w_qkv)
{
    if (blockIdx.x < PREPA_SPLITX) {
        size_t i = (size_t)blockIdx.x * 256 + threadIdx.x;
        float4 v = ((const float4*)x)[i];
        __half2* H = (__half2*)g_xhi;
        H[i * 2]     = __half2(__float2half(v.x), __float2half(v.y));
        H[i * 2 + 1] = __half2(__float2half(v.z), __float2half(v.w));
        if (blockIdx.x == 0 && threadIdx.x < 64) {
            g_invts[threadIdx.x] =
                exp2(-(double)threadIdx.x * (13.287712379549449 / 64.0));
        }
        return;
    }
    __shared__ float tile[32][33];
    const int bid = blockIdx.x - PREPA_SPLITX;
    const int cx = bid & 3;
    const int ry = (bid >> 2) & 63;
    const int mat = bid >> 8;
    const int tx = threadIdx.x & 31, ty = threadIdx.x >> 5;
    const int c0 = cx * 32, r0 = ry * 32;
    const float* A = w_qkv + (size_t)mat * Dd * Hh;
    #pragma unroll
    for (int i = ty; i < 32; i += 8)
        tile[i][tx] = A[(size_t)(r0 + i) * Hh + c0 + tx];
    __syncthreads();
    __half* H = g_wqh + (size_t)mat * Dd * Hh;
    #pragma unroll
    for (int i = ty; i < 32; i += 8)
        H[(size_t)(c0 + i) * Dd + r0 + tx] = __float2half(tile[tx][i]);
}

// ---------------------------------------------------------------------------
// w_out transpose (runs after attn)
// ---------------------------------------------------------------------------
__global__ void transpose_wout_kernel(const float* __restrict__ in)
{
    __shared__ float tile[32][33];
    const int c0 = blockIdx.x * 32, r0 = blockIdx.y * 32;
    const int tx = threadIdx.x & 31, ty = threadIdx.x >> 5;
    #pragma unroll
    for (int i = ty; i < 32; i += 8)
        tile[i][tx] = in[(size_t)(r0 + i) * Dd + c0 + tx];
    __syncthreads();
    #pragma unroll
    for (int i = ty; i < 32; i += 8)
        g_woh[(size_t)(c0 + i) * Dd + r0 + tx] = __float2half(tile[tx][i]);
}

// ---------------------------------------------------------------------------
// prep B: rope+split + vsplit
// ---------------------------------------------------------------------------
#define PREPB_ROPE 16384
__global__ void prepB_kernel(const int* __restrict__ segment_pos)
{
    if (blockIdx.x < PREPB_ROPE) {
        const int row = blockIdx.x * 4 + ((int)threadIdx.x >> 6);
        const int h = threadIdx.x & 63;
        const int b = row / (Nn * Tt);
        const int nt = row - b * (Nn * Tt);
        const int n = nt >> 11;
        const int t = nt & (Tt - 1);
        const int pos = segment_pos[b * Tt + t];

        const float ang = (float)((double)pos * g_invts[h]);
        float sn, cs;
        sincosf(ang, &sn, &cs);

        const size_t base = ((size_t)(b * Nn + n) * Tt + t) * Hh;
        const float* q = g_qkv + base;
        const float* k = g_qkv + SZQ + base;
        const float qs = 0.08838834764831845f;

        float q1 = q[h], q2 = q[h + 64];
        float qa = (q1 * cs - q2 * sn) * qs;
        float qb = (q2 * cs + q1 * sn) * qs;
        float k1 = k[h], k2 = k[h + 64];
        float ka = k1 * cs - k2 * sn;
        float kb = k2 * cs + k1 * sn;

        __nv_bfloat16 hqa = __float2bfloat16(qa), hqb = __float2bfloat16(qb);
        __nv_bfloat16 hka = __float2bfloat16(ka), hkb = __float2bfloat16(kb);
        g_qh[base + h] = hqa;       g_qh[base + h + 64] = hqb;
        g_ql[base + h] = __float2bfloat16(qa - __bfloat162float(hqa));
        g_ql[base + h + 64] = __float2bfloat16(qb - __bfloat162float(hqb));
        g_kh[base + h] = hka;       g_kh[base + h + 64] = hkb;
        g_kl[base + h] = __float2bfloat16(ka - __bfloat162float(hka));
        g_kl[base + h + 64] = __float2bfloat16(kb - __bfloat162float(hkb));
        return;
    }
    __shared__ float tile[32][33];
    const int bid = blockIdx.x - PREPB_ROPE;
    const int tx = threadIdx.x & 31, ty = threadIdx.x >> 5;
    const int xt = bid & 63;
    const int yh = (bid >> 6) & 3;
    const int bnz = bid >> 8;
    const int t0 = xt * 32, h0 = yh * 32;
    const float* v = g_qkv + 2 * SZQ + (size_t)bnz * Tt * Hh;
    #pragma unroll
    for (int i = ty; i < 32; i += 8)
        tile[i][tx] = v[(size_t)(t0 + i) * Hh + h0 + tx];
    __syncthreads();
    const size_t dbase = (size_t)bnz * Hh * Tt;
    #pragma unroll
    for (int i = ty; i < 32; i += 8) {
        float val = tile[tx][i];
        __nv_bfloat16 hi = __float2bfloat16(val);
        size_t o = dbase + (size_t)(h0 + i) * Tt + t0 + tx;
        g_vth[o] = hi;
        g_vtl[o] = __float2bfloat16(val - __bfloat162float(hi));
    }
}

// ---------------------------------------------------------------------------
// fp16 mma.sync GEMM.
// MODE 0: single-term (A_hi * B_hi), 2 tiles/stage (16 KB).
// MODE 1: 2-term (A = Ah + Al), 3 tiles/stage (24 KB).
// K-chunk 32, 3-stage ring, 256 thr, 2 CTAs/SM.
// ---------------------------------------------------------------------------
#define TILE32_B 8192
#define GEMM_SMEM0 (3 * 2 * TILE32_B)   // 48 KB
#define GEMM_SMEM1 (3 * 3 * TILE32_B)   // 72 KB

__device__ __forceinline__ uint32_t sw64(int r, int g) {
    return (uint32_t)(r * 64 + ((g ^ ((r >> 1) & 3)) << 4));
}

template<int MODE>
__global__ void __launch_bounds__(256, 2) mma_gemm(float* __restrict__ outg) {
    constexpr int NT = (MODE == 0) ? 2 : 3;      // tiles per stage
    constexpr uint32_t SB = NT * TILE32_B;       // stage bytes
    extern __shared__ char smc[];
    const uint32_t smb = smem_u32(smc);
    const int tid = threadIdx.x;
    const int wid = tid >> 5, lane = tid & 31;
    const int m0 = blockIdx.x * 128;

    const __half* gsrc[3];
    if (MODE == 0) {
        gsrc[0] = g_xhi;
        gsrc[1] = g_wqh + (size_t)blockIdx.y * (128 * Dd);
    } else {
        gsrc[0] = g_ehi;
        gsrc[1] = g_elo;
        gsrc[2] = g_woh + (size_t)blockIdx.y * (128 * Dd);
    }
    const int srow = tid >> 1, sg0 = (tid & 1) * 2;
    {
        const size_t aoff = (size_t)(m0 + srow) * Dd + sg0 * 8;
        const size_t boff = (size_t)srow * Dd + sg0 * 8;
        if (MODE == 0) { gsrc[0] += aoff; gsrc[1] += boff; }
        else           { gsrc[0] += aoff; gsrc[1] += aoff; gsrc[2] += boff; }
    }
    uint32_t soff[2];
    soff[0] = sw64(srow, sg0);
    soff[1] = sw64(srow, sg0 + 1);

    const int wm = wid & 3, wn = wid >> 2;
    const int arow = wm * 32 + (lane & 15);
    const int agsel = lane >> 4;
    const int brow = wn * 64 + (lane & 7) + (lane >> 4) * 8;
    const int bgsel = (lane >> 3) & 1;

    float acc[2][8][4];
    #pragma unroll
    for (int i = 0; i < 2; i++)
        #pragma unroll
        for (int j = 0; j < 8; j++)
            #pragma unroll
            for (int q = 0; q < 4; q++) acc[i][j][q] = 0.f;

    const int KT = Dd / 32;

    #pragma unroll
    for (int pc = 0; pc < 2; pc++) {
        uint32_t buf = smb + pc * SB;
        #pragma unroll
        for (int t = 0; t < NT; t++) {
            cp16(buf + t * TILE32_B + soff[0], gsrc[t] + pc * 32);
            cp16(buf + t * TILE32_B + soff[1], gsrc[t] + pc * 32 + 8);
        }
        CP_COMMIT();
    }

    int rbuf = 0, wbuf = 2;
    for (int kc = 0; kc < KT; kc++) {
        if (kc + 1 < KT) asm volatile("cp.async.wait_group 1;" ::: "memory");
        else             asm volatile("cp.async.wait_group 0;" ::: "memory");
        __syncthreads();

        if (kc + 2 < KT) {
            uint32_t buf = smb + wbuf * SB;
            #pragma unroll
            for (int t = 0; t < NT; t++) {
                cp16(buf + t * TILE32_B + soff[0], gsrc[t] + (kc + 2) * 32);
                cp16(buf + t * TILE32_B + soff[1], gsrc[t] + (kc + 2) * 32 + 8);
            }
            CP_COMMIT();
        }

        const uint32_t tb = smb + rbuf * SB;
        const uint32_t bb = tb + (NT - 1) * TILE32_B;
        #pragma unroll
        for (int ks = 0; ks < 2; ks++) {
            uint32_t ah[2][4], al[2][4];
            #pragma unroll
            for (int mm = 0; mm < 2; mm++) {
                uint32_t ad = sw64(arow + mm * 16, ks * 2 + agsel);
                ldm4(ah[mm], tb + ad);
                if (MODE == 1) ldm4(al[mm], tb + TILE32_B + ad);
            }
            #pragma unroll
            for (int j = 0; j < 4; j++) {
                uint32_t bd = sw64(brow + j * 16, ks * 2 + bgsel);
                uint32_t bh[4];
                ldm4(bh, bb + bd);
                mma16816h(acc[0][2 * j],     ah[0], bh[0], bh[1]);
                mma16816h(acc[0][2 * j + 1], ah[0], bh[2], bh[3]);
                mma16816h(acc[1][2 * j],     ah[1], bh[0], bh[1]);
                mma16816h(acc[1][2 * j + 1], ah[1], bh[2], bh[3]);
                if (MODE == 1) {
                    mma16816h(acc[0][2 * j],     al[0], bh[0], bh[1]);
                    mma16816h(acc[0][2 * j + 1], al[0], bh[2], bh[3]);
                    mma16816h(acc[1][2 * j],     al[1], bh[0], bh[1]);
                    mma16816h(acc[1][2 * j + 1], al[1], bh[2], bh[3]);
                }
            }
        }
        rbuf = (rbuf == 2) ? 0 : rbuf + 1;
        wbuf = (wbuf == 2) ? 0 : wbuf + 1;
    }

    #pragma unroll
    for (int mm = 0; mm < 2; mm++) {
        #pragma unroll
        for (int half = 0; half < 2; half++) {
            const int r = wm * 32 + mm * 16 + (lane >> 2) + half * 8;
            const int m = m0 + r;
            float* rowp;
            if (MODE == 0) {
                const int s = blockIdx.y >> 4, n = blockIdx.y & 15;
                const int b = m >> 11, t = m & (Tt - 1);
                rowp = g_qkv + ((size_t)s * Bx * Nn + (size_t)(b * Nn + n)) * Tt * Hh
                             + (size_t)t * Hh;
            } else {
                rowp = outg + (size_t)m * Dd + blockIdx.y * 128;
            }
            #pragma unroll
            for (int j = 0; j < 8; j++) {
                const int c = wn * 64 + j * 8 + (lane & 3) * 2;
                float2 v;
                v.x = acc[mm][j][half * 2];
                v.y = acc[mm][j][half * 2 + 1];
                *(float2*)(rowp + c) = v;
            }
        }
    }
}

// ---------------------------------------------------------------------------
// Flash attention (R14/R15, unchanged)
// ---------------------------------------------------------------------------
#define AT_STAGE 65536
#define ATTN_SMEM2 (3 * 65536)

__global__ void __launch_bounds__(256, 1) attn_mma_kernel()
{
    extern __shared__ char smc[];
    const uint32_t smb = smem_u32(smc);
    const int tid = threadIdx.x;
    const int wid = tid >> 5, lane = tid & 31;
    const int qt = 15 - (blockIdx.x >> 5);
    const int sub = blockIdx.x & 31;
    const int n = sub >> 1, b = sub & 1;
    const int t0 = qt * 128;
    const size_t bn = (size_t)(b * Nn + n) * Tt * Hh;

    const __nv_bfloat16* qhp = g_qh + bn;
    const __nv_bfloat16* qlp = g_ql + bn;
    const __nv_bfloat16* khp = g_kh + bn;
    const __nv_bfloat16* klp = g_kl + bn;
    const __nv_bfloat16* vhp = g_vth + bn;
    const __nv_bfloat16* vlp = g_vtl + bn;

    const int c_lo = (t0 >= WINDOW) ? ((t0 - WINDOW + 1) >> 6) : 0;
    const int c_hi = (t0 + 127) >> 6;

    const int arow = wid * 16 + (lane & 15);
    const int agsel = lane >> 4;
    const int bro = (lane & 7) + ((lane >> 4) << 3);
    const int bgsel = (lane >> 3) & 1;
    const int qr0 = t0 + wid * 16 + (lane >> 2);

    uint32_t qhf[8][4], qlf[8][4];
    {
        const int r = tid >> 1;
        const __nv_bfloat16* sh = qhp + (size_t)(t0 + r) * Hh;
        const __nv_bfloat16* sl = qlp + (size_t)(t0 + r) * Hh;
        #pragma unroll
        for (int i = 0; i < 8; i++) {
            int g = (tid & 1) * 8 + i;
            uint32_t off = (uint32_t)(r * 256 + ((g ^ (r & 7)) << 4));
            cp16(smb + off, sh + g * 8);
            cp16(smb + 32768 + off, sl + g * 8);
        }
        CP_COMMIT();
        asm volatile("cp.async.wait_group 0;" ::: "memory");
        __syncthreads();
        #pragma unroll
        for (int ks = 0; ks < 8; ks++) {
            uint32_t qa = (uint32_t)(arow * 256 + (((ks * 2 + agsel) ^ (arow & 7)) << 4));
            ldm4(qhf[ks], smb + qa);
            ldm4(qlf[ks], smb + 32768 + qa);
        }
        __syncthreads();
    }

    #pragma unroll 1
    for (int pc = 0; pc < 2; pc++) {
        const int c = c_lo + pc;
        const int k0 = c * 64;
        uint32_t sb = smb + pc * AT_STAGE;
        {
            const int r = tid >> 2;
            const __nv_bfloat16* sh = khp + (size_t)(k0 + r) * Hh;
            const __nv_bfloat16* sl = klp + (size_t)(k0 + r) * Hh;
            #pragma unroll
            for (int i = 0; i < 4; i++) {
                int g = (tid & 3) * 4 + i;
                uint32_t off = (uint32_t)(r * 256 + ((g ^ (r & 7)) << 4));
                cp16(sb + off, sh + g * 8);
                cp16(sb + 16384 + off, sl + g * 8);
            }
        }
        {
            const int r = tid >> 1;
            const __nv_bfloat16* sh = vhp + (size_t)r * Tt + k0;
            const __nv_bfloat16* sl = vlp + (size_t)r * Tt + k0;
            #pragma unroll
            for (int i = 0; i < 4; i++) {
                int g = (tid & 1) * 4 + i;
                uint32_t off = (uint32_t)(r * 128 + ((g ^ (r & 7)) << 4));
                cp16(sb + 32768 + off, sh + g * 8);
                cp16(sb + 49152 + off, sl + g * 8);
            }
        }
        CP_COMMIT();
    }

    float oacc[16][4];
    #pragma unroll
    for (int i = 0; i < 16; i++)
        #pragma unroll
        for (int q = 0; q < 4; q++) oacc[i][q] = 0.f;
    float l0 = 0.f, l1 = 0.f;

    int rbuf = 0, wbuf = 2;
    for (int c = c_lo; c <= c_hi; c++) {
        if (c < c_hi) asm volatile("cp.async.wait_group 1;" ::: "memory");
        else          asm volatile("cp.async.wait_group 0;" ::: "memory");
        __syncthreads();

        if (c + 2 <= c_hi) {
            const int k2 = (c + 2) * 64;
            uint32_t sb = smb + wbuf * AT_STAGE;
            {
                const int r = tid >> 2;
                const __nv_bfloat16* sh = khp + (size_t)(k2 + r) * Hh;
                const __nv_bfloat16* sl = klp + (size_t)(k2 + r) * Hh;
                #pragma unroll
                for (int i = 0; i < 4; i++) {
                    int g = (tid & 3) * 4 + i;
                    uint32_t off = (uint32_t)(r * 256 + ((g ^ (r & 7)) << 4));
                    cp16(sb + off, sh + g * 8);
                    cp16(sb + 16384 + off, sl + g * 8);
                }
            }
            {
                const int r = tid >> 1;
                const __nv_bfloat16* sh = vhp + (size_t)r * Tt + k2;
                const __nv_bfloat16* sl = vlp + (size_t)r * Tt + k2;
                #pragma unroll
                for (int i = 0; i < 4; i++) {
                    int g = (tid & 1) * 4 + i;
                    uint32_t off = (uint32_t)(r * 128 + ((g ^ (r & 7)) << 4));
                    cp16(sb + 32768 + off, sh + g * 8);
                    cp16(sb + 49152 + off, sl + g * 8);
                }
            }
            CP_COMMIT();
        }

        const int k0 = c * 64;
        const bool full = (k0 <= t0 - 64) && (k0 >= t0 - (WINDOW - 128));
        const uint32_t KHb = smb + rbuf * AT_STAGE;
        const uint32_t KLb = KHb + 16384, VHb = KHb + 32768, VLb = KHb + 49152;

        float sacc[8][4];
        #pragma unroll
        for (int i = 0; i < 8; i++)
            #pragma unroll
            for (int q = 0; q < 4; q++) sacc[i][q] = 0.f;

        #pragma unroll
        for (int ks = 0; ks < 8; ks++) {
            uint32_t khf[4][4], klf[4][4];
            #pragma unroll
            for (int nk = 0; nk < 4; nk++) {
                int r = nk * 16 + bro;
                uint32_t ka = (uint32_t)(r * 256 + (((ks * 2 + bgsel) ^ (r & 7)) << 4));
                ldm4(khf[nk], KHb + ka);
                ldm4(klf[nk], KLb + ka);
            }
            #pragma unroll
            for (int nk = 0; nk < 4; nk++) {
                mma16816(sacc[2 * nk],     qhf[ks], khf[nk][0], khf[nk][1]);
                mma16816(sacc[2 * nk + 1], qhf[ks], khf[nk][2], khf[nk][3]);
            }
            #pragma unroll
            for (int nk = 0; nk < 4; nk++) {
                mma16816(sacc[2 * nk],     qlf[ks], khf[nk][0], khf[nk][1]);
                mma16816(sacc[2 * nk + 1], qlf[ks], khf[nk][2], khf[nk][3]);
            }
            #pragma unroll
            for (int nk = 0; nk < 4; nk++) {
                mma16816(sacc[2 * nk],     qhf[ks], klf[nk][0], klf[nk][1]);
                mma16816(sacc[2 * nk + 1], qhf[ks], klf[nk][2], klf[nk][3]);
            }
        }

        float s0 = 0.f, s1 = 0.f;
        uint32_t phi[4][4], plo[4][4];
        #pragma unroll
        for (int nt = 0; nt < 8; nt++)
            #pragma unroll
            for (int q = 0; q < 4; q++) {
                float s = sacc[nt][q];
                float e = __expf(s * (2.0f / SOFT_CAP));
                float r = __fdividef(2.0f, e + 1.0f);
                float p = __expf(SOFT_CAP - SOFT_CAP * r);
                if (!full) {
                    int qr = qr0 + ((q & 2) ? 8 : 0);
                    int kc = k0 + nt * 8 + (lane & 3) * 2 + (q & 1);
                    if (kc > qr || qr - kc >= WINDOW) p = 0.f;
                }
                sacc[nt][q] = p;
                if (q & 2) s1 += p; else s0 += p;
            }
        #pragma unroll
        for (int kt = 0; kt < 4; kt++) {
            #pragma unroll
            for (int part = 0; part < 4; part++) {
                int nt = 2 * kt + (part >> 1);
                float x = sacc[nt][(part & 1) * 2];
                float y = sacc[nt][(part & 1) * 2 + 1];
                __nv_bfloat162 h2 = __floats2bfloat162_rn(x, y);
                float lx = x - __bfloat162float(h2.x);
                float ly = y - __bfloat162float(h2.y);
                __nv_bfloat162 l2 = __floats2bfloat162_rn(lx, ly);
                phi[kt][part] = *(uint32_t*)&h2;
                plo[kt][part] = *(uint32_t*)&l2;
            }
        }
        s0 += __shfl_xor_sync(0xffffffffu, s0, 1);
        s0 += __shfl_xor_sync(0xffffffffu, s0, 2);
        s1 += __shfl_xor_sync(0xffffffffu, s1, 1);
        s1 += __shfl_xor_sync(0xffffffffu, s1, 2);
        l0 += s0;
        l1 += s1;

        #pragma unroll
        for (int kt = 0; kt < 4; kt++) {
            #pragma unroll
            for (int gh = 0; gh < 2; gh++) {
                uint32_t vhf[4][4], vlf[4][4];
                #pragma unroll
                for (int j = 0; j < 4; j++) {
                    int r = (gh * 4 + j) * 16 + bro;
                    uint32_t va = (uint32_t)(r * 128 + (((kt * 2 + bgsel) ^ (r & 7)) << 4));
                    ldm4(vhf[j], VHb + va);
                    ldm4(vlf[j], VLb + va);
                }
                float (*oa)[4] = &oacc[gh * 8];
                #pragma unroll
                for (int j = 0; j < 4; j++) {
                    mma16816(oa[2 * j],     phi[kt], vhf[j][0], vhf[j][1]);
                    mma16816(oa[2 * j + 1], phi[kt], vhf[j][2], vhf[j][3]);
                }
                #pragma unroll
                for (int j = 0; j < 4; j++) {
                    mma16816(oa[2 * j],     plo[kt], vhf[j][0], vhf[j][1]);
                    mma16816(oa[2 * j + 1], plo[kt], vhf[j][2], vhf[j][3]);
                }
                #pragma unroll
                for (int j = 0; j < 4; j++) {
                    mma16816(oa[2 * j],     phi[kt], vlf[j][0], vlf[j][1]);
                    mma16816(oa[2 * j + 1], phi[kt], vlf[j][2], vlf[j][3]);
                }
            }
        }
        __syncthreads();
        rbuf = (rbuf == 2) ? 0 : rbuf + 1;
        wbuf = (wbuf == 2) ? 0 : wbuf + 1;
    }

    float inv0 = __fdividef(1.f, l0), inv1 = __fdividef(1.f, l1);
    const int tr0 = t0 + wid * 16 + (lane >> 2);
    #pragma unroll
    for (int nt = 0; nt < 16; nt++) {
        int col = nt * 8 + (lane & 3) * 2;
        size_t o0 = ((size_t)b * Tt + tr0) * Dd + n * Hh + col;
        size_t o1 = ((size_t)b * Tt + tr0 + 8) * Dd + n * Hh + col;
        float x0 = oacc[nt][0] * inv0, y0 = oacc[nt][1] * inv0;
        float x1 = oacc[nt][2] * inv1, y1 = oacc[nt][3] * inv1;
        __half hx0 = __float2half(x0), hy0 = __float2half(y0);
        __half hx1 = __float2half(x1), hy1 = __float2half(y1);
        *(__half2*)(g_ehi + o0) = __half2(hx0, hy0);
        *(__half2*)(g_elo + o0) = __half2(__float2half(x0 - __half2float(hx0)),
                                          __float2half(y0 - __half2float(hy0)));
        *(__half2*)(g_ehi + o1) = __half2(hx1, hy1);
        *(__half2*)(g_elo + o1) = __half2(__float2half(x1 - __half2float(hx1)),
                                          __float2half(y1 - __half2float(hy1)));
    }
}

// ---------------------------------------------------------------------------
extern "C" void kernel_launch(void* const* d_in, const int* in_sizes, int n_in,
                              void* d_out, int out_size)
{
    const float* x       = (const float*)d_in[0];
    const float* w_qkv   = (const float*)d_in[1];
    const float* w_out   = (const float*)d_in[2];
    const int*   seg_pos = (const int*)d_in[3];
    float* out = (float*)d_out;

    cudaFuncSetAttribute(mma_gemm<0>, cudaFuncAttributeMaxDynamicSharedMemorySize, GEMM_SMEM0);
    cudaFuncSetAttribute(mma_gemm<1>, cudaFuncAttributeMaxDynamicSharedMemorySize, GEMM_SMEM1);
    cudaFuncSetAttribute(attn_mma_kernel, cudaFuncAttributeMaxDynamicSharedMemorySize, ATTN_SMEM2);

    prepA_kernel<<<PREPA_SPLITX + 4 * 64 * 48, 256>>>(x, w_qkv);              // 1
    mma_gemm<0><<<dim3(Bx * Tt / 128, 48), 256, GEMM_SMEM0>>>(nullptr);       // 2
    prepB_kernel<<<PREPB_ROPE + 64 * 4 * 32, 256>>>(seg_pos);                 // 3
    attn_mma_kernel<<<dim3(16 * Nn * Bx), 256, ATTN_SMEM2>>>();               // 4
    transpose_wout_kernel<<<dim3(Dd / 32, Dd / 32), 256>>>(w_out);            // 5
    mma_gemm<1><<<dim3(Bx * Tt / 128, Dd / 128), 256, GEMM_SMEM1>>>(out);     // 6
}

// round 17
// speedup vs baseline: 2.5426x; 1.0004x over previous
#include <cuda_runtime.h>
#include <cuda_bf16.h>
#include <cuda_fp16.h>
#include <math.h>
#include <float.h>
#include <stdint.h>

#define Bx 2
#define Tt 2048
#define Dd 2048
#define Nn 16
#define Hh 128
#define WINDOW 1024
#define SOFT_CAP 50.0f

#define SZQ ((size_t)Bx * Nn * Tt * Hh)

// fp32 scratch
__device__ float g_qkv[3ull * Bx * Nn * Tt * Hh];
// fp16 scratch (GEMMs)
__device__ __half g_xhi[(size_t)Bx * Tt * Dd];
__device__ __half g_wqh[48ull * Hh * Dd];
__device__ __half g_woh[(size_t)Dd * Dd];
__device__ __half g_ehi[(size_t)Bx * Tt * Dd], g_elo[(size_t)Bx * Tt * Dd];
// bf16 split scratch (attention)
__device__ __nv_bfloat16 g_qh[SZQ], g_ql[SZQ];
__device__ __nv_bfloat16 g_kh[SZQ], g_kl[SZQ];
__device__ __nv_bfloat16 g_vth[SZQ], g_vtl[SZQ];
// RoPE inverse timescales
__device__ double g_invts[64];

// ---------------------------------------------------------------------------
// helpers
// ---------------------------------------------------------------------------
__device__ __forceinline__ uint32_t smem_u32(const void* p) {
    uint32_t a;
    asm("{ .reg .u64 t; cvta.to.shared.u64 t, %1; cvt.u32.u64 %0, t; }" : "=r"(a) : "l"(p));
    return a;
}
__device__ __forceinline__ void ldm4(uint32_t* r, uint32_t addr) {
    asm volatile("ldmatrix.sync.aligned.m8n8.x4.shared.b16 {%0,%1,%2,%3}, [%4];"
        : "=r"(r[0]), "=r"(r[1]), "=r"(r[2]), "=r"(r[3]) : "r"(addr));
}
__device__ __forceinline__ void mma16816(float* c, const uint32_t* a, uint32_t b0, uint32_t b1) {
    asm volatile("mma.sync.aligned.m16n8k16.row.col.f32.bf16.bf16.f32 "
        "{%0,%1,%2,%3}, {%4,%5,%6,%7}, {%8,%9}, {%0,%1,%2,%3};"
        : "+f"(c[0]), "+f"(c[1]), "+f"(c[2]), "+f"(c[3])
        : "r"(a[0]), "r"(a[1]), "r"(a[2]), "r"(a[3]), "r"(b0), "r"(b1));
}
__device__ __forceinline__ void mma16816h(float* c, const uint32_t* a, uint32_t b0, uint32_t b1) {
    asm volatile("mma.sync.aligned.m16n8k16.row.col.f32.f16.f16.f32 "
        "{%0,%1,%2,%3}, {%4,%5,%6,%7}, {%8,%9}, {%0,%1,%2,%3};"
        : "+f"(c[0]), "+f"(c[1]), "+f"(c[2]), "+f"(c[3])
        : "r"(a[0]), "r"(a[1]), "r"(a[2]), "r"(a[3]), "r"(b0), "r"(b1));
}
__device__ __forceinline__ void cp16(uint32_t dst, const void* src) {
    asm volatile("cp.async.cg.shared.global [%0], [%1], 16;" :: "r"(dst), "l"(src));
}
#define CP_COMMIT() asm volatile("cp.async.commit_group;" ::: "memory")

// ---------------------------------------------------------------------------
// prep A: split_x (fp32->fp16 hi only) + w_qkv transpose + ts table
// ---------------------------------------------------------------------------
#define PREPA_SPLITX 8192
__global__ void prepA_kernel(const float* __restrict__ x,
                             const float* __restrict__ w_qkv)
{
    if (blockIdx.x < PREPA_SPLITX) {
        size_t i = (size_t)blockIdx.x * 256 + threadIdx.x;
        float4 v = ((const float4*)x)[i];
        __half2* H = (__half2*)g_xhi;
        H[i * 2]     = __half2(__float2half(v.x), __float2half(v.y));
        H[i * 2 + 1] = __half2(__float2half(v.z), __float2half(v.w));
        if (blockIdx.x == 0 && threadIdx.x < 64) {
            g_invts[threadIdx.x] =
                exp2(-(double)threadIdx.x * (13.287712379549449 / 64.0));
        }
        return;
    }
    __shared__ float tile[32][33];
    const int bid = blockIdx.x - PREPA_SPLITX;
    const int cx = bid & 3;
    const int ry = (bid >> 2) & 63;
    const int mat = bid >> 8;
    const int tx = threadIdx.x & 31, ty = threadIdx.x >> 5;
    const int c0 = cx * 32, r0 = ry * 32;
    const float* A = w_qkv + (size_t)mat * Dd * Hh;
    #pragma unroll
    for (int i = ty; i < 32; i += 8)
        tile[i][tx] = A[(size_t)(r0 + i) * Hh + c0 + tx];
    __syncthreads();
    __half* H = g_wqh + (size_t)mat * Dd * Hh;
    #pragma unroll
    for (int i = ty; i < 32; i += 8)
        H[(size_t)(c0 + i) * Dd + r0 + tx] = __float2half(tile[tx][i]);
}

// ---------------------------------------------------------------------------
// w_out transpose (runs after attn)
// ---------------------------------------------------------------------------
__global__ void transpose_wout_kernel(const float* __restrict__ in)
{
    __shared__ float tile[32][33];
    const int c0 = blockIdx.x * 32, r0 = blockIdx.y * 32;
    const int tx = threadIdx.x & 31, ty = threadIdx.x >> 5;
    #pragma unroll
    for (int i = ty; i < 32; i += 8)
        tile[i][tx] = in[(size_t)(r0 + i) * Dd + c0 + tx];
    __syncthreads();
    #pragma unroll
    for (int i = ty; i < 32; i += 8)
        g_woh[(size_t)(c0 + i) * Dd + r0 + tx] = __float2half(tile[tx][i]);
}

// ---------------------------------------------------------------------------
// prep B: rope+split + vsplit
// ---------------------------------------------------------------------------
#define PREPB_ROPE 16384
__global__ void prepB_kernel(const int* __restrict__ segment_pos)
{
    if (blockIdx.x < PREPB_ROPE) {
        const int row = blockIdx.x * 4 + ((int)threadIdx.x >> 6);
        const int h = threadIdx.x & 63;
        const int b = row / (Nn * Tt);
        const int nt = row - b * (Nn * Tt);
        const int n = nt >> 11;
        const int t = nt & (Tt - 1);
        const int pos = segment_pos[b * Tt + t];

        const float ang = (float)((double)pos * g_invts[h]);
        float sn, cs;
        sincosf(ang, &sn, &cs);

        const size_t base = ((size_t)(b * Nn + n) * Tt + t) * Hh;
        const float* q = g_qkv + base;
        const float* k = g_qkv + SZQ + base;
        const float qs = 0.08838834764831845f;

        float q1 = q[h], q2 = q[h + 64];
        float qa = (q1 * cs - q2 * sn) * qs;
        float qb = (q2 * cs + q1 * sn) * qs;
        float k1 = k[h], k2 = k[h + 64];
        float ka = k1 * cs - k2 * sn;
        float kb = k2 * cs + k1 * sn;

        __nv_bfloat16 hqa = __float2bfloat16(qa), hqb = __float2bfloat16(qb);
        __nv_bfloat16 hka = __float2bfloat16(ka), hkb = __float2bfloat16(kb);
        g_qh[base + h] = hqa;       g_qh[base + h + 64] = hqb;
        g_ql[base + h] = __float2bfloat16(qa - __bfloat162float(hqa));
        g_ql[base + h + 64] = __float2bfloat16(qb - __bfloat162float(hqb));
        g_kh[base + h] = hka;       g_kh[base + h + 64] = hkb;
        g_kl[base + h] = __float2bfloat16(ka - __bfloat162float(hka));
        g_kl[base + h + 64] = __float2bfloat16(kb - __bfloat162float(hkb));
        return;
    }
    __shared__ float tile[32][33];
    const int bid = blockIdx.x - PREPB_ROPE;
    const int tx = threadIdx.x & 31, ty = threadIdx.x >> 5;
    const int xt = bid & 63;
    const int yh = (bid >> 6) & 3;
    const int bnz = bid >> 8;
    const int t0 = xt * 32, h0 = yh * 32;
    const float* v = g_qkv + 2 * SZQ + (size_t)bnz * Tt * Hh;
    #pragma unroll
    for (int i = ty; i < 32; i += 8)
        tile[i][tx] = v[(size_t)(t0 + i) * Hh + h0 + tx];
    __syncthreads();
    const size_t dbase = (size_t)bnz * Hh * Tt;
    #pragma unroll
    for (int i = ty; i < 32; i += 8) {
        float val = tile[tx][i];
        __nv_bfloat16 hi = __float2bfloat16(val);
        size_t o = dbase + (size_t)(h0 + i) * Tt + t0 + tx;
        g_vth[o] = hi;
        g_vtl[o] = __float2bfloat16(val - __bfloat162float(hi));
    }
}

// ---------------------------------------------------------------------------
// fp16 mma.sync GEMM.
// MODE 0: single-term (A_hi * B_hi), 2 tiles/stage (16 KB).
// MODE 1: 2-term (A = Ah + Al), 3 tiles/stage (24 KB).
// K-chunk 32, 3-stage ring, 256 thr, 2 CTAs/SM.
// ---------------------------------------------------------------------------
#define TILE32_B 8192
#define GEMM_SMEM0 (3 * 2 * TILE32_B)   // 48 KB
#define GEMM_SMEM1 (3 * 3 * TILE32_B)   // 72 KB

__device__ __forceinline__ uint32_t sw64(int r, int g) {
    return (uint32_t)(r * 64 + ((g ^ ((r >> 1) & 3)) << 4));
}

template<int MODE>
__global__ void __launch_bounds__(256, 2) mma_gemm(float* __restrict__ outg) {
    constexpr int NT = (MODE == 0) ? 2 : 3;      // tiles per stage
    constexpr uint32_t SB = NT * TILE32_B;       // stage bytes
    extern __shared__ char smc[];
    const uint32_t smb = smem_u32(smc);
    const int tid = threadIdx.x;
    const int wid = tid >> 5, lane = tid & 31;
    const int m0 = blockIdx.x * 128;

    const __half* gsrc[3];
    if (MODE == 0) {
        gsrc[0] = g_xhi;
        gsrc[1] = g_wqh + (size_t)blockIdx.y * (128 * Dd);
    } else {
        gsrc[0] = g_ehi;
        gsrc[1] = g_elo;
        gsrc[2] = g_woh + (size_t)blockIdx.y * (128 * Dd);
    }
    const int srow = tid >> 1, sg0 = (tid & 1) * 2;
    {
        const size_t aoff = (size_t)(m0 + srow) * Dd + sg0 * 8;
        const size_t boff = (size_t)srow * Dd + sg0 * 8;
        if (MODE == 0) { gsrc[0] += aoff; gsrc[1] += boff; }
        else           { gsrc[0] += aoff; gsrc[1] += aoff; gsrc[2] += boff; }
    }
    uint32_t soff[2];
    soff[0] = sw64(srow, sg0);
    soff[1] = sw64(srow, sg0 + 1);

    const int wm = wid & 3, wn = wid >> 2;
    const int arow = wm * 32 + (lane & 15);
    const int agsel = lane >> 4;
    const int brow = wn * 64 + (lane & 7) + (lane >> 4) * 8;
    const int bgsel = (lane >> 3) & 1;

    float acc[2][8][4];
    #pragma unroll
    for (int i = 0; i < 2; i++)
        #pragma unroll
        for (int j = 0; j < 8; j++)
            #pragma unroll
            for (int q = 0; q < 4; q++) acc[i][j][q] = 0.f;

    const int KT = Dd / 32;

    #pragma unroll
    for (int pc = 0; pc < 2; pc++) {
        uint32_t buf = smb + pc * SB;
        #pragma unroll
        for (int t = 0; t < NT; t++) {
            cp16(buf + t * TILE32_B + soff[0], gsrc[t] + pc * 32);
            cp16(buf + t * TILE32_B + soff[1], gsrc[t] + pc * 32 + 8);
        }
        CP_COMMIT();
    }

    int rbuf = 0, wbuf = 2;
    for (int kc = 0; kc < KT; kc++) {
        if (kc + 1 < KT) asm volatile("cp.async.wait_group 1;" ::: "memory");
        else             asm volatile("cp.async.wait_group 0;" ::: "memory");
        __syncthreads();

        if (kc + 2 < KT) {
            uint32_t buf = smb + wbuf * SB;
            #pragma unroll
            for (int t = 0; t < NT; t++) {
                cp16(buf + t * TILE32_B + soff[0], gsrc[t] + (kc + 2) * 32);
                cp16(buf + t * TILE32_B + soff[1], gsrc[t] + (kc + 2) * 32 + 8);
            }
            CP_COMMIT();
        }

        const uint32_t tb = smb + rbuf * SB;
        const uint32_t bb = tb + (NT - 1) * TILE32_B;
        #pragma unroll
        for (int ks = 0; ks < 2; ks++) {
            uint32_t ah[2][4], al[2][4];
            #pragma unroll
            for (int mm = 0; mm < 2; mm++) {
                uint32_t ad = sw64(arow + mm * 16, ks * 2 + agsel);
                ldm4(ah[mm], tb + ad);
                if (MODE == 1) ldm4(al[mm], tb + TILE32_B + ad);
            }
            #pragma unroll
            for (int j = 0; j < 4; j++) {
                uint32_t bd = sw64(brow + j * 16, ks * 2 + bgsel);
                uint32_t bh[4];
                ldm4(bh, bb + bd);
                mma16816h(acc[0][2 * j],     ah[0], bh[0], bh[1]);
                mma16816h(acc[0][2 * j + 1], ah[0], bh[2], bh[3]);
                mma16816h(acc[1][2 * j],     ah[1], bh[0], bh[1]);
                mma16816h(acc[1][2 * j + 1], ah[1], bh[2], bh[3]);
                if (MODE == 1) {
                    mma16816h(acc[0][2 * j],     al[0], bh[0], bh[1]);
                    mma16816h(acc[0][2 * j + 1], al[0], bh[2], bh[3]);
                    mma16816h(acc[1][2 * j],     al[1], bh[0], bh[1]);
                    mma16816h(acc[1][2 * j + 1], al[1], bh[2], bh[3]);
                }
            }
        }
        rbuf = (rbuf == 2) ? 0 : rbuf + 1;
        wbuf = (wbuf == 2) ? 0 : wbuf + 1;
    }

    #pragma unroll
    for (int mm = 0; mm < 2; mm++) {
        #pragma unroll
        for (int half = 0; half < 2; half++) {
            const int r = wm * 32 + mm * 16 + (lane >> 2) + half * 8;
            const int m = m0 + r;
            float* rowp;
            if (MODE == 0) {
                const int s = blockIdx.y >> 4, n = blockIdx.y & 15;
                const int b = m >> 11, t = m & (Tt - 1);
                rowp = g_qkv + ((size_t)s * Bx * Nn + (size_t)(b * Nn + n)) * Tt * Hh
                             + (size_t)t * Hh;
            } else {
                rowp = outg + (size_t)m * Dd + blockIdx.y * 128;
            }
            #pragma unroll
            for (int j = 0; j < 8; j++) {
                const int c = wn * 64 + j * 8 + (lane & 3) * 2;
                float2 v;
                v.x = acc[mm][j][half * 2];
                v.y = acc[mm][j][half * 2 + 1];
                *(float2*)(rowp + c) = v;
            }
        }
    }
}

// ---------------------------------------------------------------------------
// Flash attention (R14/R15, unchanged)
// ---------------------------------------------------------------------------
#define AT_STAGE 65536
#define ATTN_SMEM2 (3 * 65536)

__global__ void __launch_bounds__(256, 1) attn_mma_kernel()
{
    extern __shared__ char smc[];
    const uint32_t smb = smem_u32(smc);
    const int tid = threadIdx.x;
    const int wid = tid >> 5, lane = tid & 31;
    const int qt = 15 - (blockIdx.x >> 5);
    const int sub = blockIdx.x & 31;
    const int n = sub >> 1, b = sub & 1;
    const int t0 = qt * 128;
    const size_t bn = (size_t)(b * Nn + n) * Tt * Hh;

    const __nv_bfloat16* qhp = g_qh + bn;
    const __nv_bfloat16* qlp = g_ql + bn;
    const __nv_bfloat16* khp = g_kh + bn;
    const __nv_bfloat16* klp = g_kl + bn;
    const __nv_bfloat16* vhp = g_vth + bn;
    const __nv_bfloat16* vlp = g_vtl + bn;

    const int c_lo = (t0 >= WINDOW) ? ((t0 - WINDOW + 1) >> 6) : 0;
    const int c_hi = (t0 + 127) >> 6;

    const int arow = wid * 16 + (lane & 15);
    const int agsel = lane >> 4;
    const int bro = (lane & 7) + ((lane >> 4) << 3);
    const int bgsel = (lane >> 3) & 1;
    const int qr0 = t0 + wid * 16 + (lane >> 2);

    uint32_t qhf[8][4], qlf[8][4];
    {
        const int r = tid >> 1;
        const __nv_bfloat16* sh = qhp + (size_t)(t0 + r) * Hh;
        const __nv_bfloat16* sl = qlp + (size_t)(t0 + r) * Hh;
        #pragma unroll
        for (int i = 0; i < 8; i++) {
            int g = (tid & 1) * 8 + i;
            uint32_t off = (uint32_t)(r * 256 + ((g ^ (r & 7)) << 4));
            cp16(smb + off, sh + g * 8);
            cp16(smb + 32768 + off, sl + g * 8);
        }
        CP_COMMIT();
        asm volatile("cp.async.wait_group 0;" ::: "memory");
        __syncthreads();
        #pragma unroll
        for (int ks = 0; ks < 8; ks++) {
            uint32_t qa = (uint32_t)(arow * 256 + (((ks * 2 + agsel) ^ (arow & 7)) << 4));
            ldm4(qhf[ks], smb + qa);
            ldm4(qlf[ks], smb + 32768 + qa);
        }
        __syncthreads();
    }

    #pragma unroll 1
    for (int pc = 0; pc < 2; pc++) {
        const int c = c_lo + pc;
        const int k0 = c * 64;
        uint32_t sb = smb + pc * AT_STAGE;
        {
            const int r = tid >> 2;
            const __nv_bfloat16* sh = khp + (size_t)(k0 + r) * Hh;
            const __nv_bfloat16* sl = klp + (size_t)(k0 + r) * Hh;
            #pragma unroll
            for (int i = 0; i < 4; i++) {
                int g = (tid & 3) * 4 + i;
                uint32_t off = (uint32_t)(r * 256 + ((g ^ (r & 7)) << 4));
                cp16(sb + off, sh + g * 8);
                cp16(sb + 16384 + off, sl + g * 8);
            }
        }
        {
            const int r = tid >> 1;
            const __nv_bfloat16* sh = vhp + (size_t)r * Tt + k0;
            const __nv_bfloat16* sl = vlp + (size_t)r * Tt + k0;
            #pragma unroll
            for (int i = 0; i < 4; i++) {
                int g = (tid & 1) * 4 + i;
                uint32_t off = (uint32_t)(r * 128 + ((g ^ (r & 7)) << 4));
                cp16(sb + 32768 + off, sh + g * 8);
                cp16(sb + 49152 + off, sl + g * 8);
            }
        }
        CP_COMMIT();
    }

    float oacc[16][4];
    #pragma unroll
    for (int i = 0; i < 16; i++)
        #pragma unroll
        for (int q = 0; q < 4; q++) oacc[i][q] = 0.f;
    float l0 = 0.f, l1 = 0.f;

    int rbuf = 0, wbuf = 2;
    for (int c = c_lo; c <= c_hi; c++) {
        if (c < c_hi) asm volatile("cp.async.wait_group 1;" ::: "memory");
        else          asm volatile("cp.async.wait_group 0;" ::: "memory");
        __syncthreads();

        if (c + 2 <= c_hi) {
            const int k2 = (c + 2) * 64;
            uint32_t sb = smb + wbuf * AT_STAGE;
            {
                const int r = tid >> 2;
                const __nv_bfloat16* sh = khp + (size_t)(k2 + r) * Hh;
                const __nv_bfloat16* sl = klp + (size_t)(k2 + r) * Hh;
                #pragma unroll
                for (int i = 0; i < 4; i++) {
                    int g = (tid & 3) * 4 + i;
                    uint32_t off = (uint32_t)(r * 256 + ((g ^ (r & 7)) << 4));
                    cp16(sb + off, sh + g * 8);
                    cp16(sb + 16384 + off, sl + g * 8);
                }
            }
            {
                const int r = tid >> 1;
                const __nv_bfloat16* sh = vhp + (size_t)r * Tt + k2;
                const __nv_bfloat16* sl = vlp + (size_t)r * Tt + k2;
                #pragma unroll
                for (int i = 0; i < 4; i++) {
                    int g = (tid & 1) * 4 + i;
                    uint32_t off = (uint32_t)(r * 128 + ((g ^ (r & 7)) << 4));
                    cp16(sb + 32768 + off, sh + g * 8);
                    cp16(sb + 49152 + off, sl + g * 8);
                }
            }
            CP_COMMIT();
        }

        const int k0 = c * 64;
        const bool full = (k0 <= t0 - 64) && (k0 >= t0 - (WINDOW - 128));
        const uint32_t KHb = smb + rbuf * AT_STAGE;
        const uint32_t KLb = KHb + 16384, VHb = KHb + 32768, VLb = KHb + 49152;

        float sacc[8][4];
        #pragma unroll
        for (int i = 0; i < 8; i++)
            #pragma unroll
            for (int q = 0; q < 4; q++) sacc[i][q] = 0.f;

        #pragma unroll
        for (int ks = 0; ks < 8; ks++) {
            uint32_t khf[4][4], klf[4][4];
            #pragma unroll
            for (int nk = 0; nk < 4; nk++) {
                int r = nk * 16 + bro;
                uint32_t ka = (uint32_t)(r * 256 + (((ks * 2 + bgsel) ^ (r & 7)) << 4));
                ldm4(khf[nk], KHb + ka);
                ldm4(klf[nk], KLb + ka);
            }
            #pragma unroll
            for (int nk = 0; nk < 4; nk++) {
                mma16816(sacc[2 * nk],     qhf[ks], khf[nk][0], khf[nk][1]);
                mma16816(sacc[2 * nk + 1], qhf[ks], khf[nk][2], khf[nk][3]);
            }
            #pragma unroll
            for (int nk = 0; nk < 4; nk++) {
                mma16816(sacc[2 * nk],     qlf[ks], khf[nk][0], khf[nk][1]);
                mma16816(sacc[2 * nk + 1], qlf[ks], khf[nk][2], khf[nk][3]);
            }
            #pragma unroll
            for (int nk = 0; nk < 4; nk++) {
                mma16816(sacc[2 * nk],     qhf[ks], klf[nk][0], klf[nk][1]);
                mma16816(sacc[2 * nk + 1], qhf[ks], klf[nk][2], klf[nk][3]);
            }
        }

        float s0 = 0.f, s1 = 0.f;
        uint32_t phi[4][4], plo[4][4];
        #pragma unroll
        for (int nt = 0; nt < 8; nt++)
            #pragma unroll
            for (int q = 0; q < 4; q++) {
                float s = sacc[nt][q];
                float e = __expf(s * (2.0f / SOFT_CAP));
                float r = __fdividef(2.0f, e + 1.0f);
                float p = __expf(SOFT_CAP - SOFT_CAP * r);
                if (!full) {
                    int qr = qr0 + ((q & 2) ? 8 : 0);
                    int kc = k0 + nt * 8 + (lane & 3) * 2 + (q & 1);
                    if (kc > qr || qr - kc >= WINDOW) p = 0.f;
                }
                sacc[nt][q] = p;
                if (q & 2) s1 += p; else s0 += p;
            }
        #pragma unroll
        for (int kt = 0; kt < 4; kt++) {
            #pragma unroll
            for (int part = 0; part < 4; part++) {
                int nt = 2 * kt + (part >> 1);
                float x = sacc[nt][(part & 1) * 2];
                float y = sacc[nt][(part & 1) * 2 + 1];
                __nv_bfloat162 h2 = __floats2bfloat162_rn(x, y);
                float lx = x - __bfloat162float(h2.x);
                float ly = y - __bfloat162float(h2.y);
                __nv_bfloat162 l2 = __floats2bfloat162_rn(lx, ly);
                phi[kt][part] = *(uint32_t*)&h2;
                plo[kt][part] = *(uint32_t*)&l2;
            }
        }
        s0 += __shfl_xor_sync(0xffffffffu, s0, 1);
        s0 += __shfl_xor_sync(0xffffffffu, s0, 2);
        s1 += __shfl_xor_sync(0xffffffffu, s1, 1);
        s1 += __shfl_xor_sync(0xffffffffu, s1, 2);
        l0 += s0;
        l1 += s1;

        #pragma unroll
        for (int kt = 0; kt < 4; kt++) {
            #pragma unroll
            for (int gh = 0; gh < 2; gh++) {
                uint32_t vhf[4][4], vlf[4][4];
                #pragma unroll
                for (int j = 0; j < 4; j++) {
                    int r = (gh * 4 + j) * 16 + bro;
                    uint32_t va = (uint32_t)(r * 128 + (((kt * 2 + bgsel) ^ (r & 7)) << 4));
                    ldm4(vhf[j], VHb + va);
                    ldm4(vlf[j], VLb + va);
                }
                float (*oa)[4] = &oacc[gh * 8];
                #pragma unroll
                for (int j = 0; j < 4; j++) {
                    mma16816(oa[2 * j],     phi[kt], vhf[j][0], vhf[j][1]);
                    mma16816(oa[2 * j + 1], phi[kt], vhf[j][2], vhf[j][3]);
                }
                #pragma unroll
                for (int j = 0; j < 4; j++) {
                    mma16816(oa[2 * j],     plo[kt], vhf[j][0], vhf[j][1]);
                    mma16816(oa[2 * j + 1], plo[kt], vhf[j][2], vhf[j][3]);
                }
                #pragma unroll
                for (int j = 0; j < 4; j++) {
                    mma16816(oa[2 * j],     phi[kt], vlf[j][0], vlf[j][1]);
                    mma16816(oa[2 * j + 1], phi[kt], vlf[j][2], vlf[j][3]);
                }
            }
        }
        __syncthreads();
        rbuf = (rbuf == 2) ? 0 : rbuf + 1;
        wbuf = (wbuf == 2) ? 0 : wbuf + 1;
    }

    float inv0 = __fdividef(1.f, l0), inv1 = __fdividef(1.f, l1);
    const int tr0 = t0 + wid * 16 + (lane >> 2);
    #pragma unroll
    for (int nt = 0; nt < 16; nt++) {
        int col = nt * 8 + (lane & 3) * 2;
        size_t o0 = ((size_t)b * Tt + tr0) * Dd + n * Hh + col;
        size_t o1 = ((size_t)b * Tt + tr0 + 8) * Dd + n * Hh + col;
        float x0 = oacc[nt][0] * inv0, y0 = oacc[nt][1] * inv0;
        float x1 = oacc[nt][2] * inv1, y1 = oacc[nt][3] * inv1;
        __half hx0 = __float2half(x0), hy0 = __float2half(y0);
        __half hx1 = __float2half(x1), hy1 = __float2half(y1);
        *(__half2*)(g_ehi + o0) = __half2(hx0, hy0);
        *(__half2*)(g_elo + o0) = __half2(__float2half(x0 - __half2float(hx0)),
                                          __float2half(y0 - __half2float(hy0)));
        *(__half2*)(g_ehi + o1) = __half2(hx1, hy1);
        *(__half2*)(g_elo + o1) = __half2(__float2half(x1 - __half2float(hx1)),
                                          __float2half(y1 - __half2float(hy1)));
    }
}

// ---------------------------------------------------------------------------
extern "C" void kernel_launch(void* const* d_in, const int* in_sizes, int n_in,
                              void* d_out, int out_size)
{
    const float* x       = (const float*)d_in[0];
    const float* w_qkv   = (const float*)d_in[1];
    const float* w_out   = (const float*)d_in[2];
    const int*   seg_pos = (const int*)d_in[3];
    float* out = (float*)d_out;

    cudaFuncSetAttribute(mma_gemm<0>, cudaFuncAttributeMaxDynamicSharedMemorySize, GEMM_SMEM0);
    cudaFuncSetAttribute(mma_gemm<1>, cudaFuncAttributeMaxDynamicSharedMemorySize, GEMM_SMEM1);
    cudaFuncSetAttribute(attn_mma_kernel, cudaFuncAttributeMaxDynamicSharedMemorySize, ATTN_SMEM2);

    prepA_kernel<<<PREPA_SPLITX + 4 * 64 * 48, 256>>>(x, w_qkv);              // 1
    mma_gemm<0><<<dim3(Bx * Tt / 128, 48), 256, GEMM_SMEM0>>>(nullptr);       // 2
    prepB_kernel<<<PREPB_ROPE + 64 * 4 * 32, 256>>>(seg_pos);                 // 3
    attn_mma_kernel<<<dim3(16 * Nn * Bx), 256, ATTN_SMEM2>>>();               // 4
    transpose_wout_kernel<<<dim3(Dd / 32, Dd / 32), 256>>>(w_out);            // 5
    mma_gemm<1><<<dim3(Bx * Tt / 128, Dd / 128), 256, GEMM_SMEM1>>>(out);     // 6
}